// round 4
// baseline (speedup 1.0000x reference)
#include <cuda_runtime.h>
#include <cuda_bf16.h>
#include <math.h>
#include <stdint.h>

// Problem dims
#define BB 32
#define TT 256
#define CC 64
#define HH 64

// Output layout (floats)
#define LOGITS_OFF 0
#define DNC_OFF    64
#define MIX_OFF    131136ull              // 64 + 32*4096
#define RL_OFF     33685568ull            // MIX_OFF + 32*256*4096

// ---------------- static device scratch (no runtime allocs) ----------------
__device__ __nv_bfloat16 g_Ahi[8192ull * 4096];   // mixing hi  [8192][4096]
__device__ __nv_bfloat16 g_Alo[8192ull * 4096];   // mixing lo
__device__ __nv_bfloat16 g_B1hi[2048ull * 4096];  // clf1_w hi  [2048][4096]
__device__ __nv_bfloat16 g_B1lo[2048ull * 4096];
__device__ __nv_bfloat16 g_H1hi[8192ull * 2048];  // h1 hi      [8192][2048]
__device__ __nv_bfloat16 g_H1lo[8192ull * 2048];
__device__ __nv_bfloat16 g_B2hi[1024ull * 2048];  // clf2_w hi  [1024][2048]
__device__ __nv_bfloat16 g_B2lo[1024ull * 2048];
__device__ float g_lg[64 * 8 * 2];                // layer2 partials [mb][nb][2]
__device__ float g_rl[BB];

// ============================================================================
// Base-ISA PTX helpers (sm_80+ — safe on sm_103 non-'a')
// ============================================================================
__device__ __forceinline__ uint32_t smem_u32(const void* p) {
    uint32_t a;
    asm("{ .reg .u64 t; cvta.to.shared.u64 t, %1; cvt.u32.u64 %0, t; }" : "=r"(a) : "l"(p));
    return a;
}
#define CP16(dst, src) \
    asm volatile("cp.async.cg.shared.global [%0], [%1], 16;" :: "r"(dst), "l"(src))
#define CP_COMMIT() asm volatile("cp.async.commit_group;" ::: "memory")
#define CP_WAIT1()  asm volatile("cp.async.wait_group 1;" ::: "memory")
#define CP_WAIT0()  asm volatile("cp.async.wait_group 0;" ::: "memory")
#define LDSM4(R, addr) \
    asm volatile("ldmatrix.sync.aligned.m8n8.x4.shared.b16 {%0,%1,%2,%3}, [%4];" \
        : "=r"((R)[0]), "=r"((R)[1]), "=r"((R)[2]), "=r"((R)[3]) : "r"(addr))
#define LDSM2(R, addr) \
    asm volatile("ldmatrix.sync.aligned.m8n8.x2.shared.b16 {%0,%1}, [%2];" \
        : "=r"((R)[0]), "=r"((R)[1]) : "r"(addr))
#define MMA16816(D, A, Bf) \
    asm volatile("mma.sync.aligned.m16n8k16.row.col.f32.bf16.bf16.f32 " \
        "{%0,%1,%2,%3}, {%4,%5,%6,%7}, {%8,%9}, {%0,%1,%2,%3};" \
        : "+f"((D)[0]), "+f"((D)[1]), "+f"((D)[2]), "+f"((D)[3]) \
        : "r"((A)[0]), "r"((A)[1]), "r"((A)[2]), "r"((A)[3]), "r"((Bf)[0]), "r"((Bf)[1]))

// ---------------- shared mem layout for recurrent kernel (floats) ----------
#define OFF_WHHT 0
#define OFF_QWT  12288
#define OFF_KWT  16384
#define OFF_GATE 20480
#define OFF_H    24576
#define OFF_HN   28736
#define OFF_Q    32896
#define OFF_K    37056
#define OFF_TR   41216
#define OFF_DNC  45376
#define OFF_XT   49472
#define OFF_A    49536
#define OFF_B0   49728
#define OFF_BHH  49920
#define OFF_QB   50112
#define OFF_KB   50176
#define OFF_PW   50240
#define OFF_RED  50304
#define SMEM_FLOATS 50368
#define SMEM_BYTES  (SMEM_FLOATS * 4)

__device__ __forceinline__ float sigf(float x) { return 1.f / (1.f + __expf(-x)); }

// ============================================================================
// Recurrent kernel: one CTA per batch, persistent over all T steps.
// ============================================================================
__global__ __launch_bounds__(256) void recurrent_kernel(
    const float* __restrict__ x,
    const float* __restrict__ emb_w, const float* __restrict__ emb_b,
    const float* __restrict__ w_ih, const float* __restrict__ w_hh,
    const float* __restrict__ b_ih, const float* __restrict__ b_hh,
    const float* __restrict__ q_w, const float* __restrict__ q_b,
    const float* __restrict__ k_w, const float* __restrict__ k_b,
    const float* __restrict__ gate_b,
    const float* __restrict__ pred_w, const float* __restrict__ pred_b,
    float* __restrict__ out)
{
    extern __shared__ float s[];
    const int b = blockIdx.x;
    const int tid = threadIdx.x;
    const int tx = tid & 15, ty = tid >> 4;
    const int c0 = ty * 4, j0 = tx * 4;

    for (int i = tid; i < 12288; i += 256) {
        int j = i / 64, h = i % 64;
        s[OFF_WHHT + h * 192 + j] = w_hh[i];
    }
    for (int i = tid; i < 4096; i += 256) {
        int j = i / 64, h = i % 64;
        s[OFF_QWT + h * 64 + j] = q_w[i];
        s[OFF_KWT + h * 64 + j] = k_w[i];
        s[OFF_GATE + i] = gate_b[i];
    }
    if (tid < 192) {
        float a = 0.f, b0v = 0.f;
        #pragma unroll
        for (int e = 0; e < 32; e++) {
            float w = w_ih[tid * 32 + e];
            a += w * emb_w[e];
            b0v += w * emb_b[e];
        }
        s[OFF_A + tid] = a;
        s[OFF_B0 + tid] = b0v + b_ih[tid];
        s[OFF_BHH + tid] = b_hh[tid];
    }
    if (tid < 64) {
        s[OFF_QB + tid] = q_b[tid];
        s[OFF_KB + tid] = k_b[tid];
        s[OFF_PW + tid] = pred_w[tid];
    }
    for (int i = tid; i < 4160; i += 256) s[OFF_H + i] = 0.f;
    for (int i = tid; i < 4096; i += 256) s[OFF_DNC + i] = 0.f;
    const float pb = pred_b[0];
    float errsum = 0.f;
    __syncthreads();

    for (int t = 0; t < TT; t++) {
        if (tid < 64) s[OFF_XT + tid] = x[((size_t)b * TT + t) * CC + tid];
        __syncthreads();

        float ar[16], az[16], an_[16];
        #pragma unroll
        for (int ji = 0; ji < 4; ji++) {
            float br = s[OFF_BHH + j0 + ji];
            float bz = s[OFF_BHH + 64 + j0 + ji];
            float bn = s[OFF_BHH + 128 + j0 + ji];
            #pragma unroll
            for (int ci = 0; ci < 4; ci++) { ar[ci*4+ji]=br; az[ci*4+ji]=bz; an_[ci*4+ji]=bn; }
        }
        #pragma unroll 4
        for (int h = 0; h < 64; h++) {
            float hv[4];
            #pragma unroll
            for (int ci = 0; ci < 4; ci++) hv[ci] = s[OFF_H + (c0 + ci) * 65 + h];
            float4 wr4 = *(const float4*)&s[OFF_WHHT + h * 192 + j0];
            float4 wz4 = *(const float4*)&s[OFF_WHHT + h * 192 + 64 + j0];
            float4 wn4 = *(const float4*)&s[OFF_WHHT + h * 192 + 128 + j0];
            float wr[4] = {wr4.x, wr4.y, wr4.z, wr4.w};
            float wz[4] = {wz4.x, wz4.y, wz4.z, wz4.w};
            float wn[4] = {wn4.x, wn4.y, wn4.z, wn4.w};
            #pragma unroll
            for (int ci = 0; ci < 4; ci++)
                #pragma unroll
                for (int ji = 0; ji < 4; ji++) {
                    ar[ci*4+ji]  = fmaf(hv[ci], wr[ji], ar[ci*4+ji]);
                    az[ci*4+ji]  = fmaf(hv[ci], wz[ji], az[ci*4+ji]);
                    an_[ci*4+ji] = fmaf(hv[ci], wn[ji], an_[ci*4+ji]);
                }
        }
        #pragma unroll
        for (int ci = 0; ci < 4; ci++) {
            int c = c0 + ci;
            float xv = s[OFF_XT + c];
            #pragma unroll
            for (int ji = 0; ji < 4; ji++) {
                int j = j0 + ji;
                float gir = fmaf(xv, s[OFF_A + j],        s[OFF_B0 + j]);
                float giz = fmaf(xv, s[OFF_A + 64 + j],   s[OFF_B0 + 64 + j]);
                float gin = fmaf(xv, s[OFF_A + 128 + j],  s[OFF_B0 + 128 + j]);
                float r = sigf(gir + ar[ci*4+ji]);
                float z = sigf(giz + az[ci*4+ji]);
                float n = tanhf(fmaf(r, an_[ci*4+ji], gin));
                s[OFF_HN + c * 65 + j] = (1.f - z) * n + z * s[OFF_H + c * 65 + j];
            }
        }
        __syncthreads();

        float aq[16], ak[16];
        #pragma unroll
        for (int ji = 0; ji < 4; ji++) {
            float qb = s[OFF_QB + j0 + ji], kb = s[OFF_KB + j0 + ji];
            #pragma unroll
            for (int ci = 0; ci < 4; ci++) { aq[ci*4+ji]=qb; ak[ci*4+ji]=kb; }
        }
        #pragma unroll 4
        for (int h = 0; h < 64; h++) {
            float hv[4];
            #pragma unroll
            for (int ci = 0; ci < 4; ci++) hv[ci] = s[OFF_HN + (c0 + ci) * 65 + h];
            float4 qw4 = *(const float4*)&s[OFF_QWT + h * 64 + j0];
            float4 kw4 = *(const float4*)&s[OFF_KWT + h * 64 + j0];
            float qw[4] = {qw4.x, qw4.y, qw4.z, qw4.w};
            float kw[4] = {kw4.x, kw4.y, kw4.z, kw4.w};
            #pragma unroll
            for (int ci = 0; ci < 4; ci++)
                #pragma unroll
                for (int ji = 0; ji < 4; ji++) {
                    aq[ci*4+ji] = fmaf(hv[ci], qw[ji], aq[ci*4+ji]);
                    ak[ci*4+ji] = fmaf(hv[ci], kw[ji], ak[ci*4+ji]);
                }
        }
        #pragma unroll
        for (int ci = 0; ci < 4; ci++)
            #pragma unroll
            for (int ji = 0; ji < 4; ji++) {
                s[OFF_Q + (c0 + ci) * 65 + j0 + ji] = aq[ci*4+ji];
                s[OFF_K + (c0 + ci) * 65 + j0 + ji] = ak[ci*4+ji];
            }
        __syncthreads();

        float at[16];
        #pragma unroll
        for (int i = 0; i < 16; i++) at[i] = 0.f;
        #pragma unroll 4
        for (int h = 0; h < 64; h++) {
            float qv[4], kv[4];
            #pragma unroll
            for (int ci = 0; ci < 4; ci++) qv[ci] = s[OFF_Q + (c0 + ci) * 65 + h];
            #pragma unroll
            for (int ji = 0; ji < 4; ji++) kv[ji] = s[OFF_K + (j0 + ji) * 65 + h];
            #pragma unroll
            for (int ci = 0; ci < 4; ci++)
                #pragma unroll
                for (int ji = 0; ji < 4; ji++)
                    at[ci*4+ji] = fmaf(qv[ci], kv[ji], at[ci*4+ji]);
        }
        float ssq = 0.f;
        #pragma unroll
        for (int i = 0; i < 16; i++) ssq = fmaf(at[i], at[i], ssq);
        #pragma unroll
        for (int o = 16; o > 0; o >>= 1) ssq += __shfl_xor_sync(0xffffffffu, ssq, o);
        if ((tid & 31) == 0) s[OFF_RED + (tid >> 5)] = ssq;
        __syncthreads();
        float tot = 0.f;
        #pragma unroll
        for (int w = 0; w < 8; w++) tot += s[OFF_RED + w];
        float rn = 1.f / sqrtf(tot);

        size_t mixbase = MIX_OFF + ((size_t)(b * TT + t)) * 4096;
        #pragma unroll
        for (int ci = 0; ci < 4; ci++) {
            int c = c0 + ci;
            float tvv[4];
            #pragma unroll
            for (int ji = 0; ji < 4; ji++) {
                int d = j0 + ji;
                float tv = at[ci*4+ji] * rn;
                tv = tanhf(tv);
                float g = sigf(fabsf(tv) + s[OFF_GATE + c * 64 + d]);
                tv *= g;
                s[OFF_TR + c * 65 + d] = tv;
                s[OFF_DNC + c * 64 + d] += tv;
                tvv[ji] = tv;
            }
            float4 v; v.x = tvv[0]; v.y = tvv[1]; v.z = tvv[2]; v.w = tvv[3];
            *(float4*)&out[mixbase + (size_t)c * 64 + j0] = v;
        }
        __syncthreads();

        float ah[16];
        #pragma unroll
        for (int i = 0; i < 16; i++) ah[i] = 0.f;
        #pragma unroll 4
        for (int d = 0; d < 64; d++) {
            float tv[4], hv[4];
            #pragma unroll
            for (int ci = 0; ci < 4; ci++) tv[ci] = s[OFF_TR + (c0 + ci) * 65 + d];
            #pragma unroll
            for (int ji = 0; ji < 4; ji++) hv[ji] = s[OFF_HN + d * 65 + j0 + ji];
            #pragma unroll
            for (int ci = 0; ci < 4; ci++)
                #pragma unroll
                for (int ji = 0; ji < 4; ji++)
                    ah[ci*4+ji] = fmaf(tv[ci], hv[ji], ah[ci*4+ji]);
        }
        #pragma unroll
        for (int ci = 0; ci < 4; ci++)
            #pragma unroll
            for (int ji = 0; ji < 4; ji++)
                s[OFF_H + (c0 + ci) * 65 + j0 + ji] = ah[ci*4+ji];
        __syncthreads();

        if (tid < 64 && t >= 1) {
            float p = pb;
            #pragma unroll 8
            for (int h = 0; h < 64; h++) p = fmaf(s[OFF_H + tid * 65 + h], s[OFF_PW + h], p);
            float dd = p - s[OFF_XT + tid];
            errsum = fmaf(dd, dd, errsum);
        }
        __syncthreads();
    }

    for (int i = tid; i < 4096; i += 256)
        out[DNC_OFF + (size_t)b * 4096 + i] = s[OFF_DNC + i] * (1.f / 256.f);

    #pragma unroll
    for (int o = 16; o > 0; o >>= 1) errsum += __shfl_xor_sync(0xffffffffu, errsum, o);
    __syncthreads();
    if ((tid & 31) == 0) s[OFF_RED + (tid >> 5)] = errsum;
    __syncthreads();
    if (tid == 0) {
        float totv = 0.f;
        #pragma unroll
        for (int w = 0; w < 8; w++) totv += s[OFF_RED + w];
        g_rl[b] = totv;
    }
}

// ============================================================================
// Pack fp32 -> bf16 hi/lo, plain row-major (same linear layout as src).
// ============================================================================
__global__ __launch_bounds__(256) void pack_plain(
    const float* __restrict__ src, __nv_bfloat16* __restrict__ hi,
    __nv_bfloat16* __restrict__ lo, long n2)
{
    long i = (long)blockIdx.x * 256 + threadIdx.x;
    if (i >= n2) return;
    float2 v = ((const float2*)src)[i];
    __nv_bfloat16 h0 = __float2bfloat16(v.x);
    __nv_bfloat16 h1 = __float2bfloat16(v.y);
    __nv_bfloat16 l0 = __float2bfloat16(v.x - __bfloat162float(h0));
    __nv_bfloat16 l1 = __float2bfloat16(v.y - __bfloat162float(h1));
    __nv_bfloat162 hh; hh.x = h0; hh.y = h1;
    __nv_bfloat162 ll; ll.x = l0; ll.y = l1;
    ((__nv_bfloat162*)hi)[i] = hh;
    ((__nv_bfloat162*)lo)[i] = ll;
}

// ============================================================================
// bf16x3 mma.sync GEMM: D[M][N] = sum_k A[m][k]*B[n][k]  (A,B K-major bf16)
// BM=128, BN=128, BK=32, 256 threads, 8 warps (2x4), warp tile 64x32.
// Passes: (Ahi,Bhi), (Ahi,Blo), (Alo,Bhi) accumulated in fp32 regs.
// LAYER=1: bias+relu -> bf16 hi/lo row-major out (layer2 A).
// LAYER=2: bias+relu -> fused clf3 projection partial sums.
// ============================================================================
template <int LAYER>
__global__ __launch_bounds__(256, 2) void gemm_mma(
    const __nv_bfloat16* __restrict__ Ahi, const __nv_bfloat16* __restrict__ Alo,
    const __nv_bfloat16* __restrict__ Bhi, const __nv_bfloat16* __restrict__ Blo,
    const float* __restrict__ bias,
    __nv_bfloat16* __restrict__ Ohi, __nv_bfloat16* __restrict__ Olo,
    const float* __restrict__ w3,
    int K, int Nout)
{
    __shared__ __align__(128) __nv_bfloat16 sA[2][128 * 32];
    __shared__ __align__(128) __nv_bfloat16 sB[2][128 * 32];
    __shared__ float red[16];

    const int tid = threadIdx.x, lane = tid & 31, wid = tid >> 5;
    const int wm = wid & 1, wn = wid >> 1;
    const int mb = blockIdx.y, nb = blockIdx.x;
    const int KT = K / 32, iters = 3 * KT;
    const uint32_t sAb = smem_u32(sA), sBb = smem_u32(sB);

    // cp.async source/dest mapping: thread -> (row = tid/2, two 16B chunks)
    const int lr = tid >> 1, lc = (tid & 1) * 2;
    const uint32_t dA0 = sAb + lr * 64 + (((lc)     ^ ((lr >> 1) & 3)) << 4);
    const uint32_t dA1 = sAb + lr * 64 + (((lc + 1) ^ ((lr >> 1) & 3)) << 4);
    const uint32_t dB0 = sBb + lr * 64 + (((lc)     ^ ((lr >> 1) & 3)) << 4);
    const uint32_t dB1 = sBb + lr * 64 + (((lc + 1) ^ ((lr >> 1) & 3)) << 4);
    const long gA0 = (long)(mb * 128 + lr) * K + lc * 8;
    const long gB0 = (long)(nb * 128 + lr) * K + lc * 8;

    // ldmatrix per-lane geometry
    int rowA[4], swA[4], rowB[4], swB[4];
    const int halfA = (lane >> 4) & 1, halfB = (lane >> 3) & 1;
    #pragma unroll
    for (int mi = 0; mi < 4; mi++) {
        rowA[mi] = wm * 64 + mi * 16 + (lane & 15);
        swA[mi] = (rowA[mi] >> 1) & 3;
    }
    #pragma unroll
    for (int ni = 0; ni < 4; ni++) {
        rowB[ni] = wn * 32 + ni * 8 + (lane & 7);
        swB[ni] = (rowB[ni] >> 1) & 3;
    }

    float acc[4][4][4];
    #pragma unroll
    for (int mi = 0; mi < 4; mi++)
        #pragma unroll
        for (int ni = 0; ni < 4; ni++)
            #pragma unroll
            for (int r = 0; r < 4; r++) acc[mi][ni][r] = 0.f;

    auto loadTile = [&](int it) {
        int pass = it / KT, kb = it - pass * KT;
        const __nv_bfloat16* As = (pass == 2) ? Alo : Ahi;
        const __nv_bfloat16* Bs = (pass == 1) ? Blo : Bhi;
        uint32_t bo = (uint32_t)(it & 1) * 8192;
        const __nv_bfloat16* ga = As + gA0 + kb * 32;
        const __nv_bfloat16* gb = Bs + gB0 + kb * 32;
        CP16(dA0 + bo, ga);
        CP16(dA1 + bo, ga + 8);
        CP16(dB0 + bo, gb);
        CP16(dB1 + bo, gb + 8);
    };

    loadTile(0);
    CP_COMMIT();

    for (int it = 0; it < iters; ++it) {
        if (it + 1 < iters) {
            loadTile(it + 1);
            CP_COMMIT();
            CP_WAIT1();
        } else {
            CP_WAIT0();
        }
        __syncthreads();

        uint32_t bo = (uint32_t)(it & 1) * 8192;
        #pragma unroll
        for (int ks = 0; ks < 2; ks++) {
            uint32_t a[4][4], bfr[4][2];
            #pragma unroll
            for (int mi = 0; mi < 4; mi++)
                LDSM4(a[mi], sAb + bo + rowA[mi] * 64 +
                             (((2 * ks + halfA) ^ swA[mi]) << 4));
            #pragma unroll
            for (int ni = 0; ni < 4; ni++)
                LDSM2(bfr[ni], sBb + bo + rowB[ni] * 64 +
                               (((2 * ks + halfB) ^ swB[ni]) << 4));
            #pragma unroll
            for (int mi = 0; mi < 4; mi++)
                #pragma unroll
                for (int ni = 0; ni < 4; ni++)
                    MMA16816(acc[mi][ni], a[mi], bfr[ni]);
        }
        __syncthreads();
    }

    // ---- epilogue ----
    if (LAYER == 1) {
        #pragma unroll
        for (int mi = 0; mi < 4; mi++) {
            int m0 = mb * 128 + wm * 64 + mi * 16 + (lane >> 2);
            #pragma unroll
            for (int ni = 0; ni < 4; ni++) {
                int n0 = nb * 128 + wn * 32 + ni * 8 + (lane & 3) * 2;
                float bs0 = bias[n0], bs1 = bias[n0 + 1];
                #pragma unroll
                for (int half = 0; half < 2; half++) {
                    int m = m0 + half * 8;
                    float v0 = fmaxf(acc[mi][ni][half * 2 + 0] + bs0, 0.f);
                    float v1 = fmaxf(acc[mi][ni][half * 2 + 1] + bs1, 0.f);
                    __nv_bfloat16 h0 = __float2bfloat16(v0);
                    __nv_bfloat16 h1 = __float2bfloat16(v1);
                    __nv_bfloat16 l0 = __float2bfloat16(v0 - __bfloat162float(h0));
                    __nv_bfloat16 l1 = __float2bfloat16(v1 - __bfloat162float(h1));
                    __nv_bfloat162 hh; hh.x = h0; hh.y = h1;
                    __nv_bfloat162 ll; ll.x = l0; ll.y = l1;
                    long off = (long)m * Nout + n0;
                    *(__nv_bfloat162*)(Ohi + off) = hh;
                    *(__nv_bfloat162*)(Olo + off) = ll;
                }
            }
        }
    } else {
        float p0 = 0.f, p1 = 0.f;
        #pragma unroll
        for (int ni = 0; ni < 4; ni++) {
            int n0 = nb * 128 + wn * 32 + ni * 8 + (lane & 3) * 2;
            float bs0 = bias[n0], bs1 = bias[n0 + 1];
            float wa0 = w3[n0], wa1 = w3[n0 + 1];
            float wb0 = w3[1024 + n0], wb1 = w3[1024 + n0 + 1];
            #pragma unroll
            for (int mi = 0; mi < 4; mi++) {
                float v0 = fmaxf(acc[mi][ni][0] + bs0, 0.f);
                float v1 = fmaxf(acc[mi][ni][1] + bs1, 0.f);
                float v2 = fmaxf(acc[mi][ni][2] + bs0, 0.f);
                float v3 = fmaxf(acc[mi][ni][3] + bs1, 0.f);
                float s02 = v0 + v2, s13 = v1 + v3;
                p0 = fmaf(s02, wa0, fmaf(s13, wa1, p0));
                p1 = fmaf(s02, wb0, fmaf(s13, wb1, p1));
            }
        }
        #pragma unroll
        for (int o = 16; o > 0; o >>= 1) {
            p0 += __shfl_xor_sync(0xffffffffu, p0, o);
            p1 += __shfl_xor_sync(0xffffffffu, p1, o);
        }
        if (lane == 0) { red[wid * 2] = p0; red[wid * 2 + 1] = p1; }
        __syncthreads();
        if (tid == 0) {
            float s0 = 0.f, s1 = 0.f;
            #pragma unroll
            for (int w = 0; w < 8; w++) { s0 += red[w * 2]; s1 += red[w * 2 + 1]; }
            g_lg[(mb * 8 + nb) * 2 + 0] = s0;
            g_lg[(mb * 8 + nb) * 2 + 1] = s1;
        }
    }
}

// ============================================================================
// Finalize: logits from partials + rec_loss.
// ============================================================================
__global__ void finalize_kernel(const float* __restrict__ b3, float* __restrict__ out)
{
    int tid = threadIdx.x;
    if (tid < 64) {
        int b = tid >> 1, o = tid & 1;
        float sv = 0.f;
        #pragma unroll
        for (int m2 = 0; m2 < 2; m2++)
            #pragma unroll
            for (int nbi = 0; nbi < 8; nbi++)
                sv += g_lg[((b * 2 + m2) * 8 + nbi) * 2 + o];
        out[(size_t)b * 2 + o] = sv * (1.f / 256.f) + b3[o];
    }
    if (tid == 64) {
        float ss = 0.f;
        #pragma unroll
        for (int i = 0; i < BB; i++) ss += g_rl[i];
        out[RL_OFF] = ss / (32.f * 255.f * 64.f);
    }
}

// ============================================================================
extern "C" void kernel_launch(void* const* d_in, const int* in_sizes, int n_in,
                              void* d_out, int out_size)
{
    const float* x      = (const float*)d_in[0];
    const float* emb_w  = (const float*)d_in[1];
    const float* emb_b  = (const float*)d_in[2];
    const float* w_ih   = (const float*)d_in[3];
    const float* w_hh   = (const float*)d_in[4];
    const float* b_ih   = (const float*)d_in[5];
    const float* b_hh   = (const float*)d_in[6];
    const float* q_w    = (const float*)d_in[7];
    const float* q_b    = (const float*)d_in[8];
    const float* k_w    = (const float*)d_in[9];
    const float* k_b    = (const float*)d_in[10];
    const float* gate_b = (const float*)d_in[11];
    const float* pred_w = (const float*)d_in[12];
    const float* pred_b = (const float*)d_in[13];
    const float* clf1_w = (const float*)d_in[14];
    const float* clf1_b = (const float*)d_in[15];
    const float* clf2_w = (const float*)d_in[16];
    const float* clf2_b = (const float*)d_in[17];
    const float* clf3_w = (const float*)d_in[18];
    const float* clf3_b = (const float*)d_in[19];
    float* out = (float*)d_out;

    __nv_bfloat16 *ahi, *alo, *b1hi, *b1lo, *h1hi, *h1lo, *b2hi, *b2lo;
    cudaGetSymbolAddress((void**)&ahi, g_Ahi);
    cudaGetSymbolAddress((void**)&alo, g_Alo);
    cudaGetSymbolAddress((void**)&b1hi, g_B1hi);
    cudaGetSymbolAddress((void**)&b1lo, g_B1lo);
    cudaGetSymbolAddress((void**)&h1hi, g_H1hi);
    cudaGetSymbolAddress((void**)&h1lo, g_H1lo);
    cudaGetSymbolAddress((void**)&b2hi, g_B2hi);
    cudaGetSymbolAddress((void**)&b2lo, g_B2lo);

    cudaFuncSetAttribute(recurrent_kernel,
                         cudaFuncAttributeMaxDynamicSharedMemorySize, SMEM_BYTES);

    // pack classifier weights (small)
    pack_plain<<<16384, 256>>>(clf1_w, b1hi, b1lo, 2048l * 4096 / 2);
    pack_plain<<<4096, 256>>>(clf2_w, b2hi, b2lo, 1024l * 2048 / 2);

    recurrent_kernel<<<BB, 256, SMEM_BYTES>>>(
        x, emb_w, emb_b, w_ih, w_hh, b_ih, b_hh,
        q_w, q_b, k_w, k_b, gate_b, pred_w, pred_b, out);

    // pack mixing (layer1 A)
    pack_plain<<<65536, 256>>>(out + MIX_OFF, ahi, alo, 8192l * 4096 / 2);

    // layer1: [8192,4096] @ [2048,4096]^T -> relu -> bf16 hi/lo
    dim3 g1(16, 64);
    gemm_mma<1><<<g1, 256>>>(ahi, alo, b1hi, b1lo, clf1_b,
                             h1hi, h1lo, nullptr, 4096, 2048);

    // layer2: [8192,2048] @ [1024,2048]^T -> relu -> fused clf3 partials
    dim3 g2(8, 64);
    gemm_mma<2><<<g2, 256>>>(h1hi, h1lo, b2hi, b2lo, clf2_b,
                             nullptr, nullptr, clf3_w, 2048, 1024);

    finalize_kernel<<<1, 128>>>(clf3_b, out);
}

// round 5
// speedup vs baseline: 1.7417x; 1.7417x over previous
#include <cuda_runtime.h>
#include <math.h>
#include <stdint.h>

// Problem dims
#define BB 32
#define TT 256
#define CC 64
#define HH 64
#define NSM 148

// Output layout (floats)
#define LOGITS_OFF 0
#define DNC_OFF    64
#define MIX_OFF    131136ull              // 64 + 32*4096
#define RL_OFF     33685568ull            // MIX_OFF + 32*256*4096

// ---------------- static device scratch (no runtime allocs) ----------------
__device__ float g_h1[8192ull * 2048ull]; // 64 MB  layer1 activations
__device__ float g_lg[512 * 4 * 2];       // layer2 fused-clf3 partials [t2][bl][o]
__device__ float g_rl[BB];
__device__ int   g_ticket;
__device__ int   g_progress[BB];
__device__ int   g_rbdone[64];

// ---------------- shared mem layout for recurrent role (floats) ------------
#define OFF_WHHT 0
#define OFF_QWT  12288
#define OFF_KWT  16384
#define OFF_GATE 20480
#define OFF_H    24576
#define OFF_HN   28736
#define OFF_Q    32896
#define OFF_K    37056
#define OFF_TR   41216
#define OFF_DNC  45376
#define OFF_XT   49472
#define OFF_A    49536
#define OFF_B0   49728
#define OFF_BHH  49920
#define OFF_QB   50112
#define OFF_KB   50176
#define OFF_PW   50240
#define OFF_RED  50304
#define SMEM_FLOATS 50368
#define SMEM_BYTES  (SMEM_FLOATS * 4)

// worker layout (aliases recurrent region; used only when not recurring)
#define W_A0   0
#define W_A1   2112
#define W_B0   4224
#define W_B1   6336
#define W_RED  8448
#define W_TK   8464

#define NT1 1024          // layer1 tiles
#define NT2 512           // layer2 tiles
#define NTOT (NT1 + NT2)

__device__ __forceinline__ float sigf(float x) { return 1.f / (1.f + __expf(-x)); }

// row mapping: tile row r (0..127) of rowgroup (tg,bg) -> global (b*256+t) row
__device__ __forceinline__ int arow_map(int tg, int bg, int r) {
    return (bg * 4 + (r >> 5)) * 256 + tg * 32 + (r & 31);
}

// ============================================================================
// init: reset cross-launch counters (graph-replay determinism)
// ============================================================================
__global__ void init_kernel() {
    int tid = threadIdx.x;
    if (tid == 0) g_ticket = 0;
    if (tid < BB) g_progress[tid] = 0;
    if (tid < 64) g_rbdone[tid] = 0;
}

// ============================================================================
// Worker GEMM tile: C128x128 = A(rows via arow_map) x Bw^T, K steps of 16,
// double-buffered via registers. layer==1: bias+relu -> h1.
// layer==2: bias+relu -> fused clf3 partials (per 32-row batch subgroup).
// ============================================================================
__device__ void gemm_tile(float* s, const float* __restrict__ A,
                          const float* __restrict__ Bw,
                          const float* __restrict__ bias, int K,
                          int tg, int bg, int nb, int layer,
                          float* __restrict__ h1out,
                          const float* __restrict__ w3, int t2)
{
    const int tid = threadIdx.x;
    const int tx = tid & 15, ty = tid >> 4;
    const int kq = tid & 3, row0 = tid >> 2;
    const int n_blk = nb * 128;

    const long a0 = (long)arow_map(tg, bg, row0) * K + kq * 4;
    const long a1 = (long)arow_map(tg, bg, row0 + 64) * K + kq * 4;
    const long b0 = (long)(n_blk + row0) * K + kq * 4;
    const long b1 = (long)(n_blk + row0 + 64) * K + kq * 4;

    float acc[8][8];
    #pragma unroll
    for (int i = 0; i < 8; i++)
        #pragma unroll
        for (int j = 0; j < 8; j++) acc[i][j] = 0.f;

    float4 pa0 = *(const float4*)(A + a0);
    float4 pa1 = *(const float4*)(A + a1);
    float4 pb0 = *(const float4*)(Bw + b0);
    float4 pb1 = *(const float4*)(Bw + b1);

    // store first tile into buffer 0
    {
        float* Ad = s + W_A0; float* Bd = s + W_B0;
        Ad[(kq*4+0)*132 + row0] = pa0.x; Ad[(kq*4+1)*132 + row0] = pa0.y;
        Ad[(kq*4+2)*132 + row0] = pa0.z; Ad[(kq*4+3)*132 + row0] = pa0.w;
        Ad[(kq*4+0)*132 + row0+64] = pa1.x; Ad[(kq*4+1)*132 + row0+64] = pa1.y;
        Ad[(kq*4+2)*132 + row0+64] = pa1.z; Ad[(kq*4+3)*132 + row0+64] = pa1.w;
        Bd[(kq*4+0)*132 + row0] = pb0.x; Bd[(kq*4+1)*132 + row0] = pb0.y;
        Bd[(kq*4+2)*132 + row0] = pb0.z; Bd[(kq*4+3)*132 + row0] = pb0.w;
        Bd[(kq*4+0)*132 + row0+64] = pb1.x; Bd[(kq*4+1)*132 + row0+64] = pb1.y;
        Bd[(kq*4+2)*132 + row0+64] = pb1.z; Bd[(kq*4+3)*132 + row0+64] = pb1.w;
    }
    if (16 < K) {
        pa0 = *(const float4*)(A + a0 + 16);
        pa1 = *(const float4*)(A + a1 + 16);
        pb0 = *(const float4*)(Bw + b0 + 16);
        pb1 = *(const float4*)(Bw + b1 + 16);
    }
    __syncthreads();

    int cur = 0;
    for (int kt = 0;;) {
        const float* As = s + (cur ? W_A1 : W_A0);
        const float* Bs = s + (cur ? W_B1 : W_B0);
        #pragma unroll
        for (int kk = 0; kk < 16; kk++) {
            float4 a0r = *(const float4*)&As[kk * 132 + ty * 8];
            float4 a1r = *(const float4*)&As[kk * 132 + ty * 8 + 4];
            float4 b0r = *(const float4*)&Bs[kk * 132 + tx * 8];
            float4 b1r = *(const float4*)&Bs[kk * 132 + tx * 8 + 4];
            float av[8] = {a0r.x, a0r.y, a0r.z, a0r.w, a1r.x, a1r.y, a1r.z, a1r.w};
            float bv[8] = {b0r.x, b0r.y, b0r.z, b0r.w, b1r.x, b1r.y, b1r.z, b1r.w};
            #pragma unroll
            for (int i = 0; i < 8; i++)
                #pragma unroll
                for (int j = 0; j < 8; j++)
                    acc[i][j] = fmaf(av[i], bv[j], acc[i][j]);
        }
        int nkt = kt + 16;
        if (nkt >= K) break;
        {
            float* Ad = s + (cur ? W_A0 : W_A1);
            float* Bd = s + (cur ? W_B0 : W_B1);
            Ad[(kq*4+0)*132 + row0] = pa0.x; Ad[(kq*4+1)*132 + row0] = pa0.y;
            Ad[(kq*4+2)*132 + row0] = pa0.z; Ad[(kq*4+3)*132 + row0] = pa0.w;
            Ad[(kq*4+0)*132 + row0+64] = pa1.x; Ad[(kq*4+1)*132 + row0+64] = pa1.y;
            Ad[(kq*4+2)*132 + row0+64] = pa1.z; Ad[(kq*4+3)*132 + row0+64] = pa1.w;
            Bd[(kq*4+0)*132 + row0] = pb0.x; Bd[(kq*4+1)*132 + row0] = pb0.y;
            Bd[(kq*4+2)*132 + row0] = pb0.z; Bd[(kq*4+3)*132 + row0] = pb0.w;
            Bd[(kq*4+0)*132 + row0+64] = pb1.x; Bd[(kq*4+1)*132 + row0+64] = pb1.y;
            Bd[(kq*4+2)*132 + row0+64] = pb1.z; Bd[(kq*4+3)*132 + row0+64] = pb1.w;
        }
        __syncthreads();
        if (nkt + 16 < K) {
            pa0 = *(const float4*)(A + a0 + nkt + 16);
            pa1 = *(const float4*)(A + a1 + nkt + 16);
            pb0 = *(const float4*)(Bw + b0 + nkt + 16);
            pb1 = *(const float4*)(Bw + b1 + nkt + 16);
        }
        cur ^= 1;
        kt = nkt;
    }

    if (layer == 1) {
        #pragma unroll
        for (int i = 0; i < 8; i++) {
            int m = ty * 8 + i;
            long rb = (long)arow_map(tg, bg, m) * 2048 + n_blk + tx * 8;
            #pragma unroll
            for (int j = 0; j < 8; j += 4) {
                int n = n_blk + tx * 8 + j;
                float4 v;
                v.x = fmaxf(acc[i][j + 0] + bias[n + 0], 0.f);
                v.y = fmaxf(acc[i][j + 1] + bias[n + 1], 0.f);
                v.z = fmaxf(acc[i][j + 2] + bias[n + 2], 0.f);
                v.w = fmaxf(acc[i][j + 3] + bias[n + 3], 0.f);
                *(float4*)(h1out + rb + j) = v;
            }
        }
    } else {
        // fused clf3: each thread's 8 rows belong to one batch subgroup
        float p0 = 0.f, p1 = 0.f;
        #pragma unroll
        for (int j = 0; j < 8; j++) {
            int n = n_blk + tx * 8 + j;
            float bsj = bias[n], wa = w3[n], wb = w3[1024 + n];
            #pragma unroll
            for (int i = 0; i < 8; i++) {
                float v = fmaxf(acc[i][j] + bsj, 0.f);
                p0 = fmaf(v, wa, p0);
                p1 = fmaf(v, wb, p1);
            }
        }
        #pragma unroll
        for (int o = 16; o > 0; o >>= 1) {
            p0 += __shfl_xor_sync(0xffffffffu, p0, o);
            p1 += __shfl_xor_sync(0xffffffffu, p1, o);
        }
        float* red = s + W_RED;
        int wid = tid >> 5;
        if ((tid & 31) == 0) { red[wid * 2] = p0; red[wid * 2 + 1] = p1; }
        __syncthreads();
        if (tid < 8) {
            int bl = tid >> 1, o = tid & 1;
            // warps 2*bl and 2*bl+1 hold this batch subgroup
            g_lg[(t2 * 4 + bl) * 2 + o] =
                red[(2 * bl) * 2 + o] + red[(2 * bl + 1) * 2 + o];
        }
    }
}

// ============================================================================
// Mega kernel: blocks 0..31 run the recurrence, then ALL blocks become
// classifier GEMM workers consuming a global ticket queue with readiness spins.
// ============================================================================
__global__ __launch_bounds__(256) void mega_kernel(
    const float* __restrict__ x,
    const float* __restrict__ emb_w, const float* __restrict__ emb_b,
    const float* __restrict__ w_ih, const float* __restrict__ w_hh,
    const float* __restrict__ b_ih, const float* __restrict__ b_hh,
    const float* __restrict__ q_w, const float* __restrict__ q_b,
    const float* __restrict__ k_w, const float* __restrict__ k_b,
    const float* __restrict__ gate_b,
    const float* __restrict__ pred_w, const float* __restrict__ pred_b,
    const float* __restrict__ clf1_w, const float* __restrict__ clf1_b,
    const float* __restrict__ clf2_w, const float* __restrict__ clf2_b,
    const float* __restrict__ clf3_w,
    float* __restrict__ out)
{
    extern __shared__ float s[];
    const int tid = threadIdx.x;

    // ------------------------------------------------------------------
    // Role 1: recurrence (blocks 0..31)
    // ------------------------------------------------------------------
    if (blockIdx.x < BB) {
        const int b = blockIdx.x;
        const int tx = tid & 15, ty = tid >> 4;
        const int c0 = ty * 4, j0 = tx * 4;

        for (int i = tid; i < 12288; i += 256) {
            int j = i / 64, h = i % 64;
            s[OFF_WHHT + h * 192 + j] = w_hh[i];
        }
        for (int i = tid; i < 4096; i += 256) {
            int j = i / 64, h = i % 64;
            s[OFF_QWT + h * 64 + j] = q_w[i];
            s[OFF_KWT + h * 64 + j] = k_w[i];
            s[OFF_GATE + i] = gate_b[i];
        }
        if (tid < 192) {
            float a = 0.f, b0v = 0.f;
            #pragma unroll
            for (int e = 0; e < 32; e++) {
                float w = w_ih[tid * 32 + e];
                a += w * emb_w[e];
                b0v += w * emb_b[e];
            }
            s[OFF_A + tid] = a;
            s[OFF_B0 + tid] = b0v + b_ih[tid];
            s[OFF_BHH + tid] = b_hh[tid];
        }
        if (tid < 64) {
            s[OFF_QB + tid] = q_b[tid];
            s[OFF_KB + tid] = k_b[tid];
            s[OFF_PW + tid] = pred_w[tid];
        }
        for (int i = tid; i < 4160; i += 256) s[OFF_H + i] = 0.f;
        for (int i = tid; i < 4096; i += 256) s[OFF_DNC + i] = 0.f;
        const float pb = pred_b[0];
        float errsum = 0.f;
        __syncthreads();

        for (int t = 0; t < TT; t++) {
            if (tid < 64) s[OFF_XT + tid] = x[((size_t)b * TT + t) * CC + tid];
            __syncthreads();

            float ar[16], az[16], an_[16];
            #pragma unroll
            for (int ji = 0; ji < 4; ji++) {
                float br = s[OFF_BHH + j0 + ji];
                float bz = s[OFF_BHH + 64 + j0 + ji];
                float bn = s[OFF_BHH + 128 + j0 + ji];
                #pragma unroll
                for (int ci = 0; ci < 4; ci++) { ar[ci*4+ji]=br; az[ci*4+ji]=bz; an_[ci*4+ji]=bn; }
            }
            #pragma unroll 4
            for (int h = 0; h < 64; h++) {
                float hv[4];
                #pragma unroll
                for (int ci = 0; ci < 4; ci++) hv[ci] = s[OFF_H + (c0 + ci) * 65 + h];
                float4 wr4 = *(const float4*)&s[OFF_WHHT + h * 192 + j0];
                float4 wz4 = *(const float4*)&s[OFF_WHHT + h * 192 + 64 + j0];
                float4 wn4 = *(const float4*)&s[OFF_WHHT + h * 192 + 128 + j0];
                float wr[4] = {wr4.x, wr4.y, wr4.z, wr4.w};
                float wz[4] = {wz4.x, wz4.y, wz4.z, wz4.w};
                float wn[4] = {wn4.x, wn4.y, wn4.z, wn4.w};
                #pragma unroll
                for (int ci = 0; ci < 4; ci++)
                    #pragma unroll
                    for (int ji = 0; ji < 4; ji++) {
                        ar[ci*4+ji]  = fmaf(hv[ci], wr[ji], ar[ci*4+ji]);
                        az[ci*4+ji]  = fmaf(hv[ci], wz[ji], az[ci*4+ji]);
                        an_[ci*4+ji] = fmaf(hv[ci], wn[ji], an_[ci*4+ji]);
                    }
            }
            #pragma unroll
            for (int ci = 0; ci < 4; ci++) {
                int c = c0 + ci;
                float xv = s[OFF_XT + c];
                #pragma unroll
                for (int ji = 0; ji < 4; ji++) {
                    int j = j0 + ji;
                    float gir = fmaf(xv, s[OFF_A + j],        s[OFF_B0 + j]);
                    float giz = fmaf(xv, s[OFF_A + 64 + j],   s[OFF_B0 + 64 + j]);
                    float gin = fmaf(xv, s[OFF_A + 128 + j],  s[OFF_B0 + 128 + j]);
                    float r = sigf(gir + ar[ci*4+ji]);
                    float z = sigf(giz + az[ci*4+ji]);
                    float n = tanhf(fmaf(r, an_[ci*4+ji], gin));
                    s[OFF_HN + c * 65 + j] = (1.f - z) * n + z * s[OFF_H + c * 65 + j];
                }
            }
            __syncthreads();

            float aq[16], ak[16];
            #pragma unroll
            for (int ji = 0; ji < 4; ji++) {
                float qb = s[OFF_QB + j0 + ji], kb = s[OFF_KB + j0 + ji];
                #pragma unroll
                for (int ci = 0; ci < 4; ci++) { aq[ci*4+ji]=qb; ak[ci*4+ji]=kb; }
            }
            #pragma unroll 4
            for (int h = 0; h < 64; h++) {
                float hv[4];
                #pragma unroll
                for (int ci = 0; ci < 4; ci++) hv[ci] = s[OFF_HN + (c0 + ci) * 65 + h];
                float4 qw4 = *(const float4*)&s[OFF_QWT + h * 64 + j0];
                float4 kw4 = *(const float4*)&s[OFF_KWT + h * 64 + j0];
                float qw[4] = {qw4.x, qw4.y, qw4.z, qw4.w};
                float kw[4] = {kw4.x, kw4.y, kw4.z, kw4.w};
                #pragma unroll
                for (int ci = 0; ci < 4; ci++)
                    #pragma unroll
                    for (int ji = 0; ji < 4; ji++) {
                        aq[ci*4+ji] = fmaf(hv[ci], qw[ji], aq[ci*4+ji]);
                        ak[ci*4+ji] = fmaf(hv[ci], kw[ji], ak[ci*4+ji]);
                    }
            }
            #pragma unroll
            for (int ci = 0; ci < 4; ci++)
                #pragma unroll
                for (int ji = 0; ji < 4; ji++) {
                    s[OFF_Q + (c0 + ci) * 65 + j0 + ji] = aq[ci*4+ji];
                    s[OFF_K + (c0 + ci) * 65 + j0 + ji] = ak[ci*4+ji];
                }
            __syncthreads();

            float at[16];
            #pragma unroll
            for (int i = 0; i < 16; i++) at[i] = 0.f;
            #pragma unroll 4
            for (int h = 0; h < 64; h++) {
                float qv[4], kv[4];
                #pragma unroll
                for (int ci = 0; ci < 4; ci++) qv[ci] = s[OFF_Q + (c0 + ci) * 65 + h];
                #pragma unroll
                for (int ji = 0; ji < 4; ji++) kv[ji] = s[OFF_K + (j0 + ji) * 65 + h];
                #pragma unroll
                for (int ci = 0; ci < 4; ci++)
                    #pragma unroll
                    for (int ji = 0; ji < 4; ji++)
                        at[ci*4+ji] = fmaf(qv[ci], kv[ji], at[ci*4+ji]);
            }
            float ssq = 0.f;
            #pragma unroll
            for (int i = 0; i < 16; i++) ssq = fmaf(at[i], at[i], ssq);
            #pragma unroll
            for (int o = 16; o > 0; o >>= 1) ssq += __shfl_xor_sync(0xffffffffu, ssq, o);
            if ((tid & 31) == 0) s[OFF_RED + (tid >> 5)] = ssq;
            __syncthreads();
            float tot = 0.f;
            #pragma unroll
            for (int w = 0; w < 8; w++) tot += s[OFF_RED + w];
            float rn = 1.f / sqrtf(tot);

            size_t mixbase = MIX_OFF + ((size_t)(b * TT + t)) * 4096;
            #pragma unroll
            for (int ci = 0; ci < 4; ci++) {
                int c = c0 + ci;
                float tvv[4];
                #pragma unroll
                for (int ji = 0; ji < 4; ji++) {
                    int d = j0 + ji;
                    float tv = at[ci*4+ji] * rn;
                    tv = tanhf(tv);
                    float g = sigf(fabsf(tv) + s[OFF_GATE + c * 64 + d]);
                    tv *= g;
                    s[OFF_TR + c * 65 + d] = tv;
                    s[OFF_DNC + c * 64 + d] += tv;
                    tvv[ji] = tv;
                }
                float4 v; v.x = tvv[0]; v.y = tvv[1]; v.z = tvv[2]; v.w = tvv[3];
                *(float4*)&out[mixbase + (size_t)c * 64 + j0] = v;
            }
            __threadfence();           // release mixing rows device-wide
            __syncthreads();
            if (tid == 0) atomicExch(&g_progress[b], t + 1);

            float ah[16];
            #pragma unroll
            for (int i = 0; i < 16; i++) ah[i] = 0.f;
            #pragma unroll 4
            for (int d = 0; d < 64; d++) {
                float tv[4], hv[4];
                #pragma unroll
                for (int ci = 0; ci < 4; ci++) tv[ci] = s[OFF_TR + (c0 + ci) * 65 + d];
                #pragma unroll
                for (int ji = 0; ji < 4; ji++) hv[ji] = s[OFF_HN + d * 65 + j0 + ji];
                #pragma unroll
                for (int ci = 0; ci < 4; ci++)
                    #pragma unroll
                    for (int ji = 0; ji < 4; ji++)
                        ah[ci*4+ji] = fmaf(tv[ci], hv[ji], ah[ci*4+ji]);
            }
            #pragma unroll
            for (int ci = 0; ci < 4; ci++)
                #pragma unroll
                for (int ji = 0; ji < 4; ji++)
                    s[OFF_H + (c0 + ci) * 65 + j0 + ji] = ah[ci*4+ji];
            __syncthreads();

            if (tid < 64 && t >= 1) {
                float p = pb;
                #pragma unroll 8
                for (int h = 0; h < 64; h++) p = fmaf(s[OFF_H + tid * 65 + h], s[OFF_PW + h], p);
                float dd = p - s[OFF_XT + tid];
                errsum = fmaf(dd, dd, errsum);
            }
            __syncthreads();
        }

        for (int i = tid; i < 4096; i += 256)
            out[DNC_OFF + (size_t)b * 4096 + i] = s[OFF_DNC + i] * (1.f / 256.f);

        #pragma unroll
        for (int o = 16; o > 0; o >>= 1) errsum += __shfl_xor_sync(0xffffffffu, errsum, o);
        __syncthreads();
        if ((tid & 31) == 0) s[OFF_RED + (tid >> 5)] = errsum;
        __syncthreads();
        if (tid == 0) {
            float totv = 0.f;
            #pragma unroll
            for (int w = 0; w < 8; w++) totv += s[OFF_RED + w];
            g_rl[b] = totv;
        }
        __syncthreads();   // done; fall through to worker role
    }

    // ------------------------------------------------------------------
    // Role 2: classifier GEMM worker (all blocks)
    // ------------------------------------------------------------------
    int* stk = (int*)&s[W_TK];
    const float* mix = out + MIX_OFF;
    for (;;) {
        __syncthreads();
        if (tid == 0) stk[0] = atomicAdd(&g_ticket, 1);
        __syncthreads();
        int tk = stk[0];
        if (tk >= NTOT) break;

        if (tk < NT1) {
            int tg = tk >> 7, rem = tk & 127, bg = rem >> 4, nb = rem & 15;
            if (tid == 0) {
                int need = (tg + 1) * 32;
                #pragma unroll
                for (int bi = 0; bi < 4; bi++) {
                    volatile int* p = &g_progress[bg * 4 + bi];
                    while (*p < need) __nanosleep(256);
                }
                __threadfence();   // acquire
            }
            __syncthreads();
            gemm_tile(s, mix, clf1_w, clf1_b, 4096, tg, bg, nb, 1,
                      g_h1, nullptr, 0);
            __threadfence();       // release h1 tile
            __syncthreads();
            if (tid == 0) atomicAdd(&g_rbdone[tg * 8 + bg], 1);
        } else {
            int t2 = tk - NT1;
            int tg = t2 >> 6, rem = t2 & 63, bg = rem >> 3, nb = rem & 7;
            if (tid == 0) {
                volatile int* rd = &g_rbdone[tg * 8 + bg];
                while (*rd < 16) __nanosleep(256);
                __threadfence();   // acquire
            }
            __syncthreads();
            gemm_tile(s, g_h1, clf2_w, clf2_b, 2048, tg, bg, nb, 2,
                      nullptr, clf3_w, t2);
        }
    }
}

// ============================================================================
// Finalize: logits from layer2 partials + rec_loss.
// ============================================================================
__global__ void finalize_kernel(const float* __restrict__ b3, float* __restrict__ out)
{
    int tid = threadIdx.x;
    if (tid < 64) {
        int b = tid >> 1, o = tid & 1;
        int bg = b >> 2, bl = b & 3;
        float sv = 0.f;
        #pragma unroll
        for (int tg = 0; tg < 8; tg++)
            #pragma unroll
            for (int n2 = 0; n2 < 8; n2++) {
                int t2 = tg * 64 + bg * 8 + n2;
                sv += g_lg[(t2 * 4 + bl) * 2 + o];
            }
        out[(size_t)b * 2 + o] = sv * (1.f / 256.f) + b3[o];
    }
    if (tid == 64) {
        float ss = 0.f;
        #pragma unroll
        for (int i = 0; i < BB; i++) ss += g_rl[i];
        out[RL_OFF] = ss / (32.f * 255.f * 64.f);
    }
}

// ============================================================================
extern "C" void kernel_launch(void* const* d_in, const int* in_sizes, int n_in,
                              void* d_out, int out_size)
{
    const float* x      = (const float*)d_in[0];
    const float* emb_w  = (const float*)d_in[1];
    const float* emb_b  = (const float*)d_in[2];
    const float* w_ih   = (const float*)d_in[3];
    const float* w_hh   = (const float*)d_in[4];
    const float* b_ih   = (const float*)d_in[5];
    const float* b_hh   = (const float*)d_in[6];
    const float* q_w    = (const float*)d_in[7];
    const float* q_b    = (const float*)d_in[8];
    const float* k_w    = (const float*)d_in[9];
    const float* k_b    = (const float*)d_in[10];
    const float* gate_b = (const float*)d_in[11];
    const float* pred_w = (const float*)d_in[12];
    const float* pred_b = (const float*)d_in[13];
    const float* clf1_w = (const float*)d_in[14];
    const float* clf1_b = (const float*)d_in[15];
    const float* clf2_w = (const float*)d_in[16];
    const float* clf2_b = (const float*)d_in[17];
    const float* clf3_w = (const float*)d_in[18];
    const float* clf3_b = (const float*)d_in[19];
    float* out = (float*)d_out;

    cudaFuncSetAttribute(mega_kernel,
                         cudaFuncAttributeMaxDynamicSharedMemorySize, SMEM_BYTES);

    init_kernel<<<1, 128>>>();
    mega_kernel<<<NSM, 256, SMEM_BYTES>>>(
        x, emb_w, emb_b, w_ih, w_hh, b_ih, b_hh,
        q_w, q_b, k_w, k_b, gate_b, pred_w, pred_b,
        clf1_w, clf1_b, clf2_w, clf2_b, clf3_w, out);
    finalize_kernel<<<1, 128>>>(clf3_b, out);
}

// round 7
// speedup vs baseline: 1.7775x; 1.0206x over previous
#include <cuda_runtime.h>
#include <math.h>
#include <stdint.h>

// Problem dims
#define BB 32
#define TT 256
#define CC 64
#define HH 64
#define NSM 148

// Output layout (floats)
#define LOGITS_OFF 0
#define DNC_OFF    64
#define MIX_OFF    131136ull              // 64 + 32*4096
#define RL_OFF     33685568ull            // MIX_OFF + 32*256*4096

// ---------------- static device scratch (no runtime allocs) ----------------
__device__ float g_h1[8192ull * 2048ull]; // 64 MB  layer1 activations
__device__ float g_lg[512 * 64];          // layer2 fused-clf3 partials [t2][b*2+o]
__device__ float g_rl[BB];
__device__ int   g_ticket;
__device__ int   g_progress[BB];
__device__ int   g_rbdone[64];

// ---------------- shared mem layout for recurrent role (floats) ------------
#define OFF_WHHT 0
#define OFF_QWT  12288
#define OFF_KWT  16384
#define OFF_GATE 20480
#define OFF_H    24576
#define OFF_HN   28736
#define OFF_Q    32896
#define OFF_K    37056
#define OFF_TR   41216
#define OFF_DNC  45376
#define OFF_XT   49472
#define OFF_A    49536
#define OFF_B0   49728
#define OFF_BHH  49920
#define OFF_QB   50112
#define OFF_KB   50176
#define OFF_PW   50240
#define OFF_RED  50304
#define SMEM_FLOATS 50368
#define SMEM_BYTES  (SMEM_FLOATS * 4)

// worker layout (aliases recurrent region; used only when not recurring)
#define W_A0   0
#define W_A1   2112
#define W_B0   4224
#define W_B1   6336
#define W_TK   8464

#define NT1 1024          // layer1 tiles: 64 tg x 16 nb
#define NT2 512           // layer2 tiles: 64 tg x 8 nb
#define NTOT (NT1 + NT2)

__device__ __forceinline__ float sigf(float x) { return 1.f / (1.f + __expf(-x)); }
__device__ __forceinline__ float tanh_fast(float x) {
    float e = __expf(2.f * x);
    return __fdividef(e - 1.f, e + 1.f);
}

// tile row r (0..127) of rowgroup tg -> global (b*256+t) row
// rowgroup tg = all 32 batches x timesteps [4tg, 4tg+4)
__device__ __forceinline__ int arow_map(int tg, int r) {
    return (r >> 2) * 256 + tg * 4 + (r & 3);
}

// ============================================================================
// init: reset cross-launch counters (graph-replay determinism)
// ============================================================================
__global__ void init_kernel() {
    int tid = threadIdx.x;
    if (tid == 0) g_ticket = 0;
    if (tid < BB) g_progress[tid] = 0;
    if (tid < 64) g_rbdone[tid] = 0;
}

// ============================================================================
// Worker GEMM tile: C128x128 = A(rows via arow_map) x Bw^T, K steps of 16,
// double-buffered via registers. layer==1: bias+relu -> h1.
// layer==2: bias+relu -> fused clf3 partials (2 batches per thread).
// ============================================================================
__device__ void gemm_tile(float* s, const float* __restrict__ A,
                          const float* __restrict__ Bw,
                          const float* __restrict__ bias, int K,
                          int tg, int nb, int layer,
                          float* __restrict__ h1out,
                          const float* __restrict__ w3, int t2)
{
    const int tid = threadIdx.x;
    const int tx = tid & 15, ty = tid >> 4;
    const int kq = tid & 3, row0 = tid >> 2;
    const int n_blk = nb * 128;

    const long a0 = (long)arow_map(tg, row0) * K + kq * 4;
    const long a1 = (long)arow_map(tg, row0 + 64) * K + kq * 4;
    const long b0 = (long)(n_blk + row0) * K + kq * 4;
    const long b1 = (long)(n_blk + row0 + 64) * K + kq * 4;

    float acc[8][8];
    #pragma unroll
    for (int i = 0; i < 8; i++)
        #pragma unroll
        for (int j = 0; j < 8; j++) acc[i][j] = 0.f;

    float4 pa0 = *(const float4*)(A + a0);
    float4 pa1 = *(const float4*)(A + a1);
    float4 pb0 = *(const float4*)(Bw + b0);
    float4 pb1 = *(const float4*)(Bw + b1);

    {
        float* Ad = s + W_A0; float* Bd = s + W_B0;
        Ad[(kq*4+0)*132 + row0] = pa0.x; Ad[(kq*4+1)*132 + row0] = pa0.y;
        Ad[(kq*4+2)*132 + row0] = pa0.z; Ad[(kq*4+3)*132 + row0] = pa0.w;
        Ad[(kq*4+0)*132 + row0+64] = pa1.x; Ad[(kq*4+1)*132 + row0+64] = pa1.y;
        Ad[(kq*4+2)*132 + row0+64] = pa1.z; Ad[(kq*4+3)*132 + row0+64] = pa1.w;
        Bd[(kq*4+0)*132 + row0] = pb0.x; Bd[(kq*4+1)*132 + row0] = pb0.y;
        Bd[(kq*4+2)*132 + row0] = pb0.z; Bd[(kq*4+3)*132 + row0] = pb0.w;
        Bd[(kq*4+0)*132 + row0+64] = pb1.x; Bd[(kq*4+1)*132 + row0+64] = pb1.y;
        Bd[(kq*4+2)*132 + row0+64] = pb1.z; Bd[(kq*4+3)*132 + row0+64] = pb1.w;
    }
    if (16 < K) {
        pa0 = *(const float4*)(A + a0 + 16);
        pa1 = *(const float4*)(A + a1 + 16);
        pb0 = *(const float4*)(Bw + b0 + 16);
        pb1 = *(const float4*)(Bw + b1 + 16);
    }
    __syncthreads();

    int cur = 0;
    for (int kt = 0;;) {
        const float* As = s + (cur ? W_A1 : W_A0);
        const float* Bs = s + (cur ? W_B1 : W_B0);
        #pragma unroll
        for (int kk = 0; kk < 16; kk++) {
            float4 a0r = *(const float4*)&As[kk * 132 + ty * 8];
            float4 a1r = *(const float4*)&As[kk * 132 + ty * 8 + 4];
            float4 b0r = *(const float4*)&Bs[kk * 132 + tx * 8];
            float4 b1r = *(const float4*)&Bs[kk * 132 + tx * 8 + 4];
            float av[8] = {a0r.x, a0r.y, a0r.z, a0r.w, a1r.x, a1r.y, a1r.z, a1r.w};
            float bv[8] = {b0r.x, b0r.y, b0r.z, b0r.w, b1r.x, b1r.y, b1r.z, b1r.w};
            #pragma unroll
            for (int i = 0; i < 8; i++)
                #pragma unroll
                for (int j = 0; j < 8; j++)
                    acc[i][j] = fmaf(av[i], bv[j], acc[i][j]);
        }
        int nkt = kt + 16;
        if (nkt >= K) break;
        {
            float* Ad = s + (cur ? W_A0 : W_A1);
            float* Bd = s + (cur ? W_B0 : W_B1);
            Ad[(kq*4+0)*132 + row0] = pa0.x; Ad[(kq*4+1)*132 + row0] = pa0.y;
            Ad[(kq*4+2)*132 + row0] = pa0.z; Ad[(kq*4+3)*132 + row0] = pa0.w;
            Ad[(kq*4+0)*132 + row0+64] = pa1.x; Ad[(kq*4+1)*132 + row0+64] = pa1.y;
            Ad[(kq*4+2)*132 + row0+64] = pa1.z; Ad[(kq*4+3)*132 + row0+64] = pa1.w;
            Bd[(kq*4+0)*132 + row0] = pb0.x; Bd[(kq*4+1)*132 + row0] = pb0.y;
            Bd[(kq*4+2)*132 + row0] = pb0.z; Bd[(kq*4+3)*132 + row0] = pb0.w;
            Bd[(kq*4+0)*132 + row0+64] = pb1.x; Bd[(kq*4+1)*132 + row0+64] = pb1.y;
            Bd[(kq*4+2)*132 + row0+64] = pb1.z; Bd[(kq*4+3)*132 + row0+64] = pb1.w;
        }
        __syncthreads();
        if (nkt + 16 < K) {
            pa0 = *(const float4*)(A + a0 + nkt + 16);
            pa1 = *(const float4*)(A + a1 + nkt + 16);
            pb0 = *(const float4*)(Bw + b0 + nkt + 16);
            pb1 = *(const float4*)(Bw + b1 + nkt + 16);
        }
        cur ^= 1;
        kt = nkt;
    }

    if (layer == 1) {
        #pragma unroll
        for (int i = 0; i < 8; i++) {
            int m = ty * 8 + i;
            long rb = (long)arow_map(tg, m) * 2048 + n_blk + tx * 8;
            #pragma unroll
            for (int j = 0; j < 8; j += 4) {
                int n = n_blk + tx * 8 + j;
                float4 v;
                v.x = fmaxf(acc[i][j + 0] + bias[n + 0], 0.f);
                v.y = fmaxf(acc[i][j + 1] + bias[n + 1], 0.f);
                v.z = fmaxf(acc[i][j + 2] + bias[n + 2], 0.f);
                v.w = fmaxf(acc[i][j + 3] + bias[n + 3], 0.f);
                *(float4*)(h1out + rb + j) = v;
            }
        }
    } else {
        // fused clf3: thread rows ty*8+i -> batch 2*ty + (i>>2)
        float p00 = 0.f, p01 = 0.f, p10 = 0.f, p11 = 0.f;
        #pragma unroll
        for (int j = 0; j < 8; j++) {
            int n = n_blk + tx * 8 + j;
            float bsj = bias[n], wa = w3[n], wb = w3[1024 + n];
            #pragma unroll
            for (int i = 0; i < 4; i++) {
                float v = fmaxf(acc[i][j] + bsj, 0.f);
                p00 = fmaf(v, wa, p00);
                p01 = fmaf(v, wb, p01);
            }
            #pragma unroll
            for (int i = 4; i < 8; i++) {
                float v = fmaxf(acc[i][j] + bsj, 0.f);
                p10 = fmaf(v, wa, p10);
                p11 = fmaf(v, wb, p11);
            }
        }
        // reduce over the 16 lanes sharing this ty
        #pragma unroll
        for (int o = 8; o > 0; o >>= 1) {
            p00 += __shfl_xor_sync(0xffffffffu, p00, o);
            p01 += __shfl_xor_sync(0xffffffffu, p01, o);
            p10 += __shfl_xor_sync(0xffffffffu, p10, o);
            p11 += __shfl_xor_sync(0xffffffffu, p11, o);
        }
        if (tx == 0) {
            int b0i = 2 * ty, b1i = 2 * ty + 1;
            g_lg[t2 * 64 + b0i * 2 + 0] = p00;
            g_lg[t2 * 64 + b0i * 2 + 1] = p01;
            g_lg[t2 * 64 + b1i * 2 + 0] = p10;
            g_lg[t2 * 64 + b1i * 2 + 1] = p11;
        }
    }
}

// ============================================================================
// Mega kernel: blocks 0..31 run the recurrence, then ALL blocks become
// classifier GEMM workers consuming a global ticket queue with readiness spins.
// ============================================================================
__global__ __launch_bounds__(256) void mega_kernel(
    const float* __restrict__ x,
    const float* __restrict__ emb_w, const float* __restrict__ emb_b,
    const float* __restrict__ w_ih, const float* __restrict__ w_hh,
    const float* __restrict__ b_ih, const float* __restrict__ b_hh,
    const float* __restrict__ q_w, const float* __restrict__ q_b,
    const float* __restrict__ k_w, const float* __restrict__ k_b,
    const float* __restrict__ gate_b,
    const float* __restrict__ pred_w, const float* __restrict__ pred_b,
    const float* __restrict__ clf1_w, const float* __restrict__ clf1_b,
    const float* __restrict__ clf2_w, const float* __restrict__ clf2_b,
    const float* __restrict__ clf3_w,
    float* __restrict__ out)
{
    extern __shared__ float s[];
    const int tid = threadIdx.x;

    // ------------------------------------------------------------------
    // Role 1: recurrence (blocks 0..31)
    // ------------------------------------------------------------------
    if (blockIdx.x < BB) {
        const int b = blockIdx.x;
        const int tx = tid & 15, ty = tid >> 4;
        const int c0 = ty * 4, j0 = tx * 4;

        for (int i = tid; i < 12288; i += 256) {
            int j = i / 64, h = i % 64;
            s[OFF_WHHT + h * 192 + j] = w_hh[i];
        }
        for (int i = tid; i < 4096; i += 256) {
            int j = i / 64, h = i % 64;
            s[OFF_QWT + h * 64 + j] = q_w[i];
            s[OFF_KWT + h * 64 + j] = k_w[i];
            s[OFF_GATE + i] = gate_b[i];
        }
        if (tid < 192) {
            float a = 0.f, b0v = 0.f;
            #pragma unroll
            for (int e = 0; e < 32; e++) {
                float w = w_ih[tid * 32 + e];
                a += w * emb_w[e];
                b0v += w * emb_b[e];
            }
            s[OFF_A + tid] = a;
            s[OFF_B0 + tid] = b0v + b_ih[tid];
            s[OFF_BHH + tid] = b_hh[tid];
        }
        if (tid < 64) {
            s[OFF_QB + tid] = q_b[tid];
            s[OFF_KB + tid] = k_b[tid];
            s[OFF_PW + tid] = pred_w[tid];
        }
        for (int i = tid; i < 4160; i += 256) s[OFF_H + i] = 0.f;
        for (int i = tid; i < 4096; i += 256) s[OFF_DNC + i] = 0.f;
        const float pb = pred_b[0];
        float errsum = 0.f;
        __syncthreads();

        for (int t = 0; t < TT; t++) {
            if (tid < 64) s[OFF_XT + tid] = x[((size_t)b * TT + t) * CC + tid];
            __syncthreads();

            float ar[16], az[16], an_[16];
            #pragma unroll
            for (int ji = 0; ji < 4; ji++) {
                float br = s[OFF_BHH + j0 + ji];
                float bz = s[OFF_BHH + 64 + j0 + ji];
                float bn = s[OFF_BHH + 128 + j0 + ji];
                #pragma unroll
                for (int ci = 0; ci < 4; ci++) { ar[ci*4+ji]=br; az[ci*4+ji]=bz; an_[ci*4+ji]=bn; }
            }
            #pragma unroll 4
            for (int h = 0; h < 64; h++) {
                float hv[4];
                #pragma unroll
                for (int ci = 0; ci < 4; ci++) hv[ci] = s[OFF_H + (c0 + ci) * 65 + h];
                float4 wr4 = *(const float4*)&s[OFF_WHHT + h * 192 + j0];
                float4 wz4 = *(const float4*)&s[OFF_WHHT + h * 192 + 64 + j0];
                float4 wn4 = *(const float4*)&s[OFF_WHHT + h * 192 + 128 + j0];
                float wr[4] = {wr4.x, wr4.y, wr4.z, wr4.w};
                float wz[4] = {wz4.x, wz4.y, wz4.z, wz4.w};
                float wn[4] = {wn4.x, wn4.y, wn4.z, wn4.w};
                #pragma unroll
                for (int ci = 0; ci < 4; ci++)
                    #pragma unroll
                    for (int ji = 0; ji < 4; ji++) {
                        ar[ci*4+ji]  = fmaf(hv[ci], wr[ji], ar[ci*4+ji]);
                        az[ci*4+ji]  = fmaf(hv[ci], wz[ji], az[ci*4+ji]);
                        an_[ci*4+ji] = fmaf(hv[ci], wn[ji], an_[ci*4+ji]);
                    }
            }
            #pragma unroll
            for (int ci = 0; ci < 4; ci++) {
                int c = c0 + ci;
                float xv = s[OFF_XT + c];
                #pragma unroll
                for (int ji = 0; ji < 4; ji++) {
                    int j = j0 + ji;
                    float gir = fmaf(xv, s[OFF_A + j],        s[OFF_B0 + j]);
                    float giz = fmaf(xv, s[OFF_A + 64 + j],   s[OFF_B0 + 64 + j]);
                    float gin = fmaf(xv, s[OFF_A + 128 + j],  s[OFF_B0 + 128 + j]);
                    float r = sigf(gir + ar[ci*4+ji]);
                    float z = sigf(giz + az[ci*4+ji]);
                    float n = tanh_fast(fmaf(r, an_[ci*4+ji], gin));
                    s[OFF_HN + c * 65 + j] = (1.f - z) * n + z * s[OFF_H + c * 65 + j];
                }
            }
            __syncthreads();

            float aq[16], ak[16];
            #pragma unroll
            for (int ji = 0; ji < 4; ji++) {
                float qb = s[OFF_QB + j0 + ji], kb = s[OFF_KB + j0 + ji];
                #pragma unroll
                for (int ci = 0; ci < 4; ci++) { aq[ci*4+ji]=qb; ak[ci*4+ji]=kb; }
            }
            #pragma unroll 4
            for (int h = 0; h < 64; h++) {
                float hv[4];
                #pragma unroll
                for (int ci = 0; ci < 4; ci++) hv[ci] = s[OFF_HN + (c0 + ci) * 65 + h];
                float4 qw4 = *(const float4*)&s[OFF_QWT + h * 64 + j0];
                float4 kw4 = *(const float4*)&s[OFF_KWT + h * 64 + j0];
                float qw[4] = {qw4.x, qw4.y, qw4.z, qw4.w};
                float kw[4] = {kw4.x, kw4.y, kw4.z, kw4.w};
                #pragma unroll
                for (int ci = 0; ci < 4; ci++)
                    #pragma unroll
                    for (int ji = 0; ji < 4; ji++) {
                        aq[ci*4+ji] = fmaf(hv[ci], qw[ji], aq[ci*4+ji]);
                        ak[ci*4+ji] = fmaf(hv[ci], kw[ji], ak[ci*4+ji]);
                    }
            }
            #pragma unroll
            for (int ci = 0; ci < 4; ci++)
                #pragma unroll
                for (int ji = 0; ji < 4; ji++) {
                    s[OFF_Q + (c0 + ci) * 65 + j0 + ji] = aq[ci*4+ji];
                    s[OFF_K + (c0 + ci) * 65 + j0 + ji] = ak[ci*4+ji];
                }
            __syncthreads();

            float at[16];
            #pragma unroll
            for (int i = 0; i < 16; i++) at[i] = 0.f;
            #pragma unroll 4
            for (int h = 0; h < 64; h++) {
                float qv[4], kv[4];
                #pragma unroll
                for (int ci = 0; ci < 4; ci++) qv[ci] = s[OFF_Q + (c0 + ci) * 65 + h];
                #pragma unroll
                for (int ji = 0; ji < 4; ji++) kv[ji] = s[OFF_K + (j0 + ji) * 65 + h];
                #pragma unroll
                for (int ci = 0; ci < 4; ci++)
                    #pragma unroll
                    for (int ji = 0; ji < 4; ji++)
                        at[ci*4+ji] = fmaf(qv[ci], kv[ji], at[ci*4+ji]);
            }
            float ssq = 0.f;
            #pragma unroll
            for (int i = 0; i < 16; i++) ssq = fmaf(at[i], at[i], ssq);
            #pragma unroll
            for (int o = 16; o > 0; o >>= 1) ssq += __shfl_xor_sync(0xffffffffu, ssq, o);
            if ((tid & 31) == 0) s[OFF_RED + (tid >> 5)] = ssq;
            __syncthreads();
            float tot = 0.f;
            #pragma unroll
            for (int w = 0; w < 8; w++) tot += s[OFF_RED + w];
            float rn = 1.f / sqrtf(tot);

            size_t mixbase = MIX_OFF + ((size_t)(b * TT + t)) * 4096;
            #pragma unroll
            for (int ci = 0; ci < 4; ci++) {
                int c = c0 + ci;
                float tvv[4];
                #pragma unroll
                for (int ji = 0; ji < 4; ji++) {
                    int d = j0 + ji;
                    float tv = at[ci*4+ji] * rn;
                    tv = tanh_fast(tv);
                    float g = sigf(fabsf(tv) + s[OFF_GATE + c * 64 + d]);
                    tv *= g;
                    s[OFF_TR + c * 65 + d] = tv;
                    s[OFF_DNC + c * 64 + d] += tv;
                    tvv[ji] = tv;
                }
                float4 v; v.x = tvv[0]; v.y = tvv[1]; v.z = tvv[2]; v.w = tvv[3];
                *(float4*)&out[mixbase + (size_t)c * 64 + j0] = v;
            }
            __threadfence();           // release mixing rows device-wide
            __syncthreads();
            if (tid == 0) atomicExch(&g_progress[b], t + 1);

            float ah[16];
            #pragma unroll
            for (int i = 0; i < 16; i++) ah[i] = 0.f;
            #pragma unroll 4
            for (int d = 0; d < 64; d++) {
                float tv[4], hv[4];
                #pragma unroll
                for (int ci = 0; ci < 4; ci++) tv[ci] = s[OFF_TR + (c0 + ci) * 65 + d];
                #pragma unroll
                for (int ji = 0; ji < 4; ji++) hv[ji] = s[OFF_HN + d * 65 + j0 + ji];
                #pragma unroll
                for (int ci = 0; ci < 4; ci++)
                    #pragma unroll
                    for (int ji = 0; ji < 4; ji++)
                        ah[ci*4+ji] = fmaf(tv[ci], hv[ji], ah[ci*4+ji]);
            }
            #pragma unroll
            for (int ci = 0; ci < 4; ci++)
                #pragma unroll
                for (int ji = 0; ji < 4; ji++)
                    s[OFF_H + (c0 + ci) * 65 + j0 + ji] = ah[ci*4+ji];
            __syncthreads();

            if (tid < 64 && t >= 1) {
                float p = pb;
                #pragma unroll 8
                for (int h = 0; h < 64; h++) p = fmaf(s[OFF_H + tid * 65 + h], s[OFF_PW + h], p);
                float dd = p - s[OFF_XT + tid];
                errsum = fmaf(dd, dd, errsum);
            }
            __syncthreads();
        }

        for (int i = tid; i < 4096; i += 256)
            out[DNC_OFF + (size_t)b * 4096 + i] = s[OFF_DNC + i] * (1.f / 256.f);

        #pragma unroll
        for (int o = 16; o > 0; o >>= 1) errsum += __shfl_xor_sync(0xffffffffu, errsum, o);
        __syncthreads();
        if ((tid & 31) == 0) s[OFF_RED + (tid >> 5)] = errsum;
        __syncthreads();
        if (tid == 0) {
            float totv = 0.f;
            #pragma unroll
            for (int w = 0; w < 8; w++) totv += s[OFF_RED + w];
            g_rl[b] = totv;
        }
        __syncthreads();   // done; fall through to worker role
    }

    // ------------------------------------------------------------------
    // Role 2: classifier GEMM worker (all blocks)
    // ------------------------------------------------------------------
    int* stk = (int*)&s[W_TK];
    const float* mix = out + MIX_OFF;
    for (;;) {
        __syncthreads();
        if (tid == 0) stk[0] = atomicAdd(&g_ticket, 1);
        __syncthreads();
        int tk = stk[0];
        if (tk >= NTOT) break;

        if (tk < NT1) {
            int tg = tk >> 4, nb = tk & 15;
            if (tid == 0) {
                int need = (tg + 1) * 4;
                for (int bi = 0; bi < BB; bi++) {
                    volatile int* p = &g_progress[bi];
                    while (*p < need) __nanosleep(128);
                }
                __threadfence();   // acquire
            }
            __syncthreads();
            gemm_tile(s, mix, clf1_w, clf1_b, 4096, tg, nb, 1,
                      g_h1, nullptr, 0);
            __threadfence();       // release h1 tile
            __syncthreads();
            if (tid == 0) atomicAdd(&g_rbdone[tg], 1);
        } else {
            int t2 = tk - NT1;
            int tg = t2 >> 3, nb = t2 & 7;
            if (tid == 0) {
                volatile int* rd = &g_rbdone[tg];
                while (*rd < 16) __nanosleep(128);
                __threadfence();   // acquire
            }
            __syncthreads();
            gemm_tile(s, g_h1, clf2_w, clf2_b, 2048, tg, nb, 2,
                      nullptr, clf3_w, t2);
        }
    }
}

// ============================================================================
// Finalize: logits from layer2 partials + rec_loss.
// ============================================================================
__global__ void finalize_kernel(const float* __restrict__ b3, float* __restrict__ out)
{
    int tid = threadIdx.x;
    if (tid < 64) {
        int b = tid >> 1, o = tid & 1;
        float sv = 0.f;
        for (int t2 = 0; t2 < 512; t2++)
            sv += g_lg[t2 * 64 + b * 2 + o];
        out[(size_t)b * 2 + o] = sv * (1.f / 256.f) + b3[o];
    }
    if (tid == 64) {
        float ss = 0.f;
        #pragma unroll
        for (int i = 0; i < BB; i++) ss += g_rl[i];
        out[RL_OFF] = ss / (32.f * 255.f * 64.f);
    }
}

// ============================================================================
extern "C" void kernel_launch(void* const* d_in, const int* in_sizes, int n_in,
                              void* d_out, int out_size)
{
    const float* x      = (const float*)d_in[0];
    const float* emb_w  = (const float*)d_in[1];
    const float* emb_b  = (const float*)d_in[2];
    const float* w_ih   = (const float*)d_in[3];
    const float* w_hh   = (const float*)d_in[4];
    const float* b_ih   = (const float*)d_in[5];
    const float* b_hh   = (const float*)d_in[6];
    const float* q_w    = (const float*)d_in[7];
    const float* q_b    = (const float*)d_in[8];
    const float* k_w    = (const float*)d_in[9];
    const float* k_b    = (const float*)d_in[10];
    const float* gate_b = (const float*)d_in[11];
    const float* pred_w = (const float*)d_in[12];
    const float* pred_b = (const float*)d_in[13];
    const float* clf1_w = (const float*)d_in[14];
    const float* clf1_b = (const float*)d_in[15];
    const float* clf2_w = (const float*)d_in[16];
    const float* clf2_b = (const float*)d_in[17];
    const float* clf3_w = (const float*)d_in[18];
    const float* clf3_b = (const float*)d_in[19];
    float* out = (float*)d_out;

    cudaFuncSetAttribute(mega_kernel,
                         cudaFuncAttributeMaxDynamicSharedMemorySize, SMEM_BYTES);

    init_kernel<<<1, 128>>>();
    mega_kernel<<<NSM, 256, SMEM_BYTES>>>(
        x, emb_w, emb_b, w_ih, w_hh, b_ih, b_hh,
        q_w, q_b, k_w, k_b, gate_b, pred_w, pred_b,
        clf1_w, clf1_b, clf2_w, clf2_b, clf3_w, out);
    finalize_kernel<<<1, 128>>>(clf3_b, out);
}

// round 9
// speedup vs baseline: 2.0763x; 1.1681x over previous
#include <cuda_runtime.h>
#include <cuda_fp16.h>
#include <math.h>
#include <stdint.h>

// Problem dims
#define BB 32
#define TT 256
#define CC 64
#define HH 64
#define NSM 148

// Output layout (floats)
#define LOGITS_OFF 0
#define DNC_OFF    64
#define MIX_OFF    131136ull              // 64 + 32*4096
#define RL_OFF     33685568ull            // MIX_OFF + 32*256*4096

// ---------------- static device scratch (no runtime allocs) ----------------
__device__ __half g_mx16[8192ull * 4096]; // fp16 mixing copy [b*256+t][4096]
__device__ __half g_w1h[2048ull * 4096];  // clf1_w fp16
__device__ __half g_w2h[1024ull * 2048];  // clf2_w fp16
__device__ __half g_h1h[8192ull * 2048];  // h1 fp16
__device__ float g_lg[512 * 64];          // layer2 fused-clf3 partials [t2][b*2+o]
__device__ float g_rl[BB];
__device__ int   g_ticket;
__device__ int   g_progress[BB];
__device__ int   g_rbdone[64];
__device__ int   g_pk1done;
__device__ int   g_pk2done;

// ============================================================================
// Base-ISA PTX helpers (sm_80+)
// ============================================================================
__device__ __forceinline__ uint32_t smem_u32(const void* p) {
    uint32_t a;
    asm("{ .reg .u64 t; cvta.to.shared.u64 t, %1; cvt.u32.u64 %0, t; }" : "=r"(a) : "l"(p));
    return a;
}
#define CP16(dst, src) \
    asm volatile("cp.async.cg.shared.global [%0], [%1], 16;" :: "r"(dst), "l"(src))
#define CP_COMMIT() asm volatile("cp.async.commit_group;" ::: "memory")
#define CP_WAIT1()  asm volatile("cp.async.wait_group 1;" ::: "memory")
#define CP_WAIT0()  asm volatile("cp.async.wait_group 0;" ::: "memory")
#define LDSM4(R, addr) \
    asm volatile("ldmatrix.sync.aligned.m8n8.x4.shared.b16 {%0,%1,%2,%3}, [%4];" \
        : "=r"((R)[0]), "=r"((R)[1]), "=r"((R)[2]), "=r"((R)[3]) : "r"(addr))
#define LDSM2(R, addr) \
    asm volatile("ldmatrix.sync.aligned.m8n8.x2.shared.b16 {%0,%1}, [%2];" \
        : "=r"((R)[0]), "=r"((R)[1]) : "r"(addr))
#define MMAH(D, A, Bf) \
    asm volatile("mma.sync.aligned.m16n8k16.row.col.f32.f16.f16.f32 " \
        "{%0,%1,%2,%3}, {%4,%5,%6,%7}, {%8,%9}, {%0,%1,%2,%3};" \
        : "+f"((D)[0]), "+f"((D)[1]), "+f"((D)[2]), "+f"((D)[3]) \
        : "r"((A)[0]), "r"((A)[1]), "r"((A)[2]), "r"((A)[3]), "r"((Bf)[0]), "r"((Bf)[1]))

// ---------------- shared mem layout for recurrent role (floats) ------------
#define OFF_WHHT 0
#define OFF_QWT  12288
#define OFF_KWT  16384
#define OFF_GATE 20480
#define OFF_H    24576
#define OFF_HN   28736
#define OFF_Q    32896
#define OFF_K    37056
#define OFF_TR   41216
#define OFF_DNC  45376
#define OFF_XT   49472
#define OFF_A    49536
#define OFF_B0   49728
#define OFF_BHH  49920
#define OFF_QB   50112
#define OFF_KB   50176
#define OFF_PW   50240
#define OFF_RED  50304
#define SMEM_FLOATS 50368
#define SMEM_BYTES  (SMEM_FLOATS * 4)

// worker smem carve (bytes): [0,16384) A bufs, [16384,32768) B bufs,
// floats: sred at s[8192..8448), ticket at s[8500]
#define W_SRED 8192
#define W_TK   8500

// ticket queue: 24 packs, then interleaved L1/L2 groups
#define NPK  24
#define NQ   1536          // 16 (L1 tg0) + 63*24 + 8 (L2 tg63)
#define NTOT (NPK + NQ)

__device__ __forceinline__ float sigf(float x) { return 1.f / (1.f + __expf(-x)); }
__device__ __forceinline__ float tanh_fast(float x) {
    float e = __expf(2.f * x);
    return __fdividef(e - 1.f, e + 1.f);
}

// tile row r (0..127) of rowgroup tg -> global (b*256+t) row
__device__ __forceinline__ int arow_map(int tg, int r) {
    return (r >> 2) * 256 + tg * 4 + (r & 3);
}

// ============================================================================
__global__ void init_kernel() {
    int tid = threadIdx.x;
    if (tid == 0) { g_ticket = 0; g_pk1done = 0; g_pk2done = 0; }
    if (tid < BB) g_progress[tid] = 0;
    if (tid < 64) g_rbdone[tid] = 0;
}

// ============================================================================
// fp16 mma.sync GEMM tile: 128x128, BK=32, 256 thr, 8 warps (2m x 4n), 64x32/warp.
// A rows via arow_map (stride K), B rows n_blk+lr (stride K).
// layer==1: bias+relu -> g_h1h fp16. layer==2: bias+relu -> fused clf3 partials.
// ============================================================================
__device__ void gemm16(float* s, const __half* __restrict__ Ah,
                       const __half* __restrict__ Bh,
                       const float* __restrict__ bias, int K,
                       int tg, int nb, int layer,
                       const float* __restrict__ w3, int t2)
{
    const int tid = threadIdx.x, lane = tid & 31, wid = tid >> 5;
    const int wm = wid & 1, wn = wid >> 1;
    const int n_blk = nb * 128;
    const uint32_t sAb = smem_u32(s);
    const uint32_t sBb = sAb + 16384;

    const int lr = tid >> 1, lc = (tid & 1) * 2;
    const uint32_t swl = (lr >> 1) & 3;
    const uint32_t dA0 = sAb + lr * 64 + (((uint32_t)lc ^ swl) << 4);
    const uint32_t dA1 = sAb + lr * 64 + (((uint32_t)(lc + 1) ^ swl) << 4);
    const uint32_t dB0 = sBb + lr * 64 + (((uint32_t)lc ^ swl) << 4);
    const uint32_t dB1 = sBb + lr * 64 + (((uint32_t)(lc + 1) ^ swl) << 4);
    const long gA0 = (long)arow_map(tg, lr) * K + lc * 8;
    const long gB0 = (long)(n_blk + lr) * K + lc * 8;

    int rowA[4], swA[4], rowB[4], swB[4];
    const int halfA = (lane >> 4) & 1, halfB = (lane >> 3) & 1;
    #pragma unroll
    for (int mi = 0; mi < 4; mi++) {
        rowA[mi] = wm * 64 + mi * 16 + (lane & 15);
        swA[mi] = (rowA[mi] >> 1) & 3;
    }
    #pragma unroll
    for (int ni = 0; ni < 4; ni++) {
        rowB[ni] = wn * 32 + ni * 8 + (lane & 7);
        swB[ni] = (rowB[ni] >> 1) & 3;
    }

    float acc[4][4][4];
    #pragma unroll
    for (int mi = 0; mi < 4; mi++)
        #pragma unroll
        for (int ni = 0; ni < 4; ni++)
            #pragma unroll
            for (int r = 0; r < 4; r++) acc[mi][ni][r] = 0.f;

    const int iters = K / 32;
    {
        CP16(dA0, Ah + gA0);
        CP16(dA1, Ah + gA0 + 8);
        CP16(dB0, Bh + gB0);
        CP16(dB1, Bh + gB0 + 8);
        CP_COMMIT();
    }
    for (int it = 0; it < iters; ++it) {
        if (it + 1 < iters) {
            uint32_t bo = (uint32_t)((it + 1) & 1) * 8192;
            long ko = (long)(it + 1) * 32;
            CP16(dA0 + bo, Ah + gA0 + ko);
            CP16(dA1 + bo, Ah + gA0 + ko + 8);
            CP16(dB0 + bo, Bh + gB0 + ko);
            CP16(dB1 + bo, Bh + gB0 + ko + 8);
            CP_COMMIT();
            CP_WAIT1();
        } else {
            CP_WAIT0();
        }
        __syncthreads();

        uint32_t bo = (uint32_t)(it & 1) * 8192;
        #pragma unroll
        for (int ks = 0; ks < 2; ks++) {
            uint32_t a[4][4], bfr[4][2];
            #pragma unroll
            for (int mi = 0; mi < 4; mi++)
                LDSM4(a[mi], sAb + bo + rowA[mi] * 64 +
                             (((uint32_t)(2 * ks + halfA) ^ (uint32_t)swA[mi]) << 4));
            #pragma unroll
            for (int ni = 0; ni < 4; ni++)
                LDSM2(bfr[ni], sBb + bo + rowB[ni] * 64 +
                               (((uint32_t)(2 * ks + halfB) ^ (uint32_t)swB[ni]) << 4));
            #pragma unroll
            for (int mi = 0; mi < 4; mi++)
                #pragma unroll
                for (int ni = 0; ni < 4; ni++)
                    MMAH(acc[mi][ni], a[mi], bfr[ni]);
        }
        __syncthreads();
    }

    if (layer == 1) {
        #pragma unroll
        for (int mi = 0; mi < 4; mi++) {
            #pragma unroll
            for (int ni = 0; ni < 4; ni++) {
                int n0 = n_blk + wn * 32 + ni * 8 + (lane & 3) * 2;
                float bs0 = bias[n0], bs1 = bias[n0 + 1];
                #pragma unroll
                for (int h = 0; h < 2; h++) {
                    int ml = wm * 64 + mi * 16 + (lane >> 2) + h * 8;
                    int row = arow_map(tg, ml);
                    float v0 = fmaxf(acc[mi][ni][h * 2 + 0] + bs0, 0.f);
                    float v1 = fmaxf(acc[mi][ni][h * 2 + 1] + bs1, 0.f);
                    *(__half2*)(g_h1h + (long)row * 2048 + n0) =
                        __floats2half2_rn(v0, v1);
                }
            }
        }
    } else {
        float pa[4][2][2];
        #pragma unroll
        for (int mi = 0; mi < 4; mi++)
            #pragma unroll
            for (int h = 0; h < 2; h++) { pa[mi][h][0] = 0.f; pa[mi][h][1] = 0.f; }
        #pragma unroll
        for (int ni = 0; ni < 4; ni++) {
            int n0 = n_blk + wn * 32 + ni * 8 + (lane & 3) * 2;
            float bs0 = bias[n0], bs1 = bias[n0 + 1];
            float wa0 = w3[n0], wa1 = w3[n0 + 1];
            float wb0 = w3[1024 + n0], wb1 = w3[1024 + n0 + 1];
            #pragma unroll
            for (int mi = 0; mi < 4; mi++) {
                #pragma unroll
                for (int h = 0; h < 2; h++) {
                    float v0 = fmaxf(acc[mi][ni][h * 2 + 0] + bs0, 0.f);
                    float v1 = fmaxf(acc[mi][ni][h * 2 + 1] + bs1, 0.f);
                    pa[mi][h][0] = fmaf(v0, wa0, fmaf(v1, wa1, pa[mi][h][0]));
                    pa[mi][h][1] = fmaf(v0, wb0, fmaf(v1, wb1, pa[mi][h][1]));
                }
            }
        }
        // reduce over 16 lanes sharing each batch (xor masks stay in 16-half)
        #pragma unroll
        for (int mi = 0; mi < 4; mi++)
            #pragma unroll
            for (int h = 0; h < 2; h++)
                #pragma unroll
                for (int o = 0; o < 2; o++) {
                    float v = pa[mi][h][o];
                    #pragma unroll
                    for (int msk = 8; msk > 0; msk >>= 1)
                        v += __shfl_xor_sync(0xffffffffu, v, msk);
                    pa[mi][h][o] = v;
                }
        float* sred = s + W_SRED;   // [4 wn][32 bat][2 o]
        if ((lane & 15) == 0) {
            #pragma unroll
            for (int mi = 0; mi < 4; mi++)
                #pragma unroll
                for (int h = 0; h < 2; h++) {
                    int bat = wm * 16 + mi * 4 + 2 * h + (lane >> 4);
                    sred[(wn * 32 + bat) * 2 + 0] = pa[mi][h][0];
                    sred[(wn * 32 + bat) * 2 + 1] = pa[mi][h][1];
                }
        }
        __syncthreads();
        if (tid < 64) {
            int b = tid >> 1, o = tid & 1;
            float sv = sred[(0 * 32 + b) * 2 + o] + sred[(1 * 32 + b) * 2 + o]
                     + sred[(2 * 32 + b) * 2 + o] + sred[(3 * 32 + b) * 2 + o];
            g_lg[t2 * 64 + b * 2 + o] = sv;
        }
        __syncthreads();
    }
}

// ============================================================================
// Mega kernel: blocks 0..31 recurrence, all blocks then fp16-GEMM workers.
// ============================================================================
__global__ __launch_bounds__(256) void mega_kernel(
    const float* __restrict__ x,
    const float* __restrict__ emb_w, const float* __restrict__ emb_b,
    const float* __restrict__ w_ih, const float* __restrict__ w_hh,
    const float* __restrict__ b_ih, const float* __restrict__ b_hh,
    const float* __restrict__ q_w, const float* __restrict__ q_b,
    const float* __restrict__ k_w, const float* __restrict__ k_b,
    const float* __restrict__ gate_b,
    const float* __restrict__ pred_w, const float* __restrict__ pred_b,
    const float* __restrict__ clf1_w, const float* __restrict__ clf1_b,
    const float* __restrict__ clf2_w, const float* __restrict__ clf2_b,
    const float* __restrict__ clf3_w,
    float* __restrict__ out)
{
    extern __shared__ float s[];
    const int tid = threadIdx.x;

    // ------------------------------------------------------------------
    // Role 1: recurrence (blocks 0..31)
    // ------------------------------------------------------------------
    if (blockIdx.x < BB) {
        const int b = blockIdx.x;
        const int tx = tid & 15, ty = tid >> 4;
        const int c0 = ty * 4, j0 = tx * 4;

        for (int i = tid; i < 12288; i += 256) {
            int j = i / 64, h = i % 64;
            s[OFF_WHHT + h * 192 + j] = w_hh[i];
        }
        for (int i = tid; i < 4096; i += 256) {
            int j = i / 64, h = i % 64;
            s[OFF_QWT + h * 64 + j] = q_w[i];
            s[OFF_KWT + h * 64 + j] = k_w[i];
            s[OFF_GATE + i] = gate_b[i];
        }
        if (tid < 192) {
            float a = 0.f, b0v = 0.f;
            #pragma unroll
            for (int e = 0; e < 32; e++) {
                float w = w_ih[tid * 32 + e];
                a += w * emb_w[e];
                b0v += w * emb_b[e];
            }
            s[OFF_A + tid] = a;
            s[OFF_B0 + tid] = b0v + b_ih[tid];
            s[OFF_BHH + tid] = b_hh[tid];
        }
        if (tid < 64) {
            s[OFF_QB + tid] = q_b[tid];
            s[OFF_KB + tid] = k_b[tid];
            s[OFF_PW + tid] = pred_w[tid];
        }
        for (int i = tid; i < 4160; i += 256) s[OFF_H + i] = 0.f;
        for (int i = tid; i < 4096; i += 256) s[OFF_DNC + i] = 0.f;
        const float pb = pred_b[0];
        float errsum = 0.f;
        __syncthreads();

        for (int t = 0; t < TT; t++) {
            if (tid < 64) s[OFF_XT + tid] = x[((size_t)b * TT + t) * CC + tid];
            __syncthreads();

            float ar[16], az[16], an_[16];
            #pragma unroll
            for (int ji = 0; ji < 4; ji++) {
                float br = s[OFF_BHH + j0 + ji];
                float bz = s[OFF_BHH + 64 + j0 + ji];
                float bn = s[OFF_BHH + 128 + j0 + ji];
                #pragma unroll
                for (int ci = 0; ci < 4; ci++) { ar[ci*4+ji]=br; az[ci*4+ji]=bz; an_[ci*4+ji]=bn; }
            }
            #pragma unroll 4
            for (int h = 0; h < 64; h++) {
                float hv[4];
                #pragma unroll
                for (int ci = 0; ci < 4; ci++) hv[ci] = s[OFF_H + (c0 + ci) * 65 + h];
                float4 wr4 = *(const float4*)&s[OFF_WHHT + h * 192 + j0];
                float4 wz4 = *(const float4*)&s[OFF_WHHT + h * 192 + 64 + j0];
                float4 wn4 = *(const float4*)&s[OFF_WHHT + h * 192 + 128 + j0];
                float wr[4] = {wr4.x, wr4.y, wr4.z, wr4.w};
                float wz[4] = {wz4.x, wz4.y, wz4.z, wz4.w};
                float wn[4] = {wn4.x, wn4.y, wn4.z, wn4.w};
                #pragma unroll
                for (int ci = 0; ci < 4; ci++)
                    #pragma unroll
                    for (int ji = 0; ji < 4; ji++) {
                        ar[ci*4+ji]  = fmaf(hv[ci], wr[ji], ar[ci*4+ji]);
                        az[ci*4+ji]  = fmaf(hv[ci], wz[ji], az[ci*4+ji]);
                        an_[ci*4+ji] = fmaf(hv[ci], wn[ji], an_[ci*4+ji]);
                    }
            }
            #pragma unroll
            for (int ci = 0; ci < 4; ci++) {
                int c = c0 + ci;
                float xv = s[OFF_XT + c];
                #pragma unroll
                for (int ji = 0; ji < 4; ji++) {
                    int j = j0 + ji;
                    float gir = fmaf(xv, s[OFF_A + j],        s[OFF_B0 + j]);
                    float giz = fmaf(xv, s[OFF_A + 64 + j],   s[OFF_B0 + 64 + j]);
                    float gin = fmaf(xv, s[OFF_A + 128 + j],  s[OFF_B0 + 128 + j]);
                    float r = sigf(gir + ar[ci*4+ji]);
                    float z = sigf(giz + az[ci*4+ji]);
                    float n = tanh_fast(fmaf(r, an_[ci*4+ji], gin));
                    s[OFF_HN + c * 65 + j] = (1.f - z) * n + z * s[OFF_H + c * 65 + j];
                }
            }
            __syncthreads();

            float aq[16], ak[16];
            #pragma unroll
            for (int ji = 0; ji < 4; ji++) {
                float qb = s[OFF_QB + j0 + ji], kb = s[OFF_KB + j0 + ji];
                #pragma unroll
                for (int ci = 0; ci < 4; ci++) { aq[ci*4+ji]=qb; ak[ci*4+ji]=kb; }
            }
            #pragma unroll 4
            for (int h = 0; h < 64; h++) {
                float hv[4];
                #pragma unroll
                for (int ci = 0; ci < 4; ci++) hv[ci] = s[OFF_HN + (c0 + ci) * 65 + h];
                float4 qw4 = *(const float4*)&s[OFF_QWT + h * 64 + j0];
                float4 kw4 = *(const float4*)&s[OFF_KWT + h * 64 + j0];
                float qw[4] = {qw4.x, qw4.y, qw4.z, qw4.w};
                float kw[4] = {kw4.x, kw4.y, kw4.z, kw4.w};
                #pragma unroll
                for (int ci = 0; ci < 4; ci++)
                    #pragma unroll
                    for (int ji = 0; ji < 4; ji++) {
                        aq[ci*4+ji] = fmaf(hv[ci], qw[ji], aq[ci*4+ji]);
                        ak[ci*4+ji] = fmaf(hv[ci], kw[ji], ak[ci*4+ji]);
                    }
            }
            #pragma unroll
            for (int ci = 0; ci < 4; ci++)
                #pragma unroll
                for (int ji = 0; ji < 4; ji++) {
                    s[OFF_Q + (c0 + ci) * 65 + j0 + ji] = aq[ci*4+ji];
                    s[OFF_K + (c0 + ci) * 65 + j0 + ji] = ak[ci*4+ji];
                }
            __syncthreads();

            float at[16];
            #pragma unroll
            for (int i = 0; i < 16; i++) at[i] = 0.f;
            #pragma unroll 4
            for (int h = 0; h < 64; h++) {
                float qv[4], kv[4];
                #pragma unroll
                for (int ci = 0; ci < 4; ci++) qv[ci] = s[OFF_Q + (c0 + ci) * 65 + h];
                #pragma unroll
                for (int ji = 0; ji < 4; ji++) kv[ji] = s[OFF_K + (j0 + ji) * 65 + h];
                #pragma unroll
                for (int ci = 0; ci < 4; ci++)
                    #pragma unroll
                    for (int ji = 0; ji < 4; ji++)
                        at[ci*4+ji] = fmaf(qv[ci], kv[ji], at[ci*4+ji]);
            }
            float ssq = 0.f;
            #pragma unroll
            for (int i = 0; i < 16; i++) ssq = fmaf(at[i], at[i], ssq);
            #pragma unroll
            for (int o = 16; o > 0; o >>= 1) ssq += __shfl_xor_sync(0xffffffffu, ssq, o);
            if ((tid & 31) == 0) s[OFF_RED + (tid >> 5)] = ssq;
            __syncthreads();
            float tot = 0.f;
            #pragma unroll
            for (int w = 0; w < 8; w++) tot += s[OFF_RED + w];
            float rn = 1.f / sqrtf(tot);

            size_t rowbase = (size_t)(b * TT + t) * 4096;
            size_t mixbase = MIX_OFF + rowbase;
            #pragma unroll
            for (int ci = 0; ci < 4; ci++) {
                int c = c0 + ci;
                float tvv[4];
                #pragma unroll
                for (int ji = 0; ji < 4; ji++) {
                    int d = j0 + ji;
                    float tv = at[ci*4+ji] * rn;
                    tv = tanh_fast(tv);
                    float g = sigf(fabsf(tv) + s[OFF_GATE + c * 64 + d]);
                    tv *= g;
                    s[OFF_TR + c * 65 + d] = tv;
                    s[OFF_DNC + c * 64 + d] += tv;
                    tvv[ji] = tv;
                }
                float4 v; v.x = tvv[0]; v.y = tvv[1]; v.z = tvv[2]; v.w = tvv[3];
                *(float4*)&out[mixbase + (size_t)c * 64 + j0] = v;
                // fp16 copy for the classifier
                __half* mp = g_mx16 + rowbase + (size_t)c * 64 + j0;
                *(__half2*)(mp)     = __floats2half2_rn(tvv[0], tvv[1]);
                *(__half2*)(mp + 2) = __floats2half2_rn(tvv[2], tvv[3]);
            }
            __threadfence();           // release mixing rows device-wide
            __syncthreads();
            if (tid == 0) atomicExch(&g_progress[b], t + 1);

            float ah[16];
            #pragma unroll
            for (int i = 0; i < 16; i++) ah[i] = 0.f;
            #pragma unroll 4
            for (int d = 0; d < 64; d++) {
                float tv[4], hv[4];
                #pragma unroll
                for (int ci = 0; ci < 4; ci++) tv[ci] = s[OFF_TR + (c0 + ci) * 65 + d];
                #pragma unroll
                for (int ji = 0; ji < 4; ji++) hv[ji] = s[OFF_HN + d * 65 + j0 + ji];
                #pragma unroll
                for (int ci = 0; ci < 4; ci++)
                    #pragma unroll
                    for (int ji = 0; ji < 4; ji++)
                        ah[ci*4+ji] = fmaf(tv[ci], hv[ji], ah[ci*4+ji]);
            }
            #pragma unroll
            for (int ci = 0; ci < 4; ci++)
                #pragma unroll
                for (int ji = 0; ji < 4; ji++)
                    s[OFF_H + (c0 + ci) * 65 + j0 + ji] = ah[ci*4+ji];
            __syncthreads();

            if (tid < 64 && t >= 1) {
                float p = pb;
                #pragma unroll 8
                for (int h = 0; h < 64; h++) p = fmaf(s[OFF_H + tid * 65 + h], s[OFF_PW + h], p);
                float dd = p - s[OFF_XT + tid];
                errsum = fmaf(dd, dd, errsum);
            }
            __syncthreads();
        }

        for (int i = tid; i < 4096; i += 256)
            out[DNC_OFF + (size_t)b * 4096 + i] = s[OFF_DNC + i] * (1.f / 256.f);

        #pragma unroll
        for (int o = 16; o > 0; o >>= 1) errsum += __shfl_xor_sync(0xffffffffu, errsum, o);
        __syncthreads();
        if ((tid & 31) == 0) s[OFF_RED + (tid >> 5)] = errsum;
        __syncthreads();
        if (tid == 0) {
            float totv = 0.f;
            #pragma unroll
            for (int w = 0; w < 8; w++) totv += s[OFF_RED + w];
            g_rl[b] = totv;
        }
        __syncthreads();   // done; fall through to worker role
    }

    // ------------------------------------------------------------------
    // Role 2: worker (all blocks): pack weights, then fp16 GEMM tiles
    // ------------------------------------------------------------------
    int* stk = (int*)&s[W_TK];
    for (;;) {
        __syncthreads();
        if (tid == 0) stk[0] = atomicAdd(&g_ticket, 1);
        __syncthreads();
        int tk = stk[0];
        if (tk >= NTOT) break;

        if (tk < NPK) {
            // weight pack tickets
            if (tk < 16) {
                long base = (long)tk * 524288;           // 128 rows x 4096
                const float2* src = (const float2*)(clf1_w + base);
                __half2* dst = (__half2*)(g_w1h + base);
                for (int i = tid; i < 262144; i += 256) {
                    float2 v = src[i];
                    dst[i] = __floats2half2_rn(v.x, v.y);
                }
                __threadfence();
                __syncthreads();
                if (tid == 0) atomicAdd(&g_pk1done, 1);
            } else {
                long base = (long)(tk - 16) * 262144;    // 128 rows x 2048
                const float2* src = (const float2*)(clf2_w + base);
                __half2* dst = (__half2*)(g_w2h + base);
                for (int i = tid; i < 131072; i += 256) {
                    float2 v = src[i];
                    dst[i] = __floats2half2_rn(v.x, v.y);
                }
                __threadfence();
                __syncthreads();
                if (tid == 0) atomicAdd(&g_pk2done, 1);
            }
            continue;
        }

        // decode interleaved L1/L2 queue
        int u = tk - NPK;
        int ly, tg, nb;
        if (u < 16) { ly = 1; tg = 0; nb = u; }
        else if (u < 16 + 63 * 24) {
            int v = u - 16, g = v / 24, r = v - g * 24;
            if (r < 8) { ly = 2; tg = g; nb = r; }
            else       { ly = 1; tg = g + 1; nb = r - 8; }
        } else { ly = 2; tg = 63; nb = u - (16 + 63 * 24); }

        if (ly == 1) {
            if (tid == 0) {
                volatile int* pk = &g_pk1done;
                while (*pk < 16) __nanosleep(128);
                int need = (tg + 1) * 4;
                for (int bi = 0; bi < BB; bi++) {
                    volatile int* p = &g_progress[bi];
                    while (*p < need) __nanosleep(128);
                }
                __threadfence();
            }
            __syncthreads();
            gemm16(s, g_mx16, g_w1h, clf1_b, 4096, tg, nb, 1, nullptr, 0);
            __threadfence();
            __syncthreads();
            if (tid == 0) atomicAdd(&g_rbdone[tg], 1);
        } else {
            if (tid == 0) {
                volatile int* pk = &g_pk2done;
                while (*pk < 8) __nanosleep(128);
                volatile int* rd = &g_rbdone[tg];
                while (*rd < 16) __nanosleep(128);
                __threadfence();
            }
            __syncthreads();
            gemm16(s, g_h1h, g_w2h, clf2_b, 2048, tg, nb, 2, clf3_w, tg * 8 + nb);
        }
    }
}

// ============================================================================
__global__ void finalize_kernel(const float* __restrict__ b3, float* __restrict__ out)
{
    int tid = threadIdx.x;
    if (tid < 64) {
        int b = tid >> 1, o = tid & 1;
        float sv = 0.f;
        for (int t2 = 0; t2 < 512; t2++)
            sv += g_lg[t2 * 64 + b * 2 + o];
        out[(size_t)b * 2 + o] = sv * (1.f / 256.f) + b3[o];
    }
    if (tid == 64) {
        float ss = 0.f;
        #pragma unroll
        for (int i = 0; i < BB; i++) ss += g_rl[i];
        out[RL_OFF] = ss / (32.f * 255.f * 64.f);
    }
}

// ============================================================================
extern "C" void kernel_launch(void* const* d_in, const int* in_sizes, int n_in,
                              void* d_out, int out_size)
{
    const float* x      = (const float*)d_in[0];
    const float* emb_w  = (const float*)d_in[1];
    const float* emb_b  = (const float*)d_in[2];
    const float* w_ih   = (const float*)d_in[3];
    const float* w_hh   = (const float*)d_in[4];
    const float* b_ih   = (const float*)d_in[5];
    const float* b_hh   = (const float*)d_in[6];
    const float* q_w    = (const float*)d_in[7];
    const float* q_b    = (const float*)d_in[8];
    const float* k_w    = (const float*)d_in[9];
    const float* k_b    = (const float*)d_in[10];
    const float* gate_b = (const float*)d_in[11];
    const float* pred_w = (const float*)d_in[12];
    const float* pred_b = (const float*)d_in[13];
    const float* clf1_w = (const float*)d_in[14];
    const float* clf1_b = (const float*)d_in[15];
    const float* clf2_w = (const float*)d_in[16];
    const float* clf2_b = (const float*)d_in[17];
    const float* clf3_w = (const float*)d_in[18];
    const float* clf3_b = (const float*)d_in[19];
    float* out = (float*)d_out;

    cudaFuncSetAttribute(mega_kernel,
                         cudaFuncAttributeMaxDynamicSharedMemorySize, SMEM_BYTES);

    init_kernel<<<1, 128>>>();
    mega_kernel<<<NSM, 256, SMEM_BYTES>>>(
        x, emb_w, emb_b, w_ih, w_hh, b_ih, b_hh,
        q_w, q_b, k_w, k_b, gate_b, pred_w, pred_b,
        clf1_w, clf1_b, clf2_w, clf2_b, clf3_w, out);
    finalize_kernel<<<1, 128>>>(clf3_b, out);
}

// round 11
// speedup vs baseline: 2.2131x; 1.0659x over previous
#include <cuda_runtime.h>
#include <cuda_fp16.h>
#include <math.h>
#include <stdint.h>

// Problem dims
#define BB 32
#define TT 256
#define CC 64
#define HH 64
#define NSM 148

// Output layout (floats)
#define LOGITS_OFF 0
#define DNC_OFF    64
#define MIX_OFF    131136ull              // 64 + 32*4096
#define RL_OFF     33685568ull            // MIX_OFF + 32*256*4096

// ---------------- static device scratch (no runtime allocs) ----------------
__device__ __half g_mx16[8192ull * 4096]; // fp16 mixing copy [b*256+t][4096]
__device__ __half g_w1h[2048ull * 4096];  // clf1_w fp16
__device__ __half g_w2h[1024ull * 2048];  // clf2_w fp16
__device__ __half g_h1h[8192ull * 2048];  // h1 fp16
__device__ float g_lg[512 * 64];          // layer2 fused-clf3 partials [t2][b*2+o]
__device__ float g_rl[BB];
__device__ int   g_ticket;
__device__ int   g_progress[BB];
__device__ int   g_rbdone[64];
__device__ int   g_pk1done;
__device__ int   g_pk2done;

// ============================================================================
// Base-ISA PTX helpers (sm_80+)
// ============================================================================
__device__ __forceinline__ uint32_t smem_u32(const void* p) {
    uint32_t a;
    asm("{ .reg .u64 t; cvta.to.shared.u64 t, %1; cvt.u32.u64 %0, t; }" : "=r"(a) : "l"(p));
    return a;
}
#define CP16(dst, src) \
    asm volatile("cp.async.cg.shared.global [%0], [%1], 16;" :: "r"(dst), "l"(src))
#define CP_COMMIT() asm volatile("cp.async.commit_group;" ::: "memory")
#define CP_WAIT1()  asm volatile("cp.async.wait_group 1;" ::: "memory")
#define CP_WAIT0()  asm volatile("cp.async.wait_group 0;" ::: "memory")
#define LDSM4(R, addr) \
    asm volatile("ldmatrix.sync.aligned.m8n8.x4.shared.b16 {%0,%1,%2,%3}, [%4];" \
        : "=r"((R)[0]), "=r"((R)[1]), "=r"((R)[2]), "=r"((R)[3]) : "r"(addr))
#define LDSM2(R, addr) \
    asm volatile("ldmatrix.sync.aligned.m8n8.x2.shared.b16 {%0,%1}, [%2];" \
        : "=r"((R)[0]), "=r"((R)[1]) : "r"(addr))
#define MMAH(D, A, Bf) \
    asm volatile("mma.sync.aligned.m16n8k16.row.col.f32.f16.f16.f32 " \
        "{%0,%1,%2,%3}, {%4,%5,%6,%7}, {%8,%9}, {%0,%1,%2,%3};" \
        : "+f"((D)[0]), "+f"((D)[1]), "+f"((D)[2]), "+f"((D)[3]) \
        : "r"((A)[0]), "r"((A)[1]), "r"((A)[2]), "r"((A)[3]), "r"((Bf)[0]), "r"((Bf)[1]))

// ---------------- shared mem layout for recurrent role (floats) ------------
// state arrays use ROW STRIDE 68 (multiple of 4 -> float4-aligned everywhere)
#define SRS 68
#define OFF_WHHT 0          /* [64][192] */
#define OFF_QWT  12288      /* [64][64]  */
#define OFF_KWT  16384
#define OFF_HT   20480      /* [64][68]  hT  */
#define OFF_HN   24832      /* [64][68]  hn  */
#define OFF_HNT  29184      /* [64][68]  hnT */
#define OFF_QT   33536
#define OFF_KT   37888
#define OFF_TRT  42240
#define OFF_XT   46592      /* [2][64] double buffer */
#define OFF_A    46720      /* [192] */
#define OFF_B0   46912
#define OFF_BHH  47104
#define OFF_QB   47296
#define OFF_KB   47360
#define OFF_PW   47424
#define OFF_RED  47488
#define SMEM_FLOATS 47552
#define SMEM_BYTES  (SMEM_FLOATS * 4)

// worker smem carve: bytes [0,16384) A bufs, [16384,32768) B bufs;
// floats: sred at s[8192..8448), ticket at s[8500]
#define W_SRED 8192
#define W_TK   8500

// ticket queue: 24 packs, then interleaved L1/L2 groups
#define NPK  24
#define NQ   1536
#define NTOT (NPK + NQ)

__device__ __forceinline__ float sigf(float x) { return 1.f / (1.f + __expf(-x)); }
__device__ __forceinline__ float tanh_fast(float x) {
    float e = __expf(2.f * x);
    return __fdividef(e - 1.f, e + 1.f);
}

// tile row r (0..127) of rowgroup tg -> global (b*256+t) row
__device__ __forceinline__ int arow_map(int tg, int r) {
    return (r >> 2) * 256 + tg * 4 + (r & 3);
}

// ============================================================================
__global__ void init_kernel() {
    int tid = threadIdx.x;
    if (tid == 0) { g_ticket = 0; g_pk1done = 0; g_pk2done = 0; }
    if (tid < BB) g_progress[tid] = 0;
    if (tid < 64) g_rbdone[tid] = 0;
}

// ============================================================================
// fp16 mma.sync GEMM tile (proven in R9)
// ============================================================================
__device__ void gemm16(float* s, const __half* __restrict__ Ah,
                       const __half* __restrict__ Bh,
                       const float* __restrict__ bias, int K,
                       int tg, int nb, int layer,
                       const float* __restrict__ w3, int t2)
{
    const int tid = threadIdx.x, lane = tid & 31, wid = tid >> 5;
    const int wm = wid & 1, wn = wid >> 1;
    const int n_blk = nb * 128;
    const uint32_t sAb = smem_u32(s);
    const uint32_t sBb = sAb + 16384;

    const int lr = tid >> 1, lc = (tid & 1) * 2;
    const uint32_t swl = (lr >> 1) & 3;
    const uint32_t dA0 = sAb + lr * 64 + (((uint32_t)lc ^ swl) << 4);
    const uint32_t dA1 = sAb + lr * 64 + (((uint32_t)(lc + 1) ^ swl) << 4);
    const uint32_t dB0 = sBb + lr * 64 + (((uint32_t)lc ^ swl) << 4);
    const uint32_t dB1 = sBb + lr * 64 + (((uint32_t)(lc + 1) ^ swl) << 4);
    const long gA0 = (long)arow_map(tg, lr) * K + lc * 8;
    const long gB0 = (long)(n_blk + lr) * K + lc * 8;

    int rowA[4], swA[4], rowB[4], swB[4];
    const int halfA = (lane >> 4) & 1, halfB = (lane >> 3) & 1;
    #pragma unroll
    for (int mi = 0; mi < 4; mi++) {
        rowA[mi] = wm * 64 + mi * 16 + (lane & 15);
        swA[mi] = (rowA[mi] >> 1) & 3;
    }
    #pragma unroll
    for (int ni = 0; ni < 4; ni++) {
        rowB[ni] = wn * 32 + ni * 8 + (lane & 7);
        swB[ni] = (rowB[ni] >> 1) & 3;
    }

    float acc[4][4][4];
    #pragma unroll
    for (int mi = 0; mi < 4; mi++)
        #pragma unroll
        for (int ni = 0; ni < 4; ni++)
            #pragma unroll
            for (int r = 0; r < 4; r++) acc[mi][ni][r] = 0.f;

    const int iters = K / 32;
    {
        CP16(dA0, Ah + gA0);
        CP16(dA1, Ah + gA0 + 8);
        CP16(dB0, Bh + gB0);
        CP16(dB1, Bh + gB0 + 8);
        CP_COMMIT();
    }
    for (int it = 0; it < iters; ++it) {
        if (it + 1 < iters) {
            uint32_t bo = (uint32_t)((it + 1) & 1) * 8192;
            long ko = (long)(it + 1) * 32;
            CP16(dA0 + bo, Ah + gA0 + ko);
            CP16(dA1 + bo, Ah + gA0 + ko + 8);
            CP16(dB0 + bo, Bh + gB0 + ko);
            CP16(dB1 + bo, Bh + gB0 + ko + 8);
            CP_COMMIT();
            CP_WAIT1();
        } else {
            CP_WAIT0();
        }
        __syncthreads();

        uint32_t bo = (uint32_t)(it & 1) * 8192;
        #pragma unroll
        for (int ks = 0; ks < 2; ks++) {
            uint32_t a[4][4], bfr[4][2];
            #pragma unroll
            for (int mi = 0; mi < 4; mi++)
                LDSM4(a[mi], sAb + bo + rowA[mi] * 64 +
                             (((uint32_t)(2 * ks + halfA) ^ (uint32_t)swA[mi]) << 4));
            #pragma unroll
            for (int ni = 0; ni < 4; ni++)
                LDSM2(bfr[ni], sBb + bo + rowB[ni] * 64 +
                               (((uint32_t)(2 * ks + halfB) ^ (uint32_t)swB[ni]) << 4));
            #pragma unroll
            for (int mi = 0; mi < 4; mi++)
                #pragma unroll
                for (int ni = 0; ni < 4; ni++)
                    MMAH(acc[mi][ni], a[mi], bfr[ni]);
        }
        __syncthreads();
    }

    if (layer == 1) {
        #pragma unroll
        for (int mi = 0; mi < 4; mi++) {
            #pragma unroll
            for (int ni = 0; ni < 4; ni++) {
                int n0 = n_blk + wn * 32 + ni * 8 + (lane & 3) * 2;
                float bs0 = bias[n0], bs1 = bias[n0 + 1];
                #pragma unroll
                for (int h = 0; h < 2; h++) {
                    int ml = wm * 64 + mi * 16 + (lane >> 2) + h * 8;
                    int row = arow_map(tg, ml);
                    float v0 = fmaxf(acc[mi][ni][h * 2 + 0] + bs0, 0.f);
                    float v1 = fmaxf(acc[mi][ni][h * 2 + 1] + bs1, 0.f);
                    *(__half2*)(g_h1h + (long)row * 2048 + n0) =
                        __floats2half2_rn(v0, v1);
                }
            }
        }
    } else {
        float pa[4][2][2];
        #pragma unroll
        for (int mi = 0; mi < 4; mi++)
            #pragma unroll
            for (int h = 0; h < 2; h++) { pa[mi][h][0] = 0.f; pa[mi][h][1] = 0.f; }
        #pragma unroll
        for (int ni = 0; ni < 4; ni++) {
            int n0 = n_blk + wn * 32 + ni * 8 + (lane & 3) * 2;
            float bs0 = bias[n0], bs1 = bias[n0 + 1];
            float wa0 = w3[n0], wa1 = w3[n0 + 1];
            float wb0 = w3[1024 + n0], wb1 = w3[1024 + n0 + 1];
            #pragma unroll
            for (int mi = 0; mi < 4; mi++) {
                #pragma unroll
                for (int h = 0; h < 2; h++) {
                    float v0 = fmaxf(acc[mi][ni][h * 2 + 0] + bs0, 0.f);
                    float v1 = fmaxf(acc[mi][ni][h * 2 + 1] + bs1, 0.f);
                    pa[mi][h][0] = fmaf(v0, wa0, fmaf(v1, wa1, pa[mi][h][0]));
                    pa[mi][h][1] = fmaf(v0, wb0, fmaf(v1, wb1, pa[mi][h][1]));
                }
            }
        }
        #pragma unroll
        for (int mi = 0; mi < 4; mi++)
            #pragma unroll
            for (int h = 0; h < 2; h++)
                #pragma unroll
                for (int o = 0; o < 2; o++) {
                    float v = pa[mi][h][o];
                    #pragma unroll
                    for (int msk = 8; msk > 0; msk >>= 1)
                        v += __shfl_xor_sync(0xffffffffu, v, msk);
                    pa[mi][h][o] = v;
                }
        float* sred = s + W_SRED;   // [4 wn][32 bat][2 o]
        if ((lane & 15) == 0) {
            #pragma unroll
            for (int mi = 0; mi < 4; mi++)
                #pragma unroll
                for (int h = 0; h < 2; h++) {
                    int bat = wm * 16 + mi * 4 + 2 * h + (lane >> 4);
                    sred[(wn * 32 + bat) * 2 + 0] = pa[mi][h][0];
                    sred[(wn * 32 + bat) * 2 + 1] = pa[mi][h][1];
                }
        }
        __syncthreads();
        if (tid < 64) {
            int b = tid >> 1, o = tid & 1;
            float sv = sred[(0 * 32 + b) * 2 + o] + sred[(1 * 32 + b) * 2 + o]
                     + sred[(2 * 32 + b) * 2 + o] + sred[(3 * 32 + b) * 2 + o];
            g_lg[t2 * 64 + b * 2 + o] = sv;
        }
        __syncthreads();
    }
}

// ============================================================================
// Mega kernel
// ============================================================================
__global__ __launch_bounds__(256) void mega_kernel(
    const float* __restrict__ x,
    const float* __restrict__ emb_w, const float* __restrict__ emb_b,
    const float* __restrict__ w_ih, const float* __restrict__ w_hh,
    const float* __restrict__ b_ih, const float* __restrict__ b_hh,
    const float* __restrict__ q_w, const float* __restrict__ q_b,
    const float* __restrict__ k_w, const float* __restrict__ k_b,
    const float* __restrict__ gate_b,
    const float* __restrict__ pred_w, const float* __restrict__ pred_b,
    const float* __restrict__ clf1_w, const float* __restrict__ clf1_b,
    const float* __restrict__ clf2_w, const float* __restrict__ clf2_b,
    const float* __restrict__ clf3_w,
    float* __restrict__ out)
{
    extern __shared__ float s[];
    const int tid = threadIdx.x;

    // ------------------------------------------------------------------
    // Role 1: recurrence (blocks 0..31)
    // ------------------------------------------------------------------
    if (blockIdx.x < BB) {
        const int b = blockIdx.x;
        const int tx = tid & 15, ty = tid >> 4;
        const int c0 = ty * 4, j0 = tx * 4;

        for (int i = tid; i < 12288; i += 256) {
            int j = i / 64, h = i % 64;
            s[OFF_WHHT + h * 192 + j] = w_hh[i];
        }
        for (int i = tid; i < 4096; i += 256) {
            int j = i / 64, h = i % 64;
            s[OFF_QWT + h * 64 + j] = q_w[i];
            s[OFF_KWT + h * 64 + j] = k_w[i];
        }
        if (tid < 192) {
            float a = 0.f, b0v = 0.f;
            #pragma unroll
            for (int e = 0; e < 32; e++) {
                float w = w_ih[tid * 32 + e];
                a += w * emb_w[e];
                b0v += w * emb_b[e];
            }
            s[OFF_A + tid] = a;
            s[OFF_B0 + tid] = b0v + b_ih[tid];
            s[OFF_BHH + tid] = b_hh[tid];
        }
        if (tid < 64) {
            s[OFF_QB + tid] = q_b[tid];
            s[OFF_KB + tid] = k_b[tid];
            s[OFF_PW + tid] = pred_w[tid];
            s[OFF_XT + tid] = x[(size_t)b * TT * CC + tid];  // t=0
        }
        for (int i = tid; i < 64 * SRS; i += 256) s[OFF_HT + i] = 0.f;
        const float pb = pred_b[0];
        float errsum = 0.f;
        __syncthreads();

        // per-thread register caches
        float Ar[4], Az[4], An[4], B0r[4], B0z[4], B0n[4];
        float Br[4], Bz[4], Bn[4], QBv[4], KBv[4];
        #pragma unroll
        for (int ji = 0; ji < 4; ji++) {
            int j = j0 + ji;
            Ar[ji] = s[OFF_A + j];  Az[ji] = s[OFF_A + 64 + j];  An[ji] = s[OFF_A + 128 + j];
            B0r[ji] = s[OFF_B0 + j]; B0z[ji] = s[OFF_B0 + 64 + j]; B0n[ji] = s[OFF_B0 + 128 + j];
            Br[ji] = s[OFF_BHH + j]; Bz[ji] = s[OFF_BHH + 64 + j]; Bn[ji] = s[OFF_BHH + 128 + j];
            QBv[ji] = s[OFF_QB + j]; KBv[ji] = s[OFF_KB + j];
        }
        float GT[16], DNCr[16];
        #pragma unroll
        for (int ci = 0; ci < 4; ci++)
            #pragma unroll
            for (int ji = 0; ji < 4; ji++) {
                GT[ci * 4 + ji] = gate_b[(c0 + ci) * 64 + j0 + ji];
                DNCr[ci * 4 + ji] = 0.f;
            }

        for (int t = 0; t < TT; t++) {
            // ---- Phase 1: GRU hidden gemm (reads hT) ----
            float ar[16], az[16], an_[16];
            #pragma unroll
            for (int ji = 0; ji < 4; ji++)
                #pragma unroll
                for (int ci = 0; ci < 4; ci++) {
                    ar[ci*4+ji] = Br[ji]; az[ci*4+ji] = Bz[ji]; an_[ci*4+ji] = Bn[ji];
                }
            #pragma unroll 4
            for (int h = 0; h < 64; h++) {
                float4 hv4 = *(const float4*)&s[OFF_HT + h * SRS + c0];
                float4 wr4 = *(const float4*)&s[OFF_WHHT + h * 192 + j0];
                float4 wz4 = *(const float4*)&s[OFF_WHHT + h * 192 + 64 + j0];
                float4 wn4 = *(const float4*)&s[OFF_WHHT + h * 192 + 128 + j0];
                float hv[4] = {hv4.x, hv4.y, hv4.z, hv4.w};
                float wr[4] = {wr4.x, wr4.y, wr4.z, wr4.w};
                float wz[4] = {wz4.x, wz4.y, wz4.z, wz4.w};
                float wn[4] = {wn4.x, wn4.y, wn4.z, wn4.w};
                #pragma unroll
                for (int ci = 0; ci < 4; ci++)
                    #pragma unroll
                    for (int ji = 0; ji < 4; ji++) {
                        ar[ci*4+ji]  = fmaf(hv[ci], wr[ji], ar[ci*4+ji]);
                        az[ci*4+ji]  = fmaf(hv[ci], wz[ji], az[ci*4+ji]);
                        an_[ci*4+ji] = fmaf(hv[ci], wn[ji], an_[ci*4+ji]);
                    }
            }
            // ---- Phase 2: gates + hn / hnT writes ----
            float hnreg[16];
            float xv[4];
            #pragma unroll
            for (int ci = 0; ci < 4; ci++) xv[ci] = s[OFF_XT + (t & 1) * 64 + c0 + ci];
            #pragma unroll
            for (int ji = 0; ji < 4; ji++) {
                float4 hold4 = *(const float4*)&s[OFF_HT + (j0 + ji) * SRS + c0];
                float hold[4] = {hold4.x, hold4.y, hold4.z, hold4.w};
                float4 hnT4;
                #pragma unroll
                for (int ci = 0; ci < 4; ci++) {
                    float gir = fmaf(xv[ci], Ar[ji], B0r[ji]);
                    float giz = fmaf(xv[ci], Az[ji], B0z[ji]);
                    float gin = fmaf(xv[ci], An[ji], B0n[ji]);
                    float r = sigf(gir + ar[ci*4+ji]);
                    float z = sigf(giz + az[ci*4+ji]);
                    float n = tanh_fast(fmaf(r, an_[ci*4+ji], gin));
                    float hv = (1.f - z) * n + z * hold[ci];
                    hnreg[ci*4+ji] = hv;
                    (&hnT4.x)[ci] = hv;
                }
                *(float4*)&s[OFF_HNT + (j0 + ji) * SRS + c0] = hnT4;
            }
            #pragma unroll
            for (int ci = 0; ci < 4; ci++) {
                float4 v; v.x = hnreg[ci*4+0]; v.y = hnreg[ci*4+1];
                v.z = hnreg[ci*4+2]; v.w = hnreg[ci*4+3];
                *(float4*)&s[OFF_HN + (c0 + ci) * SRS + j0] = v;
            }
            __syncthreads();

            // ---- Phase 3: q/k gemm ----
            float aq[16], ak[16];
            #pragma unroll
            for (int ji = 0; ji < 4; ji++)
                #pragma unroll
                for (int ci = 0; ci < 4; ci++) { aq[ci*4+ji] = QBv[ji]; ak[ci*4+ji] = KBv[ji]; }
            #pragma unroll 4
            for (int h = 0; h < 64; h++) {
                float4 hv4 = *(const float4*)&s[OFF_HNT + h * SRS + c0];
                float4 qw4 = *(const float4*)&s[OFF_QWT + h * 64 + j0];
                float4 kw4 = *(const float4*)&s[OFF_KWT + h * 64 + j0];
                float hv[4] = {hv4.x, hv4.y, hv4.z, hv4.w};
                float qw[4] = {qw4.x, qw4.y, qw4.z, qw4.w};
                float kw[4] = {kw4.x, kw4.y, kw4.z, kw4.w};
                #pragma unroll
                for (int ci = 0; ci < 4; ci++)
                    #pragma unroll
                    for (int ji = 0; ji < 4; ji++) {
                        aq[ci*4+ji] = fmaf(hv[ci], qw[ji], aq[ci*4+ji]);
                        ak[ci*4+ji] = fmaf(hv[ci], kw[ji], ak[ci*4+ji]);
                    }
            }
            #pragma unroll
            for (int ji = 0; ji < 4; ji++) {
                float4 qv; qv.x = aq[0+ji]; qv.y = aq[4+ji]; qv.z = aq[8+ji]; qv.w = aq[12+ji];
                float4 kv; kv.x = ak[0+ji]; kv.y = ak[4+ji]; kv.z = ak[8+ji]; kv.w = ak[12+ji];
                *(float4*)&s[OFF_QT + (j0 + ji) * SRS + c0] = qv;
                *(float4*)&s[OFF_KT + (j0 + ji) * SRS + c0] = kv;
            }
            __syncthreads();

            // ---- Phase 4: transfer = q @ k^T, norm, tanh, gate ----
            float at[16];
            #pragma unroll
            for (int i = 0; i < 16; i++) at[i] = 0.f;
            #pragma unroll 4
            for (int h = 0; h < 64; h++) {
                float4 qv4 = *(const float4*)&s[OFF_QT + h * SRS + c0];
                float4 kv4 = *(const float4*)&s[OFF_KT + h * SRS + j0];
                float qv[4] = {qv4.x, qv4.y, qv4.z, qv4.w};
                float kv[4] = {kv4.x, kv4.y, kv4.z, kv4.w};
                #pragma unroll
                for (int ci = 0; ci < 4; ci++)
                    #pragma unroll
                    for (int ji = 0; ji < 4; ji++)
                        at[ci*4+ji] = fmaf(qv[ci], kv[ji], at[ci*4+ji]);
            }
            float ssq = 0.f;
            #pragma unroll
            for (int i = 0; i < 16; i++) ssq = fmaf(at[i], at[i], ssq);
            #pragma unroll
            for (int o = 16; o > 0; o >>= 1) ssq += __shfl_xor_sync(0xffffffffu, ssq, o);
            if ((tid & 31) == 0) s[OFF_RED + (tid >> 5)] = ssq;
            __syncthreads();
            float tot = 0.f;
            #pragma unroll
            for (int w = 0; w < 8; w++) tot += s[OFF_RED + w];
            float rn = 1.f / sqrtf(tot);

            size_t rowbase = (size_t)(b * TT + t) * 4096;
            size_t mixbase = MIX_OFF + rowbase;
            float tt[16];
            #pragma unroll
            for (int ci = 0; ci < 4; ci++) {
                int c = c0 + ci;
                #pragma unroll
                for (int ji = 0; ji < 4; ji++) {
                    float tv = tanh_fast(at[ci*4+ji] * rn);
                    float g = sigf(fabsf(tv) + GT[ci*4+ji]);
                    tv *= g;
                    tt[ci*4+ji] = tv;
                    DNCr[ci*4+ji] += tv;
                }
                float4 v; v.x = tt[ci*4+0]; v.y = tt[ci*4+1]; v.z = tt[ci*4+2]; v.w = tt[ci*4+3];
                *(float4*)&out[mixbase + (size_t)c * 64 + j0] = v;
                __half* mp = g_mx16 + rowbase + (size_t)c * 64 + j0;
                *(__half2*)(mp)     = __floats2half2_rn(v.x, v.y);
                *(__half2*)(mp + 2) = __floats2half2_rn(v.z, v.w);
            }
            #pragma unroll
            for (int ji = 0; ji < 4; ji++) {
                float4 v; v.x = tt[0+ji]; v.y = tt[4+ji]; v.z = tt[8+ji]; v.w = tt[12+ji];
                *(float4*)&s[OFF_TRT + (j0 + ji) * SRS + c0] = v;
            }
            // prefetch x for t+1 (other parity buffer)
            if (tid < 64 && t + 1 < TT)
                s[OFF_XT + ((t + 1) & 1) * 64 + tid] = x[((size_t)b * TT + t + 1) * CC + tid];
            __syncthreads();
            if (tid == 0) { __threadfence(); atomicExch(&g_progress[b], t + 1); }

            // ---- Phase 5: h_next = transfer @ h_new -> hT ----
            float ah[16];
            #pragma unroll
            for (int i = 0; i < 16; i++) ah[i] = 0.f;
            #pragma unroll 4
            for (int d = 0; d < 64; d++) {
                float4 tv4 = *(const float4*)&s[OFF_TRT + d * SRS + c0];
                float4 hv4 = *(const float4*)&s[OFF_HN + d * SRS + j0];
                float tv[4] = {tv4.x, tv4.y, tv4.z, tv4.w};
                float hv[4] = {hv4.x, hv4.y, hv4.z, hv4.w};
                #pragma unroll
                for (int ci = 0; ci < 4; ci++)
                    #pragma unroll
                    for (int ji = 0; ji < 4; ji++)
                        ah[ci*4+ji] = fmaf(tv[ci], hv[ji], ah[ci*4+ji]);
            }
            #pragma unroll
            for (int ji = 0; ji < 4; ji++) {
                float4 v; v.x = ah[0+ji]; v.y = ah[4+ji]; v.z = ah[8+ji]; v.w = ah[12+ji];
                *(float4*)&s[OFF_HT + (j0 + ji) * SRS + c0] = v;
            }
            __syncthreads();

            // ---- prediction / rec_loss ----
            if (tid < 64 && t >= 1) {
                float p = pb;
                #pragma unroll 8
                for (int h = 0; h < 64; h++)
                    p = fmaf(s[OFF_HT + h * SRS + tid], s[OFF_PW + h], p);
                float dd = p - s[OFF_XT + (t & 1) * 64 + tid];
                errsum = fmaf(dd, dd, errsum);
            }
        }

        // DNC output from registers
        #pragma unroll
        for (int ci = 0; ci < 4; ci++) {
            float4 v;
            v.x = DNCr[ci*4+0] * (1.f / 256.f);
            v.y = DNCr[ci*4+1] * (1.f / 256.f);
            v.z = DNCr[ci*4+2] * (1.f / 256.f);
            v.w = DNCr[ci*4+3] * (1.f / 256.f);
            *(float4*)&out[DNC_OFF + (size_t)b * 4096 + (size_t)(c0 + ci) * 64 + j0] = v;
        }

        #pragma unroll
        for (int o = 16; o > 0; o >>= 1) errsum += __shfl_xor_sync(0xffffffffu, errsum, o);
        __syncthreads();
        if ((tid & 31) == 0) s[OFF_RED + (tid >> 5)] = errsum;
        __syncthreads();
        if (tid == 0) {
            float totv = 0.f;
            #pragma unroll
            for (int w = 0; w < 8; w++) totv += s[OFF_RED + w];
            g_rl[b] = totv;
        }
        __syncthreads();   // done; fall through to worker role
    }

    // ------------------------------------------------------------------
    // Role 2: worker (all blocks): pack weights, then fp16 GEMM tiles
    // ------------------------------------------------------------------
    int* stk = (int*)&s[W_TK];
    for (;;) {
        __syncthreads();
        if (tid == 0) stk[0] = atomicAdd(&g_ticket, 1);
        __syncthreads();
        int tk = stk[0];
        if (tk >= NTOT) break;

        if (tk < NPK) {
            if (tk < 16) {
                long base = (long)tk * 524288;
                const float2* src = (const float2*)(clf1_w + base);
                __half2* dst = (__half2*)(g_w1h + base);
                for (int i = tid; i < 262144; i += 256) {
                    float2 v = src[i];
                    dst[i] = __floats2half2_rn(v.x, v.y);
                }
                __threadfence();
                __syncthreads();
                if (tid == 0) atomicAdd(&g_pk1done, 1);
            } else {
                long base = (long)(tk - 16) * 262144;
                const float2* src = (const float2*)(clf2_w + base);
                __half2* dst = (__half2*)(g_w2h + base);
                for (int i = tid; i < 131072; i += 256) {
                    float2 v = src[i];
                    dst[i] = __floats2half2_rn(v.x, v.y);
                }
                __threadfence();
                __syncthreads();
                if (tid == 0) atomicAdd(&g_pk2done, 1);
            }
            continue;
        }

        int u = tk - NPK;
        int ly, tg, nb;
        if (u < 16) { ly = 1; tg = 0; nb = u; }
        else if (u < 16 + 63 * 24) {
            int v = u - 16, g = v / 24, r = v - g * 24;
            if (r < 8) { ly = 2; tg = g; nb = r; }
            else       { ly = 1; tg = g + 1; nb = r - 8; }
        } else { ly = 2; tg = 63; nb = u - (16 + 63 * 24); }

        if (ly == 1) {
            if (tid == 0) {
                volatile int* pk = &g_pk1done;
                while (*pk < 16) __nanosleep(128);
                int need = (tg + 1) * 4;
                for (int bi = 0; bi < BB; bi++) {
                    volatile int* p = &g_progress[bi];
                    while (*p < need) __nanosleep(128);
                }
                __threadfence();
            }
            __syncthreads();
            gemm16(s, g_mx16, g_w1h, clf1_b, 4096, tg, nb, 1, nullptr, 0);
            __threadfence();
            __syncthreads();
            if (tid == 0) atomicAdd(&g_rbdone[tg], 1);
        } else {
            if (tid == 0) {
                volatile int* pk = &g_pk2done;
                while (*pk < 8) __nanosleep(128);
                volatile int* rd = &g_rbdone[tg];
                while (*rd < 16) __nanosleep(128);
                __threadfence();
            }
            __syncthreads();
            gemm16(s, g_h1h, g_w2h, clf2_b, 2048, tg, nb, 2, clf3_w, tg * 8 + nb);
        }
    }
}

// ============================================================================
__global__ void finalize_kernel(const float* __restrict__ b3, float* __restrict__ out)
{
    int tid = threadIdx.x;
    if (tid < 64) {
        int b = tid >> 1, o = tid & 1;
        float sv = 0.f;
        for (int t2 = 0; t2 < 512; t2++)
            sv += g_lg[t2 * 64 + b * 2 + o];
        out[(size_t)b * 2 + o] = sv * (1.f / 256.f) + b3[o];
    }
    if (tid == 64) {
        float ss = 0.f;
        #pragma unroll
        for (int i = 0; i < BB; i++) ss += g_rl[i];
        out[RL_OFF] = ss / (32.f * 255.f * 64.f);
    }
}

// ============================================================================
extern "C" void kernel_launch(void* const* d_in, const int* in_sizes, int n_in,
                              void* d_out, int out_size)
{
    const float* x      = (const float*)d_in[0];
    const float* emb_w  = (const float*)d_in[1];
    const float* emb_b  = (const float*)d_in[2];
    const float* w_ih   = (const float*)d_in[3];
    const float* w_hh   = (const float*)d_in[4];
    const float* b_ih   = (const float*)d_in[5];
    const float* b_hh   = (const float*)d_in[6];
    const float* q_w    = (const float*)d_in[7];
    const float* q_b    = (const float*)d_in[8];
    const float* k_w    = (const float*)d_in[9];
    const float* k_b    = (const float*)d_in[10];
    const float* gate_b = (const float*)d_in[11];
    const float* pred_w = (const float*)d_in[12];
    const float* pred_b = (const float*)d_in[13];
    const float* clf1_w = (const float*)d_in[14];
    const float* clf1_b = (const float*)d_in[15];
    const float* clf2_w = (const float*)d_in[16];
    const float* clf2_b = (const float*)d_in[17];
    const float* clf3_w = (const float*)d_in[18];
    const float* clf3_b = (const float*)d_in[19];
    float* out = (float*)d_out;

    cudaFuncSetAttribute(mega_kernel,
                         cudaFuncAttributeMaxDynamicSharedMemorySize, SMEM_BYTES);

    init_kernel<<<1, 128>>>();
    mega_kernel<<<NSM, 256, SMEM_BYTES>>>(
        x, emb_w, emb_b, w_ih, w_hh, b_ih, b_hh,
        q_w, q_b, k_w, k_b, gate_b, pred_w, pred_b,
        clf1_w, clf1_b, clf2_w, clf2_b, clf3_w, out);
    finalize_kernel<<<1, 128>>>(clf3_b, out);
}

// round 12
// speedup vs baseline: 2.4694x; 1.1158x over previous
#include <cuda_runtime.h>
#include <cuda_fp16.h>
#include <math.h>
#include <stdint.h>

// Problem dims
#define BB 32
#define TT 256
#define CC 64
#define HH 64
#define NSM 148

// Output layout (floats)
#define LOGITS_OFF 0
#define DNC_OFF    64
#define MIX_OFF    131136ull              // 64 + 32*4096
#define RL_OFF     33685568ull            // MIX_OFF + 32*256*4096

// ---------------- static device scratch (no runtime allocs) ----------------
__device__ __half g_mx16[8192ull * 4096]; // fp16 mixing copy [b*256+t][4096]
__device__ __half g_w1h[2048ull * 4096];  // clf1_w fp16
__device__ __half g_w2h[1024ull * 2048];  // clf2_w fp16
__device__ __half g_h1h[8192ull * 2048];  // h1 fp16
__device__ float g_lg[512 * 64];          // layer2 fused-clf3 partials
__device__ float g_rl[64];
__device__ int   g_ticket;
__device__ int   g_progress[64];          // per half-CTA, value = t+1
__device__ int   g_rbdone[64];
__device__ int   g_pk1done;
__device__ int   g_pk2done;
// recurrence pair-exchange buffers (double buffered by t parity)
__device__ float g_xhn[64 * 2 * 2048];    // [bidx][parity][32*64]
__device__ float g_xk [64 * 2 * 2048];
__device__ float g_xssq[64 * 2];
__device__ int   g_fhn[64];
__device__ int   g_fk[64];
__device__ int   g_fssq[64];

// ============================================================================
// Base-ISA PTX helpers (sm_80+)
// ============================================================================
__device__ __forceinline__ uint32_t smem_u32(const void* p) {
    uint32_t a;
    asm("{ .reg .u64 t; cvta.to.shared.u64 t, %1; cvt.u32.u64 %0, t; }" : "=r"(a) : "l"(p));
    return a;
}
#define CP16(dst, src) \
    asm volatile("cp.async.cg.shared.global [%0], [%1], 16;" :: "r"(dst), "l"(src))
#define CP_COMMIT() asm volatile("cp.async.commit_group;" ::: "memory")
#define CP_WAIT1()  asm volatile("cp.async.wait_group 1;" ::: "memory")
#define CP_WAIT0()  asm volatile("cp.async.wait_group 0;" ::: "memory")
#define LDSM4(R, addr) \
    asm volatile("ldmatrix.sync.aligned.m8n8.x4.shared.b16 {%0,%1,%2,%3}, [%4];" \
        : "=r"((R)[0]), "=r"((R)[1]), "=r"((R)[2]), "=r"((R)[3]) : "r"(addr))
#define LDSM2(R, addr) \
    asm volatile("ldmatrix.sync.aligned.m8n8.x2.shared.b16 {%0,%1}, [%2];" \
        : "=r"((R)[0]), "=r"((R)[1]) : "r"(addr))
#define MMAH(D, A, Bf) \
    asm volatile("mma.sync.aligned.m16n8k16.row.col.f32.f16.f16.f32 " \
        "{%0,%1,%2,%3}, {%4,%5,%6,%7}, {%8,%9}, {%0,%1,%2,%3};" \
        : "+f"((D)[0]), "+f"((D)[1]), "+f"((D)[2]), "+f"((D)[3]) \
        : "r"((A)[0]), "r"((A)[1]), "r"((A)[2]), "r"((A)[3]), "r"((Bf)[0]), "r"((Bf)[1]))

// ---------------- shared mem layout (floats) --------------------------------
#define OFF_WHHT 0          /* [64][192] */
#define OFF_QWT  12288      /* [64][64]  */
#define OFF_KWT  16384      /* [64][64]  */
#define OFF_HT   20480      /* [64 j][34 c-own]  h transposed */
#define OFF_HNT  22656      /* [64 h][34 c-own]  hn transposed */
#define OFF_QROW 24832      /* [32 c][68 a] */
#define OFF_KROW 27008      /* [64 d][68 a]  full (own + peer) */
#define OFF_HNF  31360      /* [64 d][68 j]  full hn */
#define OFF_TRT  35712      /* [64 d][34 c-own] */
#define OFF_TRR  37888      /* [32 c][68 d] */
#define OFF_XT   40064      /* [2][32] */
#define OFF_A    40128      /* [192] */
#define OFF_B0   40320
#define OFF_BHH  40512
#define OFF_QB   40704
#define OFF_KB   40768
#define OFF_PW   40832
#define OFF_RED  40896      /* [16] */
#define SMEM_FLOATS 40960
#define SMEM_BYTES  (SMEM_FLOATS * 4)

// worker smem carve: bytes [0,32768) A/B bufs; floats: sred s[8192..), tk s[8500]
#define W_SRED 8192
#define W_TK   8500

#define NPK  24
#define NQ   1536
#define NTOT (NPK + NQ)

__device__ __forceinline__ float sigf(float x) { return 1.f / (1.f + __expf(-x)); }
__device__ __forceinline__ float tanh_fast(float x) {
    float e = __expf(2.f * x);
    return __fdividef(e - 1.f, e + 1.f);
}
__device__ __forceinline__ int arow_map(int tg, int r) {
    return (r >> 2) * 256 + tg * 4 + (r & 3);
}

// ============================================================================
__global__ void init_kernel() {
    int tid = threadIdx.x;
    if (tid == 0) { g_ticket = 0; g_pk1done = 0; g_pk2done = 0; }
    if (tid < 64) {
        g_progress[tid] = 0;
        g_rbdone[tid] = 0;
        g_fhn[tid] = 0;
        g_fk[tid] = 0;
        g_fssq[tid] = 0;
    }
}

// ============================================================================
// fp16 mma.sync GEMM tile (proven R9/R11)
// ============================================================================
__device__ void gemm16(float* s, const __half* __restrict__ Ah,
                       const __half* __restrict__ Bh,
                       const float* __restrict__ bias, int K,
                       int tg, int nb, int layer,
                       const float* __restrict__ w3, int t2)
{
    const int tid = threadIdx.x, lane = tid & 31, wid = tid >> 5;
    const int wm = wid & 1, wn = wid >> 1;
    const int n_blk = nb * 128;
    const uint32_t sAb = smem_u32(s);
    const uint32_t sBb = sAb + 16384;

    const int lr = tid >> 1, lc = (tid & 1) * 2;
    const uint32_t swl = (lr >> 1) & 3;
    const uint32_t dA0 = sAb + lr * 64 + (((uint32_t)lc ^ swl) << 4);
    const uint32_t dA1 = sAb + lr * 64 + (((uint32_t)(lc + 1) ^ swl) << 4);
    const uint32_t dB0 = sBb + lr * 64 + (((uint32_t)lc ^ swl) << 4);
    const uint32_t dB1 = sBb + lr * 64 + (((uint32_t)(lc + 1) ^ swl) << 4);
    const long gA0 = (long)arow_map(tg, lr) * K + lc * 8;
    const long gB0 = (long)(n_blk + lr) * K + lc * 8;

    int rowA[4], swA[4], rowB[4], swB[4];
    const int halfA = (lane >> 4) & 1, halfB = (lane >> 3) & 1;
    #pragma unroll
    for (int mi = 0; mi < 4; mi++) {
        rowA[mi] = wm * 64 + mi * 16 + (lane & 15);
        swA[mi] = (rowA[mi] >> 1) & 3;
    }
    #pragma unroll
    for (int ni = 0; ni < 4; ni++) {
        rowB[ni] = wn * 32 + ni * 8 + (lane & 7);
        swB[ni] = (rowB[ni] >> 1) & 3;
    }

    float acc[4][4][4];
    #pragma unroll
    for (int mi = 0; mi < 4; mi++)
        #pragma unroll
        for (int ni = 0; ni < 4; ni++)
            #pragma unroll
            for (int r = 0; r < 4; r++) acc[mi][ni][r] = 0.f;

    const int iters = K / 32;
    {
        CP16(dA0, Ah + gA0);
        CP16(dA1, Ah + gA0 + 8);
        CP16(dB0, Bh + gB0);
        CP16(dB1, Bh + gB0 + 8);
        CP_COMMIT();
    }
    for (int it = 0; it < iters; ++it) {
        if (it + 1 < iters) {
            uint32_t bo = (uint32_t)((it + 1) & 1) * 8192;
            long ko = (long)(it + 1) * 32;
            CP16(dA0 + bo, Ah + gA0 + ko);
            CP16(dA1 + bo, Ah + gA0 + ko + 8);
            CP16(dB0 + bo, Bh + gB0 + ko);
            CP16(dB1 + bo, Bh + gB0 + ko + 8);
            CP_COMMIT();
            CP_WAIT1();
        } else {
            CP_WAIT0();
        }
        __syncthreads();

        uint32_t bo = (uint32_t)(it & 1) * 8192;
        #pragma unroll
        for (int ks = 0; ks < 2; ks++) {
            uint32_t a[4][4], bfr[4][2];
            #pragma unroll
            for (int mi = 0; mi < 4; mi++)
                LDSM4(a[mi], sAb + bo + rowA[mi] * 64 +
                             (((uint32_t)(2 * ks + halfA) ^ (uint32_t)swA[mi]) << 4));
            #pragma unroll
            for (int ni = 0; ni < 4; ni++)
                LDSM2(bfr[ni], sBb + bo + rowB[ni] * 64 +
                               (((uint32_t)(2 * ks + halfB) ^ (uint32_t)swB[ni]) << 4));
            #pragma unroll
            for (int mi = 0; mi < 4; mi++)
                #pragma unroll
                for (int ni = 0; ni < 4; ni++)
                    MMAH(acc[mi][ni], a[mi], bfr[ni]);
        }
        __syncthreads();
    }

    if (layer == 1) {
        #pragma unroll
        for (int mi = 0; mi < 4; mi++) {
            #pragma unroll
            for (int ni = 0; ni < 4; ni++) {
                int n0 = n_blk + wn * 32 + ni * 8 + (lane & 3) * 2;
                float bs0 = bias[n0], bs1 = bias[n0 + 1];
                #pragma unroll
                for (int h = 0; h < 2; h++) {
                    int ml = wm * 64 + mi * 16 + (lane >> 2) + h * 8;
                    int row = arow_map(tg, ml);
                    float v0 = fmaxf(acc[mi][ni][h * 2 + 0] + bs0, 0.f);
                    float v1 = fmaxf(acc[mi][ni][h * 2 + 1] + bs1, 0.f);
                    *(__half2*)(g_h1h + (long)row * 2048 + n0) =
                        __floats2half2_rn(v0, v1);
                }
            }
        }
    } else {
        float pa[4][2][2];
        #pragma unroll
        for (int mi = 0; mi < 4; mi++)
            #pragma unroll
            for (int h = 0; h < 2; h++) { pa[mi][h][0] = 0.f; pa[mi][h][1] = 0.f; }
        #pragma unroll
        for (int ni = 0; ni < 4; ni++) {
            int n0 = n_blk + wn * 32 + ni * 8 + (lane & 3) * 2;
            float bs0 = bias[n0], bs1 = bias[n0 + 1];
            float wa0 = w3[n0], wa1 = w3[n0 + 1];
            float wb0 = w3[1024 + n0], wb1 = w3[1024 + n0 + 1];
            #pragma unroll
            for (int mi = 0; mi < 4; mi++) {
                #pragma unroll
                for (int h = 0; h < 2; h++) {
                    float v0 = fmaxf(acc[mi][ni][h * 2 + 0] + bs0, 0.f);
                    float v1 = fmaxf(acc[mi][ni][h * 2 + 1] + bs1, 0.f);
                    pa[mi][h][0] = fmaf(v0, wa0, fmaf(v1, wa1, pa[mi][h][0]));
                    pa[mi][h][1] = fmaf(v0, wb0, fmaf(v1, wb1, pa[mi][h][1]));
                }
            }
        }
        #pragma unroll
        for (int mi = 0; mi < 4; mi++)
            #pragma unroll
            for (int h = 0; h < 2; h++)
                #pragma unroll
                for (int o = 0; o < 2; o++) {
                    float v = pa[mi][h][o];
                    #pragma unroll
                    for (int msk = 8; msk > 0; msk >>= 1)
                        v += __shfl_xor_sync(0xffffffffu, v, msk);
                    pa[mi][h][o] = v;
                }
        float* sred = s + W_SRED;
        if ((lane & 15) == 0) {
            #pragma unroll
            for (int mi = 0; mi < 4; mi++)
                #pragma unroll
                for (int h = 0; h < 2; h++) {
                    int bat = wm * 16 + mi * 4 + 2 * h + (lane >> 4);
                    sred[(wn * 32 + bat) * 2 + 0] = pa[mi][h][0];
                    sred[(wn * 32 + bat) * 2 + 1] = pa[mi][h][1];
                }
        }
        __syncthreads();
        if (tid < 64) {
            int b = tid >> 1, o = tid & 1;
            float sv = sred[(0 * 32 + b) * 2 + o] + sred[(1 * 32 + b) * 2 + o]
                     + sred[(2 * 32 + b) * 2 + o] + sred[(3 * 32 + b) * 2 + o];
            g_lg[t2 * 64 + b * 2 + o] = sv;
        }
        __syncthreads();
    }
}

// ============================================================================
// Mega kernel: blocks 0..63 = split recurrence (2 CTAs per batch), then workers
// ============================================================================
__global__ __launch_bounds__(256) void mega_kernel(
    const float* __restrict__ x,
    const float* __restrict__ emb_w, const float* __restrict__ emb_b,
    const float* __restrict__ w_ih, const float* __restrict__ w_hh,
    const float* __restrict__ b_ih, const float* __restrict__ b_hh,
    const float* __restrict__ q_w, const float* __restrict__ q_b,
    const float* __restrict__ k_w, const float* __restrict__ k_b,
    const float* __restrict__ gate_b,
    const float* __restrict__ pred_w, const float* __restrict__ pred_b,
    const float* __restrict__ clf1_w, const float* __restrict__ clf1_b,
    const float* __restrict__ clf2_w, const float* __restrict__ clf2_b,
    const float* __restrict__ clf3_w,
    float* __restrict__ out)
{
    extern __shared__ float s[];
    const int tid = threadIdx.x;
    const int bidx = blockIdx.x;

    if (bidx < 64) {
        const int b = bidx >> 1, half = bidx & 1, pidx = bidx ^ 1;
        const int ph = half ^ 1;
        const int tx = tid & 15, ty = tid >> 4;
        const int j0 = 4 * tx;

        // ---- weight loads ----
        for (int i = tid; i < 12288; i += 256) {
            int j = i / 64, h = i % 64;
            s[OFF_WHHT + h * 192 + j] = w_hh[i];
        }
        for (int i = tid; i < 4096; i += 256) {
            int j = i / 64, h = i % 64;
            s[OFF_QWT + h * 64 + j] = q_w[i];
            s[OFF_KWT + h * 64 + j] = k_w[i];
        }
        if (tid < 192) {
            float a = 0.f, b0v = 0.f;
            #pragma unroll
            for (int e = 0; e < 32; e++) {
                float w = w_ih[tid * 32 + e];
                a += w * emb_w[e];
                b0v += w * emb_b[e];
            }
            s[OFF_A + tid] = a;
            s[OFF_B0 + tid] = b0v + b_ih[tid];
            s[OFF_BHH + tid] = b_hh[tid];
        }
        if (tid < 64) {
            s[OFF_QB + tid] = q_b[tid];
            s[OFF_KB + tid] = k_b[tid];
            s[OFF_PW + tid] = pred_w[tid];
        }
        if (tid < 32)
            s[OFF_XT + tid] = x[(size_t)b * TT * CC + half * 32 + tid];
        for (int i = tid; i < 64 * 34; i += 256) s[OFF_HT + i] = 0.f;
        const float pb = pred_b[0];
        float errsum = 0.f;
        __syncthreads();

        // register caches (j/a dim = j0 = 4tx)
        float Ar[4], Az[4], An[4], B0r[4], B0z[4], B0n[4];
        float Br[4], Bz[4], Bn[4], QBv[4], KBv[4];
        #pragma unroll
        for (int ji = 0; ji < 4; ji++) {
            int j = j0 + ji;
            Ar[ji] = s[OFF_A + j];  Az[ji] = s[OFF_A + 64 + j];  An[ji] = s[OFF_A + 128 + j];
            B0r[ji] = s[OFF_B0 + j]; B0z[ji] = s[OFF_B0 + 64 + j]; B0n[ji] = s[OFF_B0 + 128 + j];
            Br[ji] = s[OFF_BHH + j]; Bz[ji] = s[OFF_BHH + 64 + j]; Bn[ji] = s[OFF_BHH + 128 + j];
            QBv[ji] = s[OFF_QB + j]; KBv[ji] = s[OFF_KB + j];
        }
        // phase4 tiles: c = 2tx+cc (own local), d = 4ty+dd (global)
        float GT[8], DNCr[8];
        #pragma unroll
        for (int cc = 0; cc < 2; cc++)
            #pragma unroll
            for (int dd = 0; dd < 4; dd++) {
                GT[cc * 4 + dd] = gate_b[(half * 32 + 2 * tx + cc) * 64 + 4 * ty + dd];
                DNCr[cc * 4 + dd] = 0.f;
            }

        for (int t = 0; t < TT; t++) {
            const int par = t & 1;
            // ---- Phase 1: gh = h @ w_hh^T (c=2ty, j=4tx) ----
            float ar[8], az[8], an_[8];
            #pragma unroll
            for (int ji = 0; ji < 4; ji++) {
                ar[ji] = Br[ji];  ar[4 + ji] = Br[ji];
                az[ji] = Bz[ji];  az[4 + ji] = Bz[ji];
                an_[ji] = Bn[ji]; an_[4 + ji] = Bn[ji];
            }
            #pragma unroll 4
            for (int h = 0; h < 64; h++) {
                float2 hv2 = *(const float2*)&s[OFF_HT + h * 34 + 2 * ty];
                float4 wr4 = *(const float4*)&s[OFF_WHHT + h * 192 + j0];
                float4 wz4 = *(const float4*)&s[OFF_WHHT + h * 192 + 64 + j0];
                float4 wn4 = *(const float4*)&s[OFF_WHHT + h * 192 + 128 + j0];
                float wr[4] = {wr4.x, wr4.y, wr4.z, wr4.w};
                float wz[4] = {wz4.x, wz4.y, wz4.z, wz4.w};
                float wn[4] = {wn4.x, wn4.y, wn4.z, wn4.w};
                #pragma unroll
                for (int ji = 0; ji < 4; ji++) {
                    ar[ji]  = fmaf(hv2.x, wr[ji], ar[ji]);
                    az[ji]  = fmaf(hv2.x, wz[ji], az[ji]);
                    an_[ji] = fmaf(hv2.x, wn[ji], an_[ji]);
                    ar[4+ji]  = fmaf(hv2.y, wr[ji], ar[4+ji]);
                    az[4+ji]  = fmaf(hv2.y, wz[ji], az[4+ji]);
                    an_[4+ji] = fmaf(hv2.y, wn[ji], an_[4+ji]);
                }
            }
            // ---- Phase 2: gates -> hn ----
            float hnreg[8];
            float xv0 = s[OFF_XT + par * 32 + 2 * ty];
            float xv1 = s[OFF_XT + par * 32 + 2 * ty + 1];
            #pragma unroll
            for (int ji = 0; ji < 4; ji++) {
                float2 ho = *(const float2*)&s[OFF_HT + (j0 + ji) * 34 + 2 * ty];
                {
                    float gir = fmaf(xv0, Ar[ji], B0r[ji]);
                    float giz = fmaf(xv0, Az[ji], B0z[ji]);
                    float gin = fmaf(xv0, An[ji], B0n[ji]);
                    float r = sigf(gir + ar[ji]);
                    float z = sigf(giz + az[ji]);
                    float n = tanh_fast(fmaf(r, an_[ji], gin));
                    hnreg[ji] = (1.f - z) * n + z * ho.x;
                }
                {
                    float gir = fmaf(xv1, Ar[ji], B0r[ji]);
                    float giz = fmaf(xv1, Az[ji], B0z[ji]);
                    float gin = fmaf(xv1, An[ji], B0n[ji]);
                    float r = sigf(gir + ar[4+ji]);
                    float z = sigf(giz + az[4+ji]);
                    float n = tanh_fast(fmaf(r, an_[4+ji], gin));
                    hnreg[4 + ji] = (1.f - z) * n + z * ho.y;
                }
                float2 w2; w2.x = hnreg[ji]; w2.y = hnreg[4 + ji];
                *(float2*)&s[OFF_HNT + (j0 + ji) * 34 + 2 * ty] = w2;
            }
            {
                float* xb = &g_xhn[((size_t)bidx * 2 + par) * 2048];
                #pragma unroll
                for (int cc = 0; cc < 2; cc++) {
                    float4 v; v.x = hnreg[cc*4+0]; v.y = hnreg[cc*4+1];
                    v.z = hnreg[cc*4+2]; v.w = hnreg[cc*4+3];
                    *(float4*)&s[OFF_HNF + (half*32 + 2*ty + cc) * 68 + j0] = v;
                    *(float4*)&xb[(2*ty + cc) * 64 + j0] = v;
                }
            }
            __syncthreads();
            if (tid == 0) { __threadfence(); atomicExch(&g_fhn[bidx], t + 1); }

            // ---- Phase 3: q/k (c=2ty, a=4tx) ----
            float aq[8], ak[8];
            #pragma unroll
            for (int ji = 0; ji < 4; ji++) {
                aq[ji] = QBv[ji]; aq[4+ji] = QBv[ji];
                ak[ji] = KBv[ji]; ak[4+ji] = KBv[ji];
            }
            #pragma unroll 4
            for (int h = 0; h < 64; h++) {
                float2 hv2 = *(const float2*)&s[OFF_HNT + h * 34 + 2 * ty];
                float4 qw4 = *(const float4*)&s[OFF_QWT + h * 64 + j0];
                float4 kw4 = *(const float4*)&s[OFF_KWT + h * 64 + j0];
                float qw[4] = {qw4.x, qw4.y, qw4.z, qw4.w};
                float kw[4] = {kw4.x, kw4.y, kw4.z, kw4.w};
                #pragma unroll
                for (int ji = 0; ji < 4; ji++) {
                    aq[ji]   = fmaf(hv2.x, qw[ji], aq[ji]);
                    ak[ji]   = fmaf(hv2.x, kw[ji], ak[ji]);
                    aq[4+ji] = fmaf(hv2.y, qw[ji], aq[4+ji]);
                    ak[4+ji] = fmaf(hv2.y, kw[ji], ak[4+ji]);
                }
            }
            {
                float* xb = &g_xk[((size_t)bidx * 2 + par) * 2048];
                #pragma unroll
                for (int cc = 0; cc < 2; cc++) {
                    float4 qv; qv.x = aq[cc*4+0]; qv.y = aq[cc*4+1];
                    qv.z = aq[cc*4+2]; qv.w = aq[cc*4+3];
                    float4 kv; kv.x = ak[cc*4+0]; kv.y = ak[cc*4+1];
                    kv.z = ak[cc*4+2]; kv.w = ak[cc*4+3];
                    *(float4*)&s[OFF_QROW + (2*ty + cc) * 68 + j0] = qv;
                    *(float4*)&s[OFF_KROW + (half*32 + 2*ty + cc) * 68 + j0] = kv;
                    *(float4*)&xb[(2*ty + cc) * 64 + j0] = kv;
                }
            }
            __syncthreads();
            if (tid == 0) {
                __threadfence(); atomicExch(&g_fk[bidx], t + 1);
                volatile int* fk = &g_fk[pidx];
                while (*fk < t + 1) __nanosleep(64);
                volatile int* fh = &g_fhn[pidx];
                while (*fh < t + 1) __nanosleep(64);
            }
            __syncthreads();
            {   // import peer k and hn halves (L2 reads)
                int r = tid >> 3, c8 = (tid & 7) * 8;
                const float4* pk = (const float4*)&g_xk[((size_t)pidx * 2 + par) * 2048 + r * 64 + c8];
                float4 k0 = __ldcg(pk), k1 = __ldcg(pk + 1);
                *(float4*)&s[OFF_KROW + (ph*32 + r) * 68 + c8] = k0;
                *(float4*)&s[OFF_KROW + (ph*32 + r) * 68 + c8 + 4] = k1;
                const float4* phn = (const float4*)&g_xhn[((size_t)pidx * 2 + par) * 2048 + r * 64 + c8];
                float4 h0 = __ldcg(phn), h1 = __ldcg(phn + 1);
                *(float4*)&s[OFF_HNF + (ph*32 + r) * 68 + c8] = h0;
                *(float4*)&s[OFF_HNF + (ph*32 + r) * 68 + c8 + 4] = h1;
            }
            __syncthreads();

            // ---- Phase 4: tr = q k^T (c=2tx local, d=4ty) ----
            float tr[8];
            #pragma unroll
            for (int i = 0; i < 8; i++) tr[i] = 0.f;
            #pragma unroll 2
            for (int a4 = 0; a4 < 64; a4 += 4) {
                float4 q0 = *(const float4*)&s[OFF_QROW + (2*tx) * 68 + a4];
                float4 q1 = *(const float4*)&s[OFF_QROW + (2*tx + 1) * 68 + a4];
                float4 kv0 = *(const float4*)&s[OFF_KROW + (4*ty) * 68 + a4];
                float4 kv1 = *(const float4*)&s[OFF_KROW + (4*ty + 1) * 68 + a4];
                float4 kv2 = *(const float4*)&s[OFF_KROW + (4*ty + 2) * 68 + a4];
                float4 kv3 = *(const float4*)&s[OFF_KROW + (4*ty + 3) * 68 + a4];
                const float* qa0 = &q0.x; const float* qa1 = &q1.x;
                const float* kk0 = &kv0.x; const float* kk1 = &kv1.x;
                const float* kk2 = &kv2.x; const float* kk3 = &kv3.x;
                #pragma unroll
                for (int ai = 0; ai < 4; ai++) {
                    tr[0] = fmaf(qa0[ai], kk0[ai], tr[0]);
                    tr[1] = fmaf(qa0[ai], kk1[ai], tr[1]);
                    tr[2] = fmaf(qa0[ai], kk2[ai], tr[2]);
                    tr[3] = fmaf(qa0[ai], kk3[ai], tr[3]);
                    tr[4] = fmaf(qa1[ai], kk0[ai], tr[4]);
                    tr[5] = fmaf(qa1[ai], kk1[ai], tr[5]);
                    tr[6] = fmaf(qa1[ai], kk2[ai], tr[6]);
                    tr[7] = fmaf(qa1[ai], kk3[ai], tr[7]);
                }
            }
            float ssq = 0.f;
            #pragma unroll
            for (int i = 0; i < 8; i++) ssq = fmaf(tr[i], tr[i], ssq);
            #pragma unroll
            for (int o = 16; o > 0; o >>= 1) ssq += __shfl_xor_sync(0xffffffffu, ssq, o);
            if ((tid & 31) == 0) s[OFF_RED + (tid >> 5)] = ssq;
            __syncthreads();
            float ownTot = 0.f;
            #pragma unroll
            for (int w = 0; w < 8; w++) ownTot += s[OFF_RED + w];
            if (tid == 0) {
                g_xssq[bidx * 2 + par] = ownTot;
                __threadfence();
                atomicExch(&g_fssq[bidx], t + 1);
                volatile int* fs = &g_fssq[pidx];
                while (*fs < t + 1) __nanosleep(64);
                s[OFF_RED + 8] = *(volatile float*)&g_xssq[pidx * 2 + par];
            }
            __syncthreads();
            float rn = rsqrtf(ownTot + s[OFF_RED + 8]);

            // gates + writes
            float tt[8];
            #pragma unroll
            for (int cc = 0; cc < 2; cc++)
                #pragma unroll
                for (int dd = 0; dd < 4; dd++) {
                    float tv = tanh_fast(tr[cc*4+dd] * rn);
                    float g = sigf(fabsf(tv) + GT[cc*4+dd]);
                    tv *= g;
                    tt[cc*4+dd] = tv;
                    DNCr[cc*4+dd] += tv;
                }
            #pragma unroll
            for (int dd = 0; dd < 4; dd++) {
                float2 w2; w2.x = tt[dd]; w2.y = tt[4 + dd];
                *(float2*)&s[OFF_TRT + (4*ty + dd) * 34 + 2 * tx] = w2;
            }
            #pragma unroll
            for (int cc = 0; cc < 2; cc++) {
                float4 v; v.x = tt[cc*4+0]; v.y = tt[cc*4+1];
                v.z = tt[cc*4+2]; v.w = tt[cc*4+3];
                *(float4*)&s[OFF_TRR + (2*tx + cc) * 68 + 4 * ty] = v;
            }
            if (tid < 32 && t + 1 < TT)
                s[OFF_XT + ((t + 1) & 1) * 32 + tid] =
                    x[((size_t)b * TT + t + 1) * CC + half * 32 + tid];
            __syncthreads();
            {   // coalesced mixing + fp16 copy
                int r = tid >> 3, c8 = (tid & 7) * 8;
                float4 m0 = *(const float4*)&s[OFF_TRR + r * 68 + c8];
                float4 m1 = *(const float4*)&s[OFF_TRR + r * 68 + c8 + 4];
                size_t rowb = ((size_t)(b * TT + t)) * 4096 + (half*32 + r) * 64 + c8;
                *(float4*)&out[MIX_OFF + rowb] = m0;
                *(float4*)&out[MIX_OFF + rowb + 4] = m1;
                __half* mp = g_mx16 + rowb;
                *(__half2*)(mp + 0) = __floats2half2_rn(m0.x, m0.y);
                *(__half2*)(mp + 2) = __floats2half2_rn(m0.z, m0.w);
                *(__half2*)(mp + 4) = __floats2half2_rn(m1.x, m1.y);
                *(__half2*)(mp + 6) = __floats2half2_rn(m1.z, m1.w);
            }
            __syncthreads();
            if (tid == 0) { __threadfence(); atomicExch(&g_progress[bidx], t + 1); }

            // ---- Phase 5: h_next = tr @ hn (c=2tx local, j=4ty) ----
            float ah[8];
            #pragma unroll
            for (int i = 0; i < 8; i++) ah[i] = 0.f;
            #pragma unroll 4
            for (int d = 0; d < 64; d++) {
                float2 tv2 = *(const float2*)&s[OFF_TRT + d * 34 + 2 * tx];
                float4 hv4 = *(const float4*)&s[OFF_HNF + d * 68 + 4 * ty];
                float hv[4] = {hv4.x, hv4.y, hv4.z, hv4.w};
                #pragma unroll
                for (int ji = 0; ji < 4; ji++) {
                    ah[ji]   = fmaf(tv2.x, hv[ji], ah[ji]);
                    ah[4+ji] = fmaf(tv2.y, hv[ji], ah[4+ji]);
                }
            }
            #pragma unroll
            for (int ji = 0; ji < 4; ji++) {
                float2 w2; w2.x = ah[ji]; w2.y = ah[4 + ji];
                *(float2*)&s[OFF_HT + (4*ty + ji) * 34 + 2 * tx] = w2;
            }
            __syncthreads();

            if (tid < 32 && t >= 1) {
                float p = pb;
                #pragma unroll 8
                for (int h = 0; h < 64; h++)
                    p = fmaf(s[OFF_HT + h * 34 + tid], s[OFF_PW + h], p);
                float dd = p - s[OFF_XT + par * 32 + tid];
                errsum = fmaf(dd, dd, errsum);
            }
        }

        // DNC output (own rows)
        #pragma unroll
        for (int cc = 0; cc < 2; cc++) {
            float4 v;
            v.x = DNCr[cc*4+0] * (1.f / 256.f);
            v.y = DNCr[cc*4+1] * (1.f / 256.f);
            v.z = DNCr[cc*4+2] * (1.f / 256.f);
            v.w = DNCr[cc*4+3] * (1.f / 256.f);
            *(float4*)&out[DNC_OFF + (size_t)b * 4096 +
                           (size_t)(half*32 + 2*tx + cc) * 64 + 4 * ty] = v;
        }
        if (tid < 32) {
            #pragma unroll
            for (int o = 16; o > 0; o >>= 1)
                errsum += __shfl_xor_sync(0xffffffffu, errsum, o);
            if (tid == 0) g_rl[bidx] = errsum;
        }
        __syncthreads();   // fall through to worker role
    }

    // ------------------------------------------------------------------
    // Role 2: worker (all blocks)
    // ------------------------------------------------------------------
    int* stk = (int*)&s[W_TK];
    for (;;) {
        __syncthreads();
        if (tid == 0) stk[0] = atomicAdd(&g_ticket, 1);
        __syncthreads();
        int tk = stk[0];
        if (tk >= NTOT) break;

        if (tk < NPK) {
            if (tk < 16) {
                long base = (long)tk * 524288;
                const float2* src = (const float2*)(clf1_w + base);
                __half2* dst = (__half2*)(g_w1h + base);
                for (int i = tid; i < 262144; i += 256) {
                    float2 v = src[i];
                    dst[i] = __floats2half2_rn(v.x, v.y);
                }
                __threadfence();
                __syncthreads();
                if (tid == 0) atomicAdd(&g_pk1done, 1);
            } else {
                long base = (long)(tk - 16) * 262144;
                const float2* src = (const float2*)(clf2_w + base);
                __half2* dst = (__half2*)(g_w2h + base);
                for (int i = tid; i < 131072; i += 256) {
                    float2 v = src[i];
                    dst[i] = __floats2half2_rn(v.x, v.y);
                }
                __threadfence();
                __syncthreads();
                if (tid == 0) atomicAdd(&g_pk2done, 1);
            }
            continue;
        }

        int u = tk - NPK;
        int ly, tg, nb;
        if (u < 16) { ly = 1; tg = 0; nb = u; }
        else if (u < 16 + 63 * 24) {
            int v = u - 16, g = v / 24, r = v - g * 24;
            if (r < 8) { ly = 2; tg = g; nb = r; }
            else       { ly = 1; tg = g + 1; nb = r - 8; }
        } else { ly = 2; tg = 63; nb = u - (16 + 63 * 24); }

        if (ly == 1) {
            if (tid == 0) {
                volatile int* pk = &g_pk1done;
                while (*pk < 16) __nanosleep(128);
                int need = (tg + 1) * 4;
                for (int bi = 0; bi < 64; bi++) {
                    volatile int* p = &g_progress[bi];
                    while (*p < need) __nanosleep(128);
                }
                __threadfence();
            }
            __syncthreads();
            gemm16(s, g_mx16, g_w1h, clf1_b, 4096, tg, nb, 1, nullptr, 0);
            __threadfence();
            __syncthreads();
            if (tid == 0) atomicAdd(&g_rbdone[tg], 1);
        } else {
            if (tid == 0) {
                volatile int* pk = &g_pk2done;
                while (*pk < 8) __nanosleep(128);
                volatile int* rd = &g_rbdone[tg];
                while (*rd < 16) __nanosleep(128);
                __threadfence();
            }
            __syncthreads();
            gemm16(s, g_h1h, g_w2h, clf2_b, 2048, tg, nb, 2, clf3_w, tg * 8 + nb);
        }
    }
}

// ============================================================================
__global__ void finalize_kernel(const float* __restrict__ b3, float* __restrict__ out)
{
    int tid = threadIdx.x;
    if (tid < 64) {
        int b = tid >> 1, o = tid & 1;
        float sv = 0.f;
        for (int t2 = 0; t2 < 512; t2++)
            sv += g_lg[t2 * 64 + b * 2 + o];
        out[(size_t)b * 2 + o] = sv * (1.f / 256.f) + b3[o];
    }
    if (tid == 64) {
        float ss = 0.f;
        #pragma unroll
        for (int i = 0; i < 64; i++) ss += g_rl[i];
        out[RL_OFF] = ss / (32.f * 255.f * 64.f);
    }
}

// ============================================================================
extern "C" void kernel_launch(void* const* d_in, const int* in_sizes, int n_in,
                              void* d_out, int out_size)
{
    const float* x      = (const float*)d_in[0];
    const float* emb_w  = (const float*)d_in[1];
    const float* emb_b  = (const float*)d_in[2];
    const float* w_ih   = (const float*)d_in[3];
    const float* w_hh   = (const float*)d_in[4];
    const float* b_ih   = (const float*)d_in[5];
    const float* b_hh   = (const float*)d_in[6];
    const float* q_w    = (const float*)d_in[7];
    const float* q_b    = (const float*)d_in[8];
    const float* k_w    = (const float*)d_in[9];
    const float* k_b    = (const float*)d_in[10];
    const float* gate_b = (const float*)d_in[11];
    const float* pred_w = (const float*)d_in[12];
    const float* pred_b = (const float*)d_in[13];
    const float* clf1_w = (const float*)d_in[14];
    const float* clf1_b = (const float*)d_in[15];
    const float* clf2_w = (const float*)d_in[16];
    const float* clf2_b = (const float*)d_in[17];
    const float* clf3_w = (const float*)d_in[18];
    const float* clf3_b = (const float*)d_in[19];
    float* out = (float*)d_out;

    cudaFuncSetAttribute(mega_kernel,
                         cudaFuncAttributeMaxDynamicSharedMemorySize, SMEM_BYTES);

    init_kernel<<<1, 128>>>();
    mega_kernel<<<NSM, 256, SMEM_BYTES>>>(
        x, emb_w, emb_b, w_ih, w_hh, b_ih, b_hh,
        q_w, q_b, k_w, k_b, gate_b, pred_w, pred_b,
        clf1_w, clf1_b, clf2_w, clf2_b, clf3_w, out);
    finalize_kernel<<<1, 128>>>(clf3_b, out);
}

// round 14
// speedup vs baseline: 2.5733x; 1.0421x over previous
#include <cuda_runtime.h>
#include <cuda_fp16.h>
#include <math.h>
#include <stdint.h>

// Problem dims
#define BB 32
#define TT 256
#define CC 64
#define HH 64
#define NSM 148

// Output layout (floats)
#define LOGITS_OFF 0
#define DNC_OFF    64
#define MIX_OFF    131136ull              // 64 + 32*4096
#define RL_OFF     33685568ull            // MIX_OFF + 32*256*4096

// ---------------- static device scratch (no runtime allocs) ----------------
__device__ __half g_mx16[8192ull * 4096]; // fp16 mixing copy [b*256+t][4096]
__device__ __half g_w1h[2048ull * 4096];  // clf1_w fp16
__device__ __half g_w2h[1024ull * 2048];  // clf2_w fp16
__device__ __half g_h1h[8192ull * 2048];  // h1 fp16
__device__ float g_lg[512 * 64];          // layer2 fused-clf3 partials
__device__ float g_rl[64];
__device__ int   g_ticket;
__device__ int   g_progress[64];          // per half-CTA, value = t+1
__device__ int   g_rbdone[64];
__device__ int   g_pk1done;
__device__ int   g_pk2done;

// ============================================================================
// Base-ISA PTX helpers (sm_80+/sm_90 base — no 'a' features)
// ============================================================================
__device__ __forceinline__ uint32_t smem_u32(const void* p) {
    uint32_t a;
    asm("{ .reg .u64 t; cvta.to.shared.u64 t, %1; cvt.u32.u64 %0, t; }" : "=r"(a) : "l"(p));
    return a;
}
#define CP16(dst, src) \
    asm volatile("cp.async.cg.shared.global [%0], [%1], 16;" :: "r"(dst), "l"(src))
#define CP_COMMIT() asm volatile("cp.async.commit_group;" ::: "memory")
#define CP_WAIT1()  asm volatile("cp.async.wait_group 1;" ::: "memory")
#define CP_WAIT0()  asm volatile("cp.async.wait_group 0;" ::: "memory")
#define LDSM4(R, addr) \
    asm volatile("ldmatrix.sync.aligned.m8n8.x4.shared.b16 {%0,%1,%2,%3}, [%4];" \
        : "=r"((R)[0]), "=r"((R)[1]), "=r"((R)[2]), "=r"((R)[3]) : "r"(addr))
#define LDSM2(R, addr) \
    asm volatile("ldmatrix.sync.aligned.m8n8.x2.shared.b16 {%0,%1}, [%2];" \
        : "=r"((R)[0]), "=r"((R)[1]) : "r"(addr))
#define MMAH(D, A, Bf) \
    asm volatile("mma.sync.aligned.m16n8k16.row.col.f32.f16.f16.f32 " \
        "{%0,%1,%2,%3}, {%4,%5,%6,%7}, {%8,%9}, {%0,%1,%2,%3};" \
        : "+f"((D)[0]), "+f"((D)[1]), "+f"((D)[2]), "+f"((D)[3]) \
        : "r"((A)[0]), "r"((A)[1]), "r"((A)[2]), "r"((A)[3]), "r"((Bf)[0]), "r"((Bf)[1]))

// cluster primitives (sm_90 base ISA)
#define CARRIVE() asm volatile("barrier.cluster.arrive.aligned;" ::: "memory")
#define CWAIT()   asm volatile("barrier.cluster.wait.aligned;" ::: "memory")
__device__ __forceinline__ uint32_t mapa_peer(uint32_t laddr, uint32_t rank) {
    uint32_t r;
    asm("mapa.shared::cluster.u32 %0, %1, %2;" : "=r"(r) : "r"(laddr), "r"(rank));
    return r;
}
#define STC64(addr, v) \
    asm volatile("st.shared::cluster.b64 [%0], %1;" :: "r"(addr), "l"(v) : "memory")
#define STC32(addr, v) \
    asm volatile("st.shared::cluster.b32 [%0], %1;" :: "r"(addr), "r"(v) : "memory")
__device__ __forceinline__ unsigned long long packf2(float a, float b) {
    return ((unsigned long long)__float_as_uint(b) << 32) | __float_as_uint(a);
}

// ---------------- shared mem layout (floats) --------------------------------
#define OFF_WHHT 0          /* [64][192] */
#define OFF_QWT  12288      /* [64][64]  */
#define OFF_KWT  16384      /* [64][64]  */
#define OFF_HT   20480      /* [64 j][34 c-own]  h transposed */
#define OFF_HNT  22656      /* [64 h][34 c-own]  hn transposed */
#define OFF_QROW 24832      /* [32 c][68 a] */
#define OFF_KROW 27008      /* [64 d][68 a]  full (own local + peer DSMEM) */
#define OFF_HNF  31360      /* [64 d][68 j]  full hn */
#define OFF_TRR  37888      /* [32 c][68 d]  gated transfer rows */
#define OFF_XT   40064      /* [2][32] */
#define OFF_A    40128      /* [192] */
#define OFF_B0   40320
#define OFF_BHH  40512
#define OFF_QB   40704
#define OFF_KB   40768
#define OFF_PW   40832
#define OFF_RED  40896      /* [16]; [9] = peer ssq slot */
#define SMEM_FLOATS 40960
#define SMEM_BYTES  (SMEM_FLOATS * 4)

// worker smem carve: bytes [0,32768) A/B bufs; floats: sred s[8192..), tk s[8500]
#define W_SRED 8192
#define W_TK   8500

#define NPK  24
#define NQ   1536
#define NTOT (NPK + NQ)

__device__ __forceinline__ float sigf(float x) { return 1.f / (1.f + __expf(-x)); }
__device__ __forceinline__ float tanh_fast(float x) {
    float e = __expf(2.f * x);
    return __fdividef(e - 1.f, e + 1.f);
}
__device__ __forceinline__ int arow_map(int tg, int r) {
    return (r >> 2) * 256 + tg * 4 + (r & 3);
}

// ============================================================================
__global__ void init_kernel() {
    int tid = threadIdx.x;
    if (tid == 0) { g_ticket = 0; g_pk1done = 0; g_pk2done = 0; }
    if (tid < 64) {
        g_progress[tid] = 0;
        g_rbdone[tid] = 0;
    }
}

// ============================================================================
// fp16 mma.sync GEMM tile (proven R9/R11/R12)
// ============================================================================
__device__ void gemm16(float* s, const __half* __restrict__ Ah,
                       const __half* __restrict__ Bh,
                       const float* __restrict__ bias, int K,
                       int tg, int nb, int layer,
                       const float* __restrict__ w3, int t2)
{
    const int tid = threadIdx.x, lane = tid & 31, wid = tid >> 5;
    const int wm = wid & 1, wn = wid >> 1;
    const int n_blk = nb * 128;
    const uint32_t sAb = smem_u32(s);
    const uint32_t sBb = sAb + 16384;

    const int lr = tid >> 1, lc = (tid & 1) * 2;
    const uint32_t swl = (lr >> 1) & 3;
    const uint32_t dA0 = sAb + lr * 64 + (((uint32_t)lc ^ swl) << 4);
    const uint32_t dA1 = sAb + lr * 64 + (((uint32_t)(lc + 1) ^ swl) << 4);
    const uint32_t dB0 = sBb + lr * 64 + (((uint32_t)lc ^ swl) << 4);
    const uint32_t dB1 = sBb + lr * 64 + (((uint32_t)(lc + 1) ^ swl) << 4);
    const long gA0 = (long)arow_map(tg, lr) * K + lc * 8;
    const long gB0 = (long)(n_blk + lr) * K + lc * 8;

    int rowA[4], swA[4], rowB[4], swB[4];
    const int halfA = (lane >> 4) & 1, halfB = (lane >> 3) & 1;
    #pragma unroll
    for (int mi = 0; mi < 4; mi++) {
        rowA[mi] = wm * 64 + mi * 16 + (lane & 15);
        swA[mi] = (rowA[mi] >> 1) & 3;
    }
    #pragma unroll
    for (int ni = 0; ni < 4; ni++) {
        rowB[ni] = wn * 32 + ni * 8 + (lane & 7);
        swB[ni] = (rowB[ni] >> 1) & 3;
    }

    float acc[4][4][4];
    #pragma unroll
    for (int mi = 0; mi < 4; mi++)
        #pragma unroll
        for (int ni = 0; ni < 4; ni++)
            #pragma unroll
            for (int r = 0; r < 4; r++) acc[mi][ni][r] = 0.f;

    const int iters = K / 32;
    {
        CP16(dA0, Ah + gA0);
        CP16(dA1, Ah + gA0 + 8);
        CP16(dB0, Bh + gB0);
        CP16(dB1, Bh + gB0 + 8);
        CP_COMMIT();
    }
    for (int it = 0; it < iters; ++it) {
        if (it + 1 < iters) {
            uint32_t bo = (uint32_t)((it + 1) & 1) * 8192;
            long ko = (long)(it + 1) * 32;
            CP16(dA0 + bo, Ah + gA0 + ko);
            CP16(dA1 + bo, Ah + gA0 + ko + 8);
            CP16(dB0 + bo, Bh + gB0 + ko);
            CP16(dB1 + bo, Bh + gB0 + ko + 8);
            CP_COMMIT();
            CP_WAIT1();
        } else {
            CP_WAIT0();
        }
        __syncthreads();

        uint32_t bo = (uint32_t)(it & 1) * 8192;
        #pragma unroll
        for (int ks = 0; ks < 2; ks++) {
            uint32_t a[4][4], bfr[4][2];
            #pragma unroll
            for (int mi = 0; mi < 4; mi++)
                LDSM4(a[mi], sAb + bo + rowA[mi] * 64 +
                             (((uint32_t)(2 * ks + halfA) ^ (uint32_t)swA[mi]) << 4));
            #pragma unroll
            for (int ni = 0; ni < 4; ni++)
                LDSM2(bfr[ni], sBb + bo + rowB[ni] * 64 +
                               (((uint32_t)(2 * ks + halfB) ^ (uint32_t)swB[ni]) << 4));
            #pragma unroll
            for (int mi = 0; mi < 4; mi++)
                #pragma unroll
                for (int ni = 0; ni < 4; ni++)
                    MMAH(acc[mi][ni], a[mi], bfr[ni]);
        }
        __syncthreads();
    }

    if (layer == 1) {
        #pragma unroll
        for (int mi = 0; mi < 4; mi++) {
            #pragma unroll
            for (int ni = 0; ni < 4; ni++) {
                int n0 = n_blk + wn * 32 + ni * 8 + (lane & 3) * 2;
                float bs0 = bias[n0], bs1 = bias[n0 + 1];
                #pragma unroll
                for (int h = 0; h < 2; h++) {
                    int ml = wm * 64 + mi * 16 + (lane >> 2) + h * 8;
                    int row = arow_map(tg, ml);
                    float v0 = fmaxf(acc[mi][ni][h * 2 + 0] + bs0, 0.f);
                    float v1 = fmaxf(acc[mi][ni][h * 2 + 1] + bs1, 0.f);
                    *(__half2*)(g_h1h + (long)row * 2048 + n0) =
                        __floats2half2_rn(v0, v1);
                }
            }
        }
    } else {
        float pa[4][2][2];
        #pragma unroll
        for (int mi = 0; mi < 4; mi++)
            #pragma unroll
            for (int h = 0; h < 2; h++) { pa[mi][h][0] = 0.f; pa[mi][h][1] = 0.f; }
        #pragma unroll
        for (int ni = 0; ni < 4; ni++) {
            int n0 = n_blk + wn * 32 + ni * 8 + (lane & 3) * 2;
            float bs0 = bias[n0], bs1 = bias[n0 + 1];
            float wa0 = w3[n0], wa1 = w3[n0 + 1];
            float wb0 = w3[1024 + n0], wb1 = w3[1024 + n0 + 1];
            #pragma unroll
            for (int mi = 0; mi < 4; mi++) {
                #pragma unroll
                for (int h = 0; h < 2; h++) {
                    float v0 = fmaxf(acc[mi][ni][h * 2 + 0] + bs0, 0.f);
                    float v1 = fmaxf(acc[mi][ni][h * 2 + 1] + bs1, 0.f);
                    pa[mi][h][0] = fmaf(v0, wa0, fmaf(v1, wa1, pa[mi][h][0]));
                    pa[mi][h][1] = fmaf(v0, wb0, fmaf(v1, wb1, pa[mi][h][1]));
                }
            }
        }
        #pragma unroll
        for (int mi = 0; mi < 4; mi++)
            #pragma unroll
            for (int h = 0; h < 2; h++)
                #pragma unroll
                for (int o = 0; o < 2; o++) {
                    float v = pa[mi][h][o];
                    #pragma unroll
                    for (int msk = 8; msk > 0; msk >>= 1)
                        v += __shfl_xor_sync(0xffffffffu, v, msk);
                    pa[mi][h][o] = v;
                }
        float* sred = s + W_SRED;
        if ((lane & 15) == 0) {
            #pragma unroll
            for (int mi = 0; mi < 4; mi++)
                #pragma unroll
                for (int h = 0; h < 2; h++) {
                    int bat = wm * 16 + mi * 4 + 2 * h + (lane >> 4);
                    sred[(wn * 32 + bat) * 2 + 0] = pa[mi][h][0];
                    sred[(wn * 32 + bat) * 2 + 1] = pa[mi][h][1];
                }
        }
        __syncthreads();
        if (tid < 64) {
            int b = tid >> 1, o = tid & 1;
            float sv = sred[(0 * 32 + b) * 2 + o] + sred[(1 * 32 + b) * 2 + o]
                     + sred[(2 * 32 + b) * 2 + o] + sred[(3 * 32 + b) * 2 + o];
            g_lg[t2 * 64 + b * 2 + o] = sv;
        }
        __syncthreads();
    }
}

// ============================================================================
// Mega kernel: blocks 0..63 = cluster-paired split recurrence, then workers
// ============================================================================
__global__ __launch_bounds__(256) void mega_kernel(
    const float* __restrict__ x,
    const float* __restrict__ emb_w, const float* __restrict__ emb_b,
    const float* __restrict__ w_ih, const float* __restrict__ w_hh,
    const float* __restrict__ b_ih, const float* __restrict__ b_hh,
    const float* __restrict__ q_w, const float* __restrict__ q_b,
    const float* __restrict__ k_w, const float* __restrict__ k_b,
    const float* __restrict__ gate_b,
    const float* __restrict__ pred_w, const float* __restrict__ pred_b,
    const float* __restrict__ clf1_w, const float* __restrict__ clf1_b,
    const float* __restrict__ clf2_w, const float* __restrict__ clf2_b,
    const float* __restrict__ clf3_w,
    float* __restrict__ out)
{
    extern __shared__ float s[];
    const int tid = threadIdx.x;
    const int bidx = blockIdx.x;

    if (bidx < 64) {
        const int b = bidx >> 1, half = bidx & 1;
        const int ph = half ^ 1;
        const uint32_t prank = (uint32_t)ph;        // peer's cluster rank
        const int tx = tid & 15, ty = tid >> 4;
        const int j0 = 4 * tx;
        const uint32_t sbase = smem_u32(s);

        // ---- weight loads ----
        for (int i = tid; i < 12288; i += 256) {
            int j = i / 64, h = i % 64;
            s[OFF_WHHT + h * 192 + j] = w_hh[i];
        }
        for (int i = tid; i < 4096; i += 256) {
            int j = i / 64, h = i % 64;
            s[OFF_QWT + h * 64 + j] = q_w[i];
            s[OFF_KWT + h * 64 + j] = k_w[i];
        }
        if (tid < 192) {
            float a = 0.f, b0v = 0.f;
            #pragma unroll
            for (int e = 0; e < 32; e++) {
                float w = w_ih[tid * 32 + e];
                a += w * emb_w[e];
                b0v += w * emb_b[e];
            }
            s[OFF_A + tid] = a;
            s[OFF_B0 + tid] = b0v + b_ih[tid];
            s[OFF_BHH + tid] = b_hh[tid];
        }
        if (tid < 64) {
            s[OFF_QB + tid] = q_b[tid];
            s[OFF_KB + tid] = k_b[tid];
            s[OFF_PW + tid] = pred_w[tid];
        }
        if (tid < 32)
            s[OFF_XT + tid] = x[(size_t)b * TT * CC + half * 32 + tid];
        for (int i = tid; i < 64 * 34; i += 256) s[OFF_HT + i] = 0.f;
        const float pb = pred_b[0];
        float errsum = 0.f;
        __syncthreads();

        // register caches
        float Ar[4], Az[4], An[4], B0r[4], B0z[4], B0n[4];
        float Br[4], Bz[4], Bn[4], QBv[4], KBv[4];
        #pragma unroll
        for (int ji = 0; ji < 4; ji++) {
            int j = j0 + ji;
            Ar[ji] = s[OFF_A + j];  Az[ji] = s[OFF_A + 64 + j];  An[ji] = s[OFF_A + 128 + j];
            B0r[ji] = s[OFF_B0 + j]; B0z[ji] = s[OFF_B0 + 64 + j]; B0n[ji] = s[OFF_B0 + 128 + j];
            Br[ji] = s[OFF_BHH + j]; Bz[ji] = s[OFF_BHH + 64 + j]; Bn[ji] = s[OFF_BHH + 128 + j];
            QBv[ji] = s[OFF_QB + j]; KBv[ji] = s[OFF_KB + j];
        }
        // phase4 tile: c = 2tx+cc (own-local), d = (half-sel)*32 + 2ty+dd
        // index = hd*4 + cc*2 + dd ; hd=0 -> own half d, hd=1 -> peer half d
        float GT[8], DNCr[8];
        #pragma unroll
        for (int hd = 0; hd < 2; hd++) {
            int dsel = hd ? ph : half;
            #pragma unroll
            for (int cc = 0; cc < 2; cc++)
                #pragma unroll
                for (int dd = 0; dd < 2; dd++) {
                    GT[hd*4 + cc*2 + dd] =
                        gate_b[(half*32 + 2*tx + cc) * 64 + dsel*32 + 2*ty + dd];
                    DNCr[hd*4 + cc*2 + dd] = 0.f;
                }
        }

        // DSMEM peer addresses (constant per thread)
        uint32_t pHNF[2], pKROW[2];
        #pragma unroll
        for (int cc = 0; cc < 2; cc++) {
            pHNF[cc]  = mapa_peer(sbase + (uint32_t)(OFF_HNF  + (half*32 + 2*ty + cc) * 68 + j0) * 4, prank);
            pKROW[cc] = mapa_peer(sbase + (uint32_t)(OFF_KROW + (half*32 + 2*ty + cc) * 68 + j0) * 4, prank);
        }
        const uint32_t pSSQ = mapa_peer(sbase + (uint32_t)(OFF_RED + 9) * 4, prank);

        CARRIVE();   // prime barrier generation for first wait (#a)

        for (int t = 0; t < TT; t++) {
            const int par = t & 1;
            // ---- Phase 1: gh = h @ w_hh^T (c=2ty, j=4tx) [local only] ----
            float ar[8], az[8], an_[8];
            #pragma unroll
            for (int ji = 0; ji < 4; ji++) {
                ar[ji] = Br[ji];  ar[4 + ji] = Br[ji];
                az[ji] = Bz[ji];  az[4 + ji] = Bz[ji];
                an_[ji] = Bn[ji]; an_[4 + ji] = Bn[ji];
            }
            #pragma unroll 4
            for (int h = 0; h < 64; h++) {
                float2 hv2 = *(const float2*)&s[OFF_HT + h * 34 + 2 * ty];
                float4 wr4 = *(const float4*)&s[OFF_WHHT + h * 192 + j0];
                float4 wz4 = *(const float4*)&s[OFF_WHHT + h * 192 + 64 + j0];
                float4 wn4 = *(const float4*)&s[OFF_WHHT + h * 192 + 128 + j0];
                float wr[4] = {wr4.x, wr4.y, wr4.z, wr4.w};
                float wz[4] = {wz4.x, wz4.y, wz4.z, wz4.w};
                float wn[4] = {wn4.x, wn4.y, wn4.z, wn4.w};
                #pragma unroll
                for (int ji = 0; ji < 4; ji++) {
                    ar[ji]  = fmaf(hv2.x, wr[ji], ar[ji]);
                    az[ji]  = fmaf(hv2.x, wz[ji], az[ji]);
                    an_[ji] = fmaf(hv2.x, wn[ji], an_[ji]);
                    ar[4+ji]  = fmaf(hv2.y, wr[ji], ar[4+ji]);
                    az[4+ji]  = fmaf(hv2.y, wz[ji], az[4+ji]);
                    an_[4+ji] = fmaf(hv2.y, wn[ji], an_[4+ji]);
                }
            }

            CWAIT();   // #a: peer finished phase5 reads of last step -> safe to overwrite his HNF/KROW

            // ---- Phase 2: gates -> hn; publish own half to local + peer HNF ----
            float hnreg[8];
            float xv0 = s[OFF_XT + par * 32 + 2 * ty];
            float xv1 = s[OFF_XT + par * 32 + 2 * ty + 1];
            #pragma unroll
            for (int ji = 0; ji < 4; ji++) {
                float2 ho = *(const float2*)&s[OFF_HT + (j0 + ji) * 34 + 2 * ty];
                {
                    float gir = fmaf(xv0, Ar[ji], B0r[ji]);
                    float giz = fmaf(xv0, Az[ji], B0z[ji]);
                    float gin = fmaf(xv0, An[ji], B0n[ji]);
                    float r = sigf(gir + ar[ji]);
                    float z = sigf(giz + az[ji]);
                    float n = tanh_fast(fmaf(r, an_[ji], gin));
                    hnreg[ji] = (1.f - z) * n + z * ho.x;
                }
                {
                    float gir = fmaf(xv1, Ar[ji], B0r[ji]);
                    float giz = fmaf(xv1, Az[ji], B0z[ji]);
                    float gin = fmaf(xv1, An[ji], B0n[ji]);
                    float r = sigf(gir + ar[4+ji]);
                    float z = sigf(giz + az[4+ji]);
                    float n = tanh_fast(fmaf(r, an_[4+ji], gin));
                    hnreg[4 + ji] = (1.f - z) * n + z * ho.y;
                }
                float2 w2; w2.x = hnreg[ji]; w2.y = hnreg[4 + ji];
                *(float2*)&s[OFF_HNT + (j0 + ji) * 34 + 2 * ty] = w2;
            }
            #pragma unroll
            for (int cc = 0; cc < 2; cc++) {
                float4 v; v.x = hnreg[cc*4+0]; v.y = hnreg[cc*4+1];
                v.z = hnreg[cc*4+2]; v.w = hnreg[cc*4+3];
                *(float4*)&s[OFF_HNF + (half*32 + 2*ty + cc) * 68 + j0] = v;
                STC64(pHNF[cc],     packf2(v.x, v.y));
                STC64(pHNF[cc] + 8, packf2(v.z, v.w));
            }
            __syncthreads();

            // ---- Phase 3: q/k (c=2ty, a=4tx); publish own k half ----
            float aq[8], ak[8];
            #pragma unroll
            for (int ji = 0; ji < 4; ji++) {
                aq[ji] = QBv[ji]; aq[4+ji] = QBv[ji];
                ak[ji] = KBv[ji]; ak[4+ji] = KBv[ji];
            }
            #pragma unroll 4
            for (int h = 0; h < 64; h++) {
                float2 hv2 = *(const float2*)&s[OFF_HNT + h * 34 + 2 * ty];
                float4 qw4 = *(const float4*)&s[OFF_QWT + h * 64 + j0];
                float4 kw4 = *(const float4*)&s[OFF_KWT + h * 64 + j0];
                float qw[4] = {qw4.x, qw4.y, qw4.z, qw4.w};
                float kw[4] = {kw4.x, kw4.y, kw4.z, kw4.w};
                #pragma unroll
                for (int ji = 0; ji < 4; ji++) {
                    aq[ji]   = fmaf(hv2.x, qw[ji], aq[ji]);
                    ak[ji]   = fmaf(hv2.x, kw[ji], ak[ji]);
                    aq[4+ji] = fmaf(hv2.y, qw[ji], aq[4+ji]);
                    ak[4+ji] = fmaf(hv2.y, kw[ji], ak[4+ji]);
                }
            }
            #pragma unroll
            for (int cc = 0; cc < 2; cc++) {
                float4 qv; qv.x = aq[cc*4+0]; qv.y = aq[cc*4+1];
                qv.z = aq[cc*4+2]; qv.w = aq[cc*4+3];
                float4 kv; kv.x = ak[cc*4+0]; kv.y = ak[cc*4+1];
                kv.z = ak[cc*4+2]; kv.w = ak[cc*4+3];
                *(float4*)&s[OFF_QROW + (2*ty + cc) * 68 + j0] = qv;
                *(float4*)&s[OFF_KROW + (half*32 + 2*ty + cc) * 68 + j0] = kv;
                STC64(pKROW[cc],     packf2(kv.x, kv.y));
                STC64(pKROW[cc] + 8, packf2(kv.z, kv.w));
            }
            __syncthreads();
            CARRIVE();   // #b: own pubs complete (release)

            // ---- Phase 4a: tr own-d half (local data only) ----
            float tr[8];
            #pragma unroll
            for (int i = 0; i < 8; i++) tr[i] = 0.f;
            {
                int drow = half * 32 + 2 * ty;
                #pragma unroll 2
                for (int a4 = 0; a4 < 64; a4 += 4) {
                    float4 q0 = *(const float4*)&s[OFF_QROW + (2*tx) * 68 + a4];
                    float4 q1 = *(const float4*)&s[OFF_QROW + (2*tx + 1) * 68 + a4];
                    float4 k0 = *(const float4*)&s[OFF_KROW + drow * 68 + a4];
                    float4 k1 = *(const float4*)&s[OFF_KROW + (drow + 1) * 68 + a4];
                    const float* qa0 = &q0.x; const float* qa1 = &q1.x;
                    const float* ka0 = &k0.x; const float* ka1 = &k1.x;
                    #pragma unroll
                    for (int ai = 0; ai < 4; ai++) {
                        tr[0] = fmaf(qa0[ai], ka0[ai], tr[0]);
                        tr[1] = fmaf(qa0[ai], ka1[ai], tr[1]);
                        tr[2] = fmaf(qa1[ai], ka0[ai], tr[2]);
                        tr[3] = fmaf(qa1[ai], ka1[ai], tr[3]);
                    }
                }
            }
            CWAIT();     // #b: peer's k/hn DSMEM writes now visible (acquire)

            // ---- Phase 4b: tr peer-d half ----
            {
                int drow = ph * 32 + 2 * ty;
                #pragma unroll 2
                for (int a4 = 0; a4 < 64; a4 += 4) {
                    float4 q0 = *(const float4*)&s[OFF_QROW + (2*tx) * 68 + a4];
                    float4 q1 = *(const float4*)&s[OFF_QROW + (2*tx + 1) * 68 + a4];
                    float4 k0 = *(const float4*)&s[OFF_KROW + drow * 68 + a4];
                    float4 k1 = *(const float4*)&s[OFF_KROW + (drow + 1) * 68 + a4];
                    const float* qa0 = &q0.x; const float* qa1 = &q1.x;
                    const float* ka0 = &k0.x; const float* ka1 = &k1.x;
                    #pragma unroll
                    for (int ai = 0; ai < 4; ai++) {
                        tr[4] = fmaf(qa0[ai], ka0[ai], tr[4]);
                        tr[5] = fmaf(qa0[ai], ka1[ai], tr[5]);
                        tr[6] = fmaf(qa1[ai], ka0[ai], tr[6]);
                        tr[7] = fmaf(qa1[ai], ka1[ai], tr[7]);
                    }
                }
            }

            // ---- Frobenius norm: own-c partial, exchange scalar via DSMEM ----
            float ssq = 0.f;
            #pragma unroll
            for (int i = 0; i < 8; i++) ssq = fmaf(tr[i], tr[i], ssq);
            #pragma unroll
            for (int o = 16; o > 0; o >>= 1) ssq += __shfl_xor_sync(0xffffffffu, ssq, o);
            if ((tid & 31) == 0) s[OFF_RED + (tid >> 5)] = ssq;
            __syncthreads();
            float ownTot = 0.f;
            #pragma unroll
            for (int w = 0; w < 8; w++) ownTot += s[OFF_RED + w];
            if (tid == 0) STC32(pSSQ, __float_as_uint(ownTot));
            CARRIVE();   // #c
            CWAIT();
            float rn = rsqrtf(ownTot + s[OFF_RED + 9]);

            // ---- gates -> gated transfer rows (TRR full-d) ----
            float tt[8];
            #pragma unroll
            for (int hd = 0; hd < 2; hd++) {
                int dsel = hd ? ph : half;
                #pragma unroll
                for (int cc = 0; cc < 2; cc++) {
                    #pragma unroll
                    for (int dd = 0; dd < 2; dd++) {
                        int i = hd*4 + cc*2 + dd;
                        float tv = tanh_fast(tr[i] * rn);
                        float g = sigf(fabsf(tv) + GT[i]);
                        tv *= g;
                        tt[i] = tv;
                        DNCr[i] += tv;
                    }
                    float2 w2; w2.x = tt[hd*4 + cc*2]; w2.y = tt[hd*4 + cc*2 + 1];
                    *(float2*)&s[OFF_TRR + (2*tx + cc) * 68 + dsel*32 + 2*ty] = w2;
                }
            }
            if (tid < 32 && t + 1 < TT)
                s[OFF_XT + ((t + 1) & 1) * 32 + tid] =
                    x[((size_t)b * TT + t + 1) * CC + half * 32 + tid];
            __syncthreads();

            {   // coalesced mixing + fp16 copy (bounce via TRR)
                int r = tid >> 3, c8 = (tid & 7) * 8;
                float4 m0 = *(const float4*)&s[OFF_TRR + r * 68 + c8];
                float4 m1 = *(const float4*)&s[OFF_TRR + r * 68 + c8 + 4];
                size_t rowb = ((size_t)(b * TT + t)) * 4096 + (half*32 + r) * 64 + c8;
                *(float4*)&out[MIX_OFF + rowb] = m0;
                *(float4*)&out[MIX_OFF + rowb + 4] = m1;
                __half* mp = g_mx16 + rowb;
                *(__half2*)(mp + 0) = __floats2half2_rn(m0.x, m0.y);
                *(__half2*)(mp + 2) = __floats2half2_rn(m0.z, m0.w);
                *(__half2*)(mp + 4) = __floats2half2_rn(m1.x, m1.y);
                *(__half2*)(mp + 6) = __floats2half2_rn(m1.z, m1.w);
            }
            __syncthreads();
            if (tid == 0) { __threadfence(); atomicExch(&g_progress[bidx], t + 1); }

            // ---- Phase 5: h_next = tr @ hn (c=2tx+cc, j=4ty) ----
            float ah[8];
            #pragma unroll
            for (int i = 0; i < 8; i++) ah[i] = 0.f;
            #pragma unroll 2
            for (int d4 = 0; d4 < 64; d4 += 4) {
                float4 t0 = *(const float4*)&s[OFF_TRR + (2*tx) * 68 + d4];
                float4 t1 = *(const float4*)&s[OFF_TRR + (2*tx + 1) * 68 + d4];
                const float* ta = &t0.x; const float* tb = &t1.x;
                #pragma unroll
                for (int i = 0; i < 4; i++) {
                    float4 hv4 = *(const float4*)&s[OFF_HNF + (d4 + i) * 68 + 4 * ty];
                    const float* hv = &hv4.x;
                    #pragma unroll
                    for (int ji = 0; ji < 4; ji++) {
                        ah[ji]   = fmaf(ta[i], hv[ji], ah[ji]);
                        ah[4+ji] = fmaf(tb[i], hv[ji], ah[4+ji]);
                    }
                }
            }
            #pragma unroll
            for (int ji = 0; ji < 4; ji++) {
                float2 w2; w2.x = ah[ji]; w2.y = ah[4 + ji];
                *(float2*)&s[OFF_HT + (4*ty + ji) * 34 + 2 * tx] = w2;
            }
            CARRIVE();   // #a for next step (peer may overwrite our HNF/KROW after this)
            __syncthreads();

            if (tid < 32 && t >= 1) {
                float p = pb;
                #pragma unroll 8
                for (int h = 0; h < 64; h++)
                    p = fmaf(s[OFF_HT + h * 34 + tid], s[OFF_PW + h], p);
                float dd = p - s[OFF_XT + par * 32 + tid];
                errsum = fmaf(dd, dd, errsum);
            }
        }
        CWAIT();   // retire final generation

        // DNC output (own c rows, both d halves)
        #pragma unroll
        for (int hd = 0; hd < 2; hd++) {
            int dsel = hd ? ph : half;
            #pragma unroll
            for (int cc = 0; cc < 2; cc++) {
                float2 v;
                v.x = DNCr[hd*4 + cc*2 + 0] * (1.f / 256.f);
                v.y = DNCr[hd*4 + cc*2 + 1] * (1.f / 256.f);
                *(float2*)&out[DNC_OFF + (size_t)b * 4096 +
                               (size_t)(half*32 + 2*tx + cc) * 64 + dsel*32 + 2*ty] = v;
            }
        }
        if (tid < 32) {
            #pragma unroll
            for (int o = 16; o > 0; o >>= 1)
                errsum += __shfl_xor_sync(0xffffffffu, errsum, o);
            if (tid == 0) g_rl[bidx] = errsum;
        }
        __syncthreads();   // fall through to worker role
    }

    // ------------------------------------------------------------------
    // Role 2: worker (all blocks)
    // ------------------------------------------------------------------
    int* stk = (int*)&s[W_TK];
    for (;;) {
        __syncthreads();
        if (tid == 0) stk[0] = atomicAdd(&g_ticket, 1);
        __syncthreads();
        int tk = stk[0];
        if (tk >= NTOT) break;

        if (tk < NPK) {
            if (tk < 16) {
                long base = (long)tk * 524288;
                const float2* src = (const float2*)(clf1_w + base);
                __half2* dst = (__half2*)(g_w1h + base);
                for (int i = tid; i < 262144; i += 256) {
                    float2 v = src[i];
                    dst[i] = __floats2half2_rn(v.x, v.y);
                }
                __threadfence();
                __syncthreads();
                if (tid == 0) atomicAdd(&g_pk1done, 1);
            } else {
                long base = (long)(tk - 16) * 262144;
                const float2* src = (const float2*)(clf2_w + base);
                __half2* dst = (__half2*)(g_w2h + base);
                for (int i = tid; i < 131072; i += 256) {
                    float2 v = src[i];
                    dst[i] = __floats2half2_rn(v.x, v.y);
                }
                __threadfence();
                __syncthreads();
                if (tid == 0) atomicAdd(&g_pk2done, 1);
            }
            continue;
        }

        int u = tk - NPK;
        int ly, tg, nb;
        if (u < 16) { ly = 1; tg = 0; nb = u; }
        else if (u < 16 + 63 * 24) {
            int v = u - 16, g = v / 24, r = v - g * 24;
            if (r < 8) { ly = 2; tg = g; nb = r; }
            else       { ly = 1; tg = g + 1; nb = r - 8; }
        } else { ly = 2; tg = 63; nb = u - (16 + 63 * 24); }

        if (ly == 1) {
            if (tid == 0) {
                volatile int* pk = &g_pk1done;
                while (*pk < 16) __nanosleep(128);
                int need = (tg + 1) * 4;
                for (int bi = 0; bi < 64; bi++) {
                    volatile int* p = &g_progress[bi];
                    while (*p < need) __nanosleep(128);
                }
                __threadfence();
            }
            __syncthreads();
            gemm16(s, g_mx16, g_w1h, clf1_b, 4096, tg, nb, 1, nullptr, 0);
            __threadfence();
            __syncthreads();
            if (tid == 0) atomicAdd(&g_rbdone[tg], 1);
        } else {
            if (tid == 0) {
                volatile int* pk = &g_pk2done;
                while (*pk < 8) __nanosleep(128);
                volatile int* rd = &g_rbdone[tg];
                while (*rd < 16) __nanosleep(128);
                __threadfence();
            }
            __syncthreads();
            gemm16(s, g_h1h, g_w2h, clf2_b, 2048, tg, nb, 2, clf3_w, tg * 8 + nb);
        }
    }
}

// ============================================================================
__global__ void finalize_kernel(const float* __restrict__ b3, float* __restrict__ out)
{
    int tid = threadIdx.x;
    if (tid < 64) {
        int b = tid >> 1, o = tid & 1;
        float sv = 0.f;
        for (int t2 = 0; t2 < 512; t2++)
            sv += g_lg[t2 * 64 + b * 2 + o];
        out[(size_t)b * 2 + o] = sv * (1.f / 256.f) + b3[o];
    }
    if (tid == 64) {
        float ss = 0.f;
        #pragma unroll
        for (int i = 0; i < 64; i++) ss += g_rl[i];
        out[RL_OFF] = ss / (32.f * 255.f * 64.f);
    }
}

// ============================================================================
extern "C" void kernel_launch(void* const* d_in, const int* in_sizes, int n_in,
                              void* d_out, int out_size)
{
    const float* x      = (const float*)d_in[0];
    const float* emb_w  = (const float*)d_in[1];
    const float* emb_b  = (const float*)d_in[2];
    const float* w_ih   = (const float*)d_in[3];
    const float* w_hh   = (const float*)d_in[4];
    const float* b_ih   = (const float*)d_in[5];
    const float* b_hh   = (const float*)d_in[6];
    const float* q_w    = (const float*)d_in[7];
    const float* q_b    = (const float*)d_in[8];
    const float* k_w    = (const float*)d_in[9];
    const float* k_b    = (const float*)d_in[10];
    const float* gate_b = (const float*)d_in[11];
    const float* pred_w = (const float*)d_in[12];
    const float* pred_b = (const float*)d_in[13];
    const float* clf1_w = (const float*)d_in[14];
    const float* clf1_b = (const float*)d_in[15];
    const float* clf2_w = (const float*)d_in[16];
    const float* clf2_b = (const float*)d_in[17];
    const float* clf3_w = (const float*)d_in[18];
    const float* clf3_b = (const float*)d_in[19];
    float* out = (float*)d_out;

    cudaFuncSetAttribute(mega_kernel,
                         cudaFuncAttributeMaxDynamicSharedMemorySize, SMEM_BYTES);

    init_kernel<<<1, 128>>>();

    cudaLaunchConfig_t cfg = {};
    cfg.gridDim = dim3(NSM, 1, 1);
    cfg.blockDim = dim3(256, 1, 1);
    cfg.dynamicSmemBytes = SMEM_BYTES;
    cfg.stream = 0;
    cudaLaunchAttribute attrs[1];
    attrs[0].id = cudaLaunchAttributeClusterDimension;
    attrs[0].val.clusterDim.x = 2;
    attrs[0].val.clusterDim.y = 1;
    attrs[0].val.clusterDim.z = 1;
    cfg.attrs = attrs;
    cfg.numAttrs = 1;
    cudaLaunchKernelEx(&cfg, mega_kernel,
        x, emb_w, emb_b, w_ih, w_hh, b_ih, b_hh,
        q_w, q_b, k_w, k_b, gate_b, pred_w, pred_b,
        clf1_w, clf1_b, clf2_w, clf2_b, clf3_w, out);

    finalize_kernel<<<1, 128>>>(clf3_b, out);
}